// round 1
// baseline (speedup 1.0000x reference)
#include <cuda_runtime.h>
#include <math.h>

#define BATCH 64
#define DMODEL 128
#define NN 2048
#define HEAD 4
#define DK 32
#define NT 64          // node tile
#define NTILES (NN/NT) // 32

static __device__ float g_keysm[HEAD * NN * DK];          // 1 MB
static __device__ float g_biasdyn[NN * DK];               // 256 KB
static __device__ float g_kv[BATCH * HEAD * DK * DK];     // 1 MB
static __device__ float g_qsm[(size_t)BATCH * HEAD * NN * DK]; // 67 MB
static __device__ float g_v[(size_t)BATCH * DMODEL * NN];      // 67 MB

__device__ __forceinline__ float warp_max(float v) {
    #pragma unroll
    for (int o = 16; o; o >>= 1) v = fmaxf(v, __shfl_xor_sync(0xffffffffu, v, o));
    return v;
}
__device__ __forceinline__ float warp_sum(float v) {
    #pragma unroll
    for (int o = 16; o; o >>= 1) v += __shfl_xor_sync(0xffffffffu, v, o);
    return v;
}

// ---------------- P1: key softmax over d_k -------------------------------
__global__ void k_keysm(const float* __restrict__ mem) {
    const float inv_scale = 0.17677669529663687f; // 1/sqrt(32)
    int row = blockIdx.x * 8 + (threadIdx.x >> 5);   // 8192 rows
    int lane = threadIdx.x & 31;
    float v = mem[row * 32 + lane] * inv_scale;
    float m = warp_max(v);
    float e = __expf(v - m);
    float s = warp_sum(e);
    g_keysm[row * 32 + lane] = e / s;
}

// ---------------- P2: bias_dyn = softmax(relu(nv1@nv2)) @ bias_pool ------
__global__ __launch_bounds__(256) void k_biasdyn(const float* __restrict__ nv1,
                                                 const float* __restrict__ nv2,
                                                 const float* __restrict__ bpool) {
    __shared__ float p[NN];
    __shared__ float red[256];
    __shared__ float a1[10];
    int n = blockIdx.x;
    int t = threadIdx.x;
    if (t < 10) a1[t] = nv1[n * 10 + t];
    __syncthreads();

    float lv[8];
    float lmax = 0.0f;   // relu >= 0
    #pragma unroll
    for (int i = 0; i < 8; i++) {
        int m = t + i * 256;
        float acc = 0.0f;
        #pragma unroll
        for (int k = 0; k < 10; k++) acc += a1[k] * nv2[k * NN + m];
        acc = fmaxf(acc, 0.0f);
        lv[i] = acc;
        lmax = fmaxf(lmax, acc);
    }
    red[t] = lmax; __syncthreads();
    for (int s = 128; s; s >>= 1) { if (t < s) red[t] = fmaxf(red[t], red[t + s]); __syncthreads(); }
    float bmax = red[0];
    __syncthreads();

    float lsum = 0.0f;
    #pragma unroll
    for (int i = 0; i < 8; i++) {
        float e = __expf(lv[i] - bmax);
        p[t + i * 256] = e;
        lsum += e;
    }
    red[t] = lsum; __syncthreads();
    for (int s = 128; s; s >>= 1) { if (t < s) red[t] += red[t + s]; __syncthreads(); }
    float inv = 1.0f / red[0];
    __syncthreads();

    // bias_dyn[n,c] = sum_m p[m]*bpool[m,c] * inv
    int c = t & 31, g = t >> 5;   // 8 m-groups
    float acc = 0.0f;
    for (int m = g; m < NN; m += 8) acc += p[m] * bpool[m * 32 + c];
    red[t] = acc; __syncthreads();
    if (t < 32) {
        float s2 = 0.0f;
        #pragma unroll
        for (int g2 = 0; g2 < 8; g2++) s2 += red[g2 * 32 + t];
        g_biasdyn[n * 32 + t] = s2 * inv;
    }
}

// ---------------- P3: zero kv -------------------------------------------
__global__ void k_zero_kv() {
    int i = blockIdx.x * 256 + threadIdx.x;
    if (i < BATCH * HEAD * DK * DK) g_kv[i] = 0.0f;
}

// ---------------- K1: Q/V conv + q softmax + kv partials -----------------
__global__ __launch_bounds__(256, 1) void k_qv(const float* __restrict__ x,
                                               const float* __restrict__ qw,
                                               const float* __restrict__ qb,
                                               const float* __restrict__ vw,
                                               const float* __restrict__ vb) {
    extern __shared__ float sm[];
    float* wqT = sm;                 // 16384 floats  (k-major: wqT[k*128+o])
    float* wvT = sm + 16384;         // 16384
    float* xs  = sm + 32768;         // 128*64 = 8192  (xs[c*64+j]); reused as V tile
    // keysm tile reuses wqT after conv phase.

    int b = blockIdx.y;
    int n0 = blockIdx.x * NT;
    int t = threadIdx.x;

    for (int i = t; i < 16384; i += 256) {
        int o = i >> 7, k = i & 127;
        wqT[k * 128 + o] = qw[i];
        wvT[k * 128 + o] = vw[i];
    }
    for (int i = t; i < 128 * NT; i += 256) {
        int c = i >> 6, j = i & 63;
        xs[c * NT + j] = x[((size_t)b * 128 + c) * NN + n0 + j];
    }
    __syncthreads();

    int h = t >> 6, j = t & 63, c0 = h * 32;
    float qa[32], va[32];
    #pragma unroll
    for (int i = 0; i < 32; i++) { qa[i] = qb[c0 + i]; va[i] = vb[c0 + i]; }

    for (int k = 0; k < 128; k++) {
        float xv = xs[k * NT + j];
        const float4* wq4 = (const float4*)(wqT + k * 128 + c0);
        const float4* wv4 = (const float4*)(wvT + k * 128 + c0);
        #pragma unroll
        for (int i = 0; i < 8; i++) {
            float4 a = wq4[i];
            float4 c = wv4[i];
            qa[4*i+0] += a.x * xv; qa[4*i+1] += a.y * xv;
            qa[4*i+2] += a.z * xv; qa[4*i+3] += a.w * xv;
            va[4*i+0] += c.x * xv; va[4*i+1] += c.y * xv;
            va[4*i+2] += c.z * xv; va[4*i+3] += c.w * xv;
        }
    }

    // q: relu -> softmax over d_k (in registers)
    const float inv_scale = 0.17677669529663687f;
    float m = 0.0f;
    #pragma unroll
    for (int i = 0; i < 32; i++) { qa[i] = fmaxf(qa[i], 0.0f); m = fmaxf(m, qa[i]); }
    float s = 0.0f;
    #pragma unroll
    for (int i = 0; i < 32; i++) { qa[i] = __expf((qa[i] - m) * inv_scale); s += qa[i]; }
    float is = 1.0f / s;
    float4* qdst = (float4*)(g_qsm + (((size_t)b * HEAD + h) * NN + n0 + j) * 32);
    #pragma unroll
    for (int i = 0; i < 8; i++)
        qdst[i] = make_float4(qa[4*i+0]*is, qa[4*i+1]*is, qa[4*i+2]*is, qa[4*i+3]*is);

    // v: relu, store global
    #pragma unroll
    for (int i = 0; i < 32; i++) va[i] = fmaxf(va[i], 0.0f);
    #pragma unroll
    for (int i = 0; i < 32; i++)
        g_v[((size_t)b * 128 + c0 + i) * NN + n0 + j] = va[i];

    __syncthreads();  // everyone done reading xs
    #pragma unroll
    for (int i = 0; i < 32; i++) xs[(c0 + i) * NT + j] = va[i];  // V tile in smem

    // keysm tile into wqT region: ks[(h2*64+j2)*32 + xk]
    for (int i = t; i < HEAD * NT * DK; i += 256) {
        int h2 = i >> 11, r = i & 2047;
        int j2 = r >> 5, xk = r & 31;
        wqT[i] = g_keysm[(h2 * NN + n0 + j2) * 32 + xk];
    }
    __syncthreads();

    // kv partial: kv[h,x,y] += sum_j ks[h,j,x]*V[h*32+y, j]
    int idx = t & 63;
    int x0 = (idx >> 3) * 4;   // 8 x-groups
    int y0 = (idx & 7) * 4;    // 8 y-groups
    float acc[4][4];
    #pragma unroll
    for (int a = 0; a < 4; a++)
        #pragma unroll
        for (int bb = 0; bb < 4; bb++) acc[a][bb] = 0.0f;

    for (int jj = 0; jj < NT; jj++) {
        float4 kx = *(const float4*)(wqT + (h * NT + jj) * 32 + x0);
        float vy[4];
        #pragma unroll
        for (int yi = 0; yi < 4; yi++) vy[yi] = xs[(c0 + y0 + yi) * NT + jj];
        #pragma unroll
        for (int yi = 0; yi < 4; yi++) {
            acc[0][yi] += kx.x * vy[yi];
            acc[1][yi] += kx.y * vy[yi];
            acc[2][yi] += kx.z * vy[yi];
            acc[3][yi] += kx.w * vy[yi];
        }
    }
    #pragma unroll
    for (int xi = 0; xi < 4; xi++)
        #pragma unroll
        for (int yi = 0; yi < 4; yi++)
            atomicAdd(&g_kv[(((size_t)b * HEAD + h) * DK + x0 + xi) * DK + y0 + yi],
                      acc[xi][yi]);
}

// ---------------- K2: attn + output conv + affine ------------------------
__global__ __launch_bounds__(256, 1) void k_out(const float* __restrict__ cw,
                                                const float* __restrict__ cb,
                                                const float* __restrict__ wpool,
                                                const float* __restrict__ affw,
                                                const float* __restrict__ affb,
                                                float* __restrict__ out) {
    extern __shared__ float sm[];
    float* cwT = sm;            // 16384
    float* pre = sm + 16384;    // 128*64 = 8192  (pre[c*64+j])
    float* kvs = sm + 24576;    // 4096
    float* bds = sm + 28672;    // 32*64 = 2048   (bds[c*64+j])
    // total 30720 floats = 120 KB

    int b = blockIdx.y;
    int n0 = blockIdx.x * NT;
    int t = threadIdx.x;

    for (int i = t; i < 16384; i += 256) {
        int o = i >> 7, k = i & 127;
        cwT[k * 128 + o] = cw[i];
    }
    for (int i = t; i < HEAD * DK * DK; i += 256)
        kvs[i] = g_kv[(size_t)b * HEAD * DK * DK + i];
    for (int i = t; i < DK * NT; i += 256) {
        int c = i >> 6, j = i & 63;
        bds[c * NT + j] = g_biasdyn[(n0 + j) * 32 + c];
    }
    float S = 0.0f;
    #pragma unroll
    for (int i = 0; i < 9; i++) S += wpool[i];
    __syncthreads();

    int h = t >> 6, j = t & 63, c0 = h * 32;

    float q[32];
    const float4* qsrc = (const float4*)(g_qsm + (((size_t)b * HEAD + h) * NN + n0 + j) * 32);
    #pragma unroll
    for (int i = 0; i < 8; i++) {
        float4 v4 = qsrc[i];
        q[4*i+0] = v4.x; q[4*i+1] = v4.y; q[4*i+2] = v4.z; q[4*i+3] = v4.w;
    }
    float acc[32];
    #pragma unroll
    for (int y = 0; y < 32; y++) acc[y] = bds[y * NT + j];

    #pragma unroll 4
    for (int xk = 0; xk < 32; xk++) {
        float qx = q[xk];
        const float4* kr = (const float4*)(kvs + (h * 32 + xk) * 32);
        #pragma unroll
        for (int i = 0; i < 8; i++) {
            float4 kk = kr[i];
            acc[4*i+0] += qx * kk.x; acc[4*i+1] += qx * kk.y;
            acc[4*i+2] += qx * kk.z; acc[4*i+3] += qx * kk.w;
        }
    }
    #pragma unroll
    for (int y = 0; y < 32; y++) {
        float v = g_v[((size_t)b * 128 + c0 + y) * NN + n0 + j];
        acc[y] += S * v;
        pre[(c0 + y) * NT + j] = acc[y];
    }
    __syncthreads();

    int o0 = (t >> 6) * 32;
    float oacc[32];
    #pragma unroll
    for (int i = 0; i < 32; i++) oacc[i] = cb[o0 + i];
    for (int k = 0; k < 128; k++) {
        float pv = pre[k * NT + j];
        const float4* cw4 = (const float4*)(cwT + k * 128 + o0);
        #pragma unroll
        for (int i = 0; i < 8; i++) {
            float4 a = cw4[i];
            oacc[4*i+0] += a.x * pv; oacc[4*i+1] += a.y * pv;
            oacc[4*i+2] += a.z * pv; oacc[4*i+3] += a.w * pv;
        }
    }
    #pragma unroll
    for (int i = 0; i < 32; i++) {
        int o = o0 + i;
        float r = fmaxf(oacc[i], 0.0f);
        float w = affw[o * NN + n0 + j];
        float bb2 = affb[o * NN + n0 + j];
        out[((size_t)b * 128 + o) * NN + n0 + j] = r + r * w + bb2;
    }
}

extern "C" void kernel_launch(void* const* d_in, const int* in_sizes, int n_in,
                              void* d_out, int out_size) {
    const float* x     = (const float*)d_in[0];
    const float* qw    = (const float*)d_in[1];
    const float* qb    = (const float*)d_in[2];
    const float* vw    = (const float*)d_in[3];
    const float* vb    = (const float*)d_in[4];
    const float* cw    = (const float*)d_in[5];
    const float* cb    = (const float*)d_in[6];
    const float* mem   = (const float*)d_in[7];
    const float* nv1   = (const float*)d_in[8];
    const float* nv2   = (const float*)d_in[9];
    const float* wpool = (const float*)d_in[10];
    const float* bpool = (const float*)d_in[11];
    const float* affw  = (const float*)d_in[12];
    const float* affb  = (const float*)d_in[13];
    float* out = (float*)d_out;

    k_keysm<<<HEAD * NN / 8, 256>>>(mem);
    k_biasdyn<<<NN, 256>>>(nv1, nv2, bpool);
    k_zero_kv<<<(BATCH * HEAD * DK * DK + 255) / 256, 256>>>();

    size_t smem1 = (size_t)(16384 + 16384 + 8192) * 4;   // 160 KB
    cudaFuncSetAttribute(k_qv, cudaFuncAttributeMaxDynamicSharedMemorySize, (int)smem1);
    k_qv<<<dim3(NTILES, BATCH), 256, smem1>>>(x, qw, qb, vw, vb);

    size_t smem2 = (size_t)30720 * 4;                    // 120 KB
    cudaFuncSetAttribute(k_out, cudaFuncAttributeMaxDynamicSharedMemorySize, (int)smem2);
    k_out<<<dim3(NTILES, BATCH), 256, smem2>>>(cw, cb, wpool, affw, affb, out);
}

// round 2
// speedup vs baseline: 2.3396x; 2.3396x over previous
#include <cuda_runtime.h>
#include <math.h>

#define BATCH 64
#define DMODEL 128
#define NN 2048
#define HEAD 4
#define DK 32
#define NT 128          // node tile
#define NTILES (NN/NT)  // 16
#define XSTR 129        // padded smem stride

static __device__ float g_keysm[HEAD * NN * DK];               // 1 MB
static __device__ float g_biasdyn[NN * DK];                    // 256 KB
static __device__ float g_kv[BATCH * HEAD * DK * DK];          // 1 MB
static __device__ float g_qsm[(size_t)BATCH * HEAD * NN * DK]; // 67 MB
static __device__ float g_v[(size_t)BATCH * DMODEL * NN];      // 67 MB

__device__ __forceinline__ float warp_max(float v) {
    #pragma unroll
    for (int o = 16; o; o >>= 1) v = fmaxf(v, __shfl_xor_sync(0xffffffffu, v, o));
    return v;
}
__device__ __forceinline__ float warp_sum(float v) {
    #pragma unroll
    for (int o = 16; o; o >>= 1) v += __shfl_xor_sync(0xffffffffu, v, o);
    return v;
}

// ---------------- P1: key softmax over d_k -------------------------------
__global__ void k_keysm(const float* __restrict__ mem) {
    const float inv_scale = 0.17677669529663687f; // 1/sqrt(32)
    int row = blockIdx.x * 8 + (threadIdx.x >> 5);
    int lane = threadIdx.x & 31;
    float v = mem[row * 32 + lane] * inv_scale;
    float m = warp_max(v);
    float e = __expf(v - m);
    float s = warp_sum(e);
    g_keysm[row * 32 + lane] = e / s;
}

// ---------------- P2: bias_dyn, 8 rows per block -------------------------
__global__ __launch_bounds__(256) void k_biasdyn(const float* __restrict__ nv1,
                                                 const float* __restrict__ nv2,
                                                 const float* __restrict__ bpool) {
    __shared__ float p[8][NN];       // 64 KB
    __shared__ float red[256];
    __shared__ float a1[8][10];
    __shared__ float invs[8];
    int n0 = blockIdx.x * 8;
    int t = threadIdx.x;
    if (t < 80) a1[t / 10][t % 10] = nv1[(n0 + t / 10) * 10 + (t % 10)];
    __syncthreads();

    for (int r = 0; r < 8; r++) {
        float lv[8];
        float lmax = 0.0f;
        #pragma unroll
        for (int i = 0; i < 8; i++) {
            int m = t + i * 256;
            float acc = 0.0f;
            #pragma unroll
            for (int k = 0; k < 10; k++) acc += a1[r][k] * nv2[k * NN + m];
            acc = fmaxf(acc, 0.0f);
            lv[i] = acc;
            lmax = fmaxf(lmax, acc);
        }
        red[t] = lmax; __syncthreads();
        for (int s = 128; s; s >>= 1) { if (t < s) red[t] = fmaxf(red[t], red[t + s]); __syncthreads(); }
        float bmax = red[0];
        __syncthreads();
        float lsum = 0.0f;
        #pragma unroll
        for (int i = 0; i < 8; i++) {
            float e = __expf(lv[i] - bmax);
            p[r][t + i * 256] = e;
            lsum += e;
        }
        red[t] = lsum; __syncthreads();
        for (int s = 128; s; s >>= 1) { if (t < s) red[t] += red[t + s]; __syncthreads(); }
        if (t == 0) invs[r] = 1.0f / red[0];
        __syncthreads();
    }

    // acc[r] = sum_m p[r][m]*bpool[m,c]
    int c = t & 31, g = t >> 5;  // 8 m-groups
    float acc[8];
    #pragma unroll
    for (int r = 0; r < 8; r++) acc[r] = 0.0f;
    for (int m = g; m < NN; m += 8) {
        float bp = bpool[m * 32 + c];
        #pragma unroll
        for (int r = 0; r < 8; r++) acc[r] += p[r][m] * bp;
    }
    for (int r = 0; r < 8; r++) {
        red[t] = acc[r]; __syncthreads();
        if (t < 32) {
            float s2 = 0.0f;
            #pragma unroll
            for (int g2 = 0; g2 < 8; g2++) s2 += red[g2 * 32 + t];
            g_biasdyn[(n0 + r) * 32 + t] = s2 * invs[r];
        }
        __syncthreads();
    }
}

// ---------------- P3: zero kv -------------------------------------------
__global__ void k_zero_kv() {
    int i = blockIdx.x * 256 + threadIdx.x;
    if (i < BATCH * HEAD * DK * DK) g_kv[i] = 0.0f;
}

// ---------------- K1: Q/V conv + q softmax + kv partials -----------------
// smem: wqT 16384 | wvT 16384 | xs 128*129=16512 (stride 129)
// After convs: xs region reused as V tile, wqT region reused as keysm tile.
__global__ __launch_bounds__(256, 1) void k_qv(const float* __restrict__ x,
                                               const float* __restrict__ qw,
                                               const float* __restrict__ qb,
                                               const float* __restrict__ vw,
                                               const float* __restrict__ vb) {
    extern __shared__ float sm[];
    float* wqT = sm;                 // [k*128+o]
    float* wvT = sm + 16384;
    float* xs  = sm + 32768;         // [c*129+j], reused as vt

    int b = blockIdx.y;
    int n0 = blockIdx.x * NT;
    int t = threadIdx.x;

    for (int i = t; i < 16384; i += 256) {
        int o = i >> 7, k = i & 127;
        wqT[k * 128 + o] = qw[i];
        wvT[k * 128 + o] = vw[i];
    }
    for (int i = t; i < 16384; i += 256) {
        int c = i >> 7, j = i & 127;
        xs[c * XSTR + j] = x[((size_t)b * 128 + c) * NN + n0 + j];
    }
    __syncthreads();

    int h = t >> 6, j = t & 63, c0 = h * 32;
    const float inv_scale = 0.17677669529663687f;

    // ---- pass Q: 2 nodes (j, j+64), 32 channels each ----
    {
        float qa0[32], qa1[32];
        #pragma unroll
        for (int i = 0; i < 32; i++) { qa0[i] = qb[c0 + i]; qa1[i] = qa0[i]; }
        for (int k = 0; k < 128; k++) {
            float xv0 = xs[k * XSTR + j];
            float xv1 = xs[k * XSTR + j + 64];
            const float4* w4 = (const float4*)(wqT + k * 128 + c0);
            #pragma unroll
            for (int i = 0; i < 8; i++) {
                float4 a = w4[i];
                qa0[4*i+0] += a.x * xv0; qa0[4*i+1] += a.y * xv0;
                qa0[4*i+2] += a.z * xv0; qa0[4*i+3] += a.w * xv0;
                qa1[4*i+0] += a.x * xv1; qa1[4*i+1] += a.y * xv1;
                qa1[4*i+2] += a.z * xv1; qa1[4*i+3] += a.w * xv1;
            }
        }
        // relu -> softmax over d_k, node 0
        float m0 = 0.0f, m1 = 0.0f;
        #pragma unroll
        for (int i = 0; i < 32; i++) {
            qa0[i] = fmaxf(qa0[i], 0.0f); m0 = fmaxf(m0, qa0[i]);
            qa1[i] = fmaxf(qa1[i], 0.0f); m1 = fmaxf(m1, qa1[i]);
        }
        float s0 = 0.0f, s1 = 0.0f;
        #pragma unroll
        for (int i = 0; i < 32; i++) {
            qa0[i] = __expf((qa0[i] - m0) * inv_scale); s0 += qa0[i];
            qa1[i] = __expf((qa1[i] - m1) * inv_scale); s1 += qa1[i];
        }
        float is0 = 1.0f / s0, is1 = 1.0f / s1;
        float4* q0 = (float4*)(g_qsm + (((size_t)b * HEAD + h) * NN + n0 + j) * 32);
        float4* q1 = (float4*)(g_qsm + (((size_t)b * HEAD + h) * NN + n0 + j + 64) * 32);
        #pragma unroll
        for (int i = 0; i < 8; i++) {
            q0[i] = make_float4(qa0[4*i]*is0, qa0[4*i+1]*is0, qa0[4*i+2]*is0, qa0[4*i+3]*is0);
            q1[i] = make_float4(qa1[4*i]*is1, qa1[4*i+1]*is1, qa1[4*i+2]*is1, qa1[4*i+3]*is1);
        }
    }

    // ---- pass V ----
    float va0[32], va1[32];
    {
        #pragma unroll
        for (int i = 0; i < 32; i++) { va0[i] = vb[c0 + i]; va1[i] = va0[i]; }
        for (int k = 0; k < 128; k++) {
            float xv0 = xs[k * XSTR + j];
            float xv1 = xs[k * XSTR + j + 64];
            const float4* w4 = (const float4*)(wvT + k * 128 + c0);
            #pragma unroll
            for (int i = 0; i < 8; i++) {
                float4 a = w4[i];
                va0[4*i+0] += a.x * xv0; va0[4*i+1] += a.y * xv0;
                va0[4*i+2] += a.z * xv0; va0[4*i+3] += a.w * xv0;
                va1[4*i+0] += a.x * xv1; va1[4*i+1] += a.y * xv1;
                va1[4*i+2] += a.z * xv1; va1[4*i+3] += a.w * xv1;
            }
        }
        #pragma unroll
        for (int i = 0; i < 32; i++) {
            va0[i] = fmaxf(va0[i], 0.0f);
            va1[i] = fmaxf(va1[i], 0.0f);
        }
        #pragma unroll
        for (int i = 0; i < 32; i++) {
            g_v[((size_t)b * 128 + c0 + i) * NN + n0 + j] = va0[i];
            g_v[((size_t)b * 128 + c0 + i) * NN + n0 + j + 64] = va1[i];
        }
    }

    __syncthreads();   // all conv reads of xs/wqT done

    // V tile into xs region: vt[c*129 + node]
    #pragma unroll
    for (int i = 0; i < 32; i++) {
        xs[(c0 + i) * XSTR + j] = va0[i];
        xs[(c0 + i) * XSTR + j + 64] = va1[i];
    }
    // keysm tile into wqT region: ks[(h2*128 + j2)*32 + xk]
    for (int i = t; i < 16384; i += 256) {
        int h2 = i >> 12, r = i & 4095;
        int j2 = r >> 5, xk = r & 31;
        wqT[i] = g_keysm[(h2 * NN + n0 + j2) * 32 + xk];
    }
    __syncthreads();

    // kv partial: kv[h,x,y] += sum_j ks[h,j,x]*V[h*32+y, j]
    int idx = t & 63;
    int x0 = (idx >> 3) * 4;
    int y0 = (idx & 7) * 4;
    float acc[4][4];
    #pragma unroll
    for (int a = 0; a < 4; a++)
        #pragma unroll
        for (int bb = 0; bb < 4; bb++) acc[a][bb] = 0.0f;

    #pragma unroll 4
    for (int jj = 0; jj < NT; jj++) {
        float4 kx = *(const float4*)(wqT + (h * NT + jj) * 32 + x0);
        float vy[4];
        #pragma unroll
        for (int yi = 0; yi < 4; yi++) vy[yi] = xs[(c0 + y0 + yi) * XSTR + jj];
        #pragma unroll
        for (int yi = 0; yi < 4; yi++) {
            acc[0][yi] += kx.x * vy[yi];
            acc[1][yi] += kx.y * vy[yi];
            acc[2][yi] += kx.z * vy[yi];
            acc[3][yi] += kx.w * vy[yi];
        }
    }
    #pragma unroll
    for (int xi = 0; xi < 4; xi++)
        #pragma unroll
        for (int yi = 0; yi < 4; yi++)
            atomicAdd(&g_kv[(((size_t)b * HEAD + h) * DK + x0 + xi) * DK + y0 + yi],
                      acc[xi][yi]);
}

// ---------------- K2: attn + output conv + affine ------------------------
// smem: cwT 16384 | pre 16512 (stride 129) | kvs 4096 | bds 4096
__global__ __launch_bounds__(256, 1) void k_out(const float* __restrict__ cw,
                                                const float* __restrict__ cb,
                                                const float* __restrict__ wpool,
                                                const float* __restrict__ affw,
                                                const float* __restrict__ affb,
                                                float* __restrict__ out) {
    extern __shared__ float sm[];
    float* cwT = sm;             // [k*128+o]
    float* pre = sm + 16384;     // [c*129+j], first q stage, then conv input
    float* kvs = sm + 32896;     // 4096
    float* bds = sm + 36992;     // [c*128+j]

    int b = blockIdx.y;
    int n0 = blockIdx.x * NT;
    int t = threadIdx.x;

    for (int i = t; i < 16384; i += 256) {
        int o = i >> 7, k = i & 127;
        cwT[k * 128 + o] = cw[i];
    }
    for (int i = t; i < HEAD * DK * DK; i += 256)
        kvs[i] = g_kv[(size_t)b * HEAD * DK * DK + i];
    for (int i = t; i < DK * NT; i += 256) {
        int c = i >> 7, jj = i & 127;
        bds[c * NT + jj] = g_biasdyn[(n0 + jj) * 32 + c];
    }
    float S = 0.0f;
    #pragma unroll
    for (int i = 0; i < 9; i++) S += wpool[i];

    int h = t >> 6, j = t & 63, c0 = h * 32;

    // stage q into pre region: pre[(c0+xk)*129 + node]
    {
        const float4* q0 = (const float4*)(g_qsm + (((size_t)b * HEAD + h) * NN + n0 + j) * 32);
        const float4* q1 = (const float4*)(g_qsm + (((size_t)b * HEAD + h) * NN + n0 + j + 64) * 32);
        #pragma unroll
        for (int i = 0; i < 8; i++) {
            float4 a = q0[i];
            pre[(c0 + 4*i + 0) * XSTR + j] = a.x;
            pre[(c0 + 4*i + 1) * XSTR + j] = a.y;
            pre[(c0 + 4*i + 2) * XSTR + j] = a.z;
            pre[(c0 + 4*i + 3) * XSTR + j] = a.w;
            float4 c = q1[i];
            pre[(c0 + 4*i + 0) * XSTR + j + 64] = c.x;
            pre[(c0 + 4*i + 1) * XSTR + j + 64] = c.y;
            pre[(c0 + 4*i + 2) * XSTR + j + 64] = c.z;
            pre[(c0 + 4*i + 3) * XSTR + j + 64] = c.w;
        }
    }
    __syncthreads();

    float acc0[32], acc1[32];
    #pragma unroll
    for (int y = 0; y < 32; y++) {
        acc0[y] = bds[y * NT + j];
        acc1[y] = bds[y * NT + j + 64];
    }
    #pragma unroll 4
    for (int xk = 0; xk < 32; xk++) {
        float qx0 = pre[(c0 + xk) * XSTR + j];
        float qx1 = pre[(c0 + xk) * XSTR + j + 64];
        const float4* kr = (const float4*)(kvs + (h * 32 + xk) * 32);
        #pragma unroll
        for (int i = 0; i < 8; i++) {
            float4 kk = kr[i];
            acc0[4*i+0] += qx0 * kk.x; acc0[4*i+1] += qx0 * kk.y;
            acc0[4*i+2] += qx0 * kk.z; acc0[4*i+3] += qx0 * kk.w;
            acc1[4*i+0] += qx1 * kk.x; acc1[4*i+1] += qx1 * kk.y;
            acc1[4*i+2] += qx1 * kk.z; acc1[4*i+3] += qx1 * kk.w;
        }
    }
    #pragma unroll
    for (int y = 0; y < 32; y++) {
        float v0 = g_v[((size_t)b * 128 + c0 + y) * NN + n0 + j];
        float v1 = g_v[((size_t)b * 128 + c0 + y) * NN + n0 + j + 64];
        acc0[y] += S * v0;
        acc1[y] += S * v1;
    }
    __syncthreads();   // everyone done reading pre (q)
    #pragma unroll
    for (int y = 0; y < 32; y++) {
        pre[(c0 + y) * XSTR + j] = acc0[y];
        pre[(c0 + y) * XSTR + j + 64] = acc1[y];
    }
    __syncthreads();

    // output conv
    float oacc0[32], oacc1[32];
    #pragma unroll
    for (int i = 0; i < 32; i++) { oacc0[i] = cb[c0 + i]; oacc1[i] = oacc0[i]; }
    for (int k = 0; k < 128; k++) {
        float pv0 = pre[k * XSTR + j];
        float pv1 = pre[k * XSTR + j + 64];
        const float4* cw4 = (const float4*)(cwT + k * 128 + c0);
        #pragma unroll
        for (int i = 0; i < 8; i++) {
            float4 a = cw4[i];
            oacc0[4*i+0] += a.x * pv0; oacc0[4*i+1] += a.y * pv0;
            oacc0[4*i+2] += a.z * pv0; oacc0[4*i+3] += a.w * pv0;
            oacc1[4*i+0] += a.x * pv1; oacc1[4*i+1] += a.y * pv1;
            oacc1[4*i+2] += a.z * pv1; oacc1[4*i+3] += a.w * pv1;
        }
    }
    #pragma unroll
    for (int i = 0; i < 32; i++) {
        int o = c0 + i;
        float r0 = fmaxf(oacc0[i], 0.0f);
        float r1 = fmaxf(oacc1[i], 0.0f);
        float w0 = affw[o * NN + n0 + j];
        float w1 = affw[o * NN + n0 + j + 64];
        float b0 = affb[o * NN + n0 + j];
        float b1 = affb[o * NN + n0 + j + 64];
        out[((size_t)b * 128 + o) * NN + n0 + j] = r0 + r0 * w0 + b0;
        out[((size_t)b * 128 + o) * NN + n0 + j + 64] = r1 + r1 * w1 + b1;
    }
}

extern "C" void kernel_launch(void* const* d_in, const int* in_sizes, int n_in,
                              void* d_out, int out_size) {
    const float* x     = (const float*)d_in[0];
    const float* qw    = (const float*)d_in[1];
    const float* qb    = (const float*)d_in[2];
    const float* vw    = (const float*)d_in[3];
    const float* vb    = (const float*)d_in[4];
    const float* cw    = (const float*)d_in[5];
    const float* cb    = (const float*)d_in[6];
    const float* mem   = (const float*)d_in[7];
    const float* nv1   = (const float*)d_in[8];
    const float* nv2   = (const float*)d_in[9];
    const float* wpool = (const float*)d_in[10];
    const float* bpool = (const float*)d_in[11];
    const float* affw  = (const float*)d_in[12];
    const float* affb  = (const float*)d_in[13];
    float* out = (float*)d_out;

    k_keysm<<<HEAD * NN / 8, 256>>>(mem);
    k_biasdyn<<<NN / 8, 256>>>(nv1, nv2, bpool);
    k_zero_kv<<<(BATCH * HEAD * DK * DK + 255) / 256, 256>>>();

    size_t smem1 = (size_t)(16384 + 16384 + 128 * XSTR) * 4;   // ~192.5 KB
    cudaFuncSetAttribute(k_qv, cudaFuncAttributeMaxDynamicSharedMemorySize, (int)smem1);
    k_qv<<<dim3(NTILES, BATCH), 256, smem1>>>(x, qw, qb, vw, vb);

    size_t smem2 = (size_t)(16384 + 128 * XSTR + 4096 + 4096) * 4;  // ~160.5 KB
    cudaFuncSetAttribute(k_out, cudaFuncAttributeMaxDynamicSharedMemorySize, (int)smem2);
    k_out<<<dim3(NTILES, BATCH), 256, smem2>>>(cw, cb, wpool, affw, affb, out);
}

// round 3
// speedup vs baseline: 2.3473x; 1.0033x over previous
#include <cuda_runtime.h>
#include <math.h>

#define BATCH 64
#define DMODEL 128
#define NN 2048
#define HEAD 4
#define DK 32
#define NT 128          // node tile
#define NTILES (NN/NT)  // 16
#define XSTR 129        // padded smem stride

static __device__ float g_keysm[HEAD * NN * DK];               // 1 MB
static __device__ float g_biasdyn[NN * DK];                    // 256 KB
static __device__ float g_kv[BATCH * HEAD * DK * DK];          // 1 MB
static __device__ float g_qsm[(size_t)BATCH * HEAD * NN * DK]; // 67 MB
static __device__ float g_v[(size_t)BATCH * DMODEL * NN];      // 67 MB

__device__ __forceinline__ float warp_max(float v) {
    #pragma unroll
    for (int o = 16; o; o >>= 1) v = fmaxf(v, __shfl_xor_sync(0xffffffffu, v, o));
    return v;
}
__device__ __forceinline__ float warp_sum(float v) {
    #pragma unroll
    for (int o = 16; o; o >>= 1) v += __shfl_xor_sync(0xffffffffu, v, o);
    return v;
}

// ---------------- P1: key softmax over d_k -------------------------------
__global__ void k_keysm(const float* __restrict__ mem) {
    const float inv_scale = 0.17677669529663687f; // 1/sqrt(32)
    int row = blockIdx.x * 8 + (threadIdx.x >> 5);
    int lane = threadIdx.x & 31;
    float v = mem[row * 32 + lane] * inv_scale;
    float m = warp_max(v);
    float e = __expf(v - m);
    float s = warp_sum(e);
    g_keysm[row * 32 + lane] = e / s;
}

// ---------------- P2: bias_dyn, 8 rows per block -------------------------
__global__ __launch_bounds__(256) void k_biasdyn(const float* __restrict__ nv1,
                                                 const float* __restrict__ nv2,
                                                 const float* __restrict__ bpool) {
    __shared__ float p[8][NN];
    __shared__ float red[256];
    __shared__ float a1[8][10];
    __shared__ float invs[8];
    int n0 = blockIdx.x * 8;
    int t = threadIdx.x;
    if (t < 80) a1[t / 10][t % 10] = nv1[(n0 + t / 10) * 10 + (t % 10)];
    __syncthreads();

    for (int r = 0; r < 8; r++) {
        float lv[8];
        float lmax = 0.0f;
        #pragma unroll
        for (int i = 0; i < 8; i++) {
            int m = t + i * 256;
            float acc = 0.0f;
            #pragma unroll
            for (int k = 0; k < 10; k++) acc += a1[r][k] * nv2[k * NN + m];
            acc = fmaxf(acc, 0.0f);
            lv[i] = acc;
            lmax = fmaxf(lmax, acc);
        }
        red[t] = lmax; __syncthreads();
        for (int s = 128; s; s >>= 1) { if (t < s) red[t] = fmaxf(red[t], red[t + s]); __syncthreads(); }
        float bmax = red[0];
        __syncthreads();
        float lsum = 0.0f;
        #pragma unroll
        for (int i = 0; i < 8; i++) {
            float e = __expf(lv[i] - bmax);
            p[r][t + i * 256] = e;
            lsum += e;
        }
        red[t] = lsum; __syncthreads();
        for (int s = 128; s; s >>= 1) { if (t < s) red[t] += red[t + s]; __syncthreads(); }
        if (t == 0) invs[r] = 1.0f / red[0];
        __syncthreads();
    }

    int c = t & 31, g = t >> 5;  // 8 m-groups
    float acc[8];
    #pragma unroll
    for (int r = 0; r < 8; r++) acc[r] = 0.0f;
    for (int m = g; m < NN; m += 8) {
        float bp = bpool[m * 32 + c];
        #pragma unroll
        for (int r = 0; r < 8; r++) acc[r] += p[r][m] * bp;
    }
    for (int r = 0; r < 8; r++) {
        red[t] = acc[r]; __syncthreads();
        if (t < 32) {
            float s2 = 0.0f;
            #pragma unroll
            for (int g2 = 0; g2 < 8; g2++) s2 += red[g2 * 32 + t];
            g_biasdyn[(n0 + r) * 32 + t] = s2 * invs[r];
        }
        __syncthreads();
    }
}

// ---------------- P3: zero kv -------------------------------------------
__global__ void k_zero_kv() {
    int i = blockIdx.x * 256 + threadIdx.x;
    if (i < BATCH * HEAD * DK * DK) g_kv[i] = 0.0f;
}

// ---------------- K1: fused Q/V conv + q softmax + kv partials -----------
// 512 threads, 1 node/thread. smem: wqT 16384 | wvT 16384 | xs 128*129
// After convs: xs region reused as V tile, wqT region reused as keysm tile.
__global__ __launch_bounds__(512, 1) void k_qv(const float* __restrict__ x,
                                               const float* __restrict__ qw,
                                               const float* __restrict__ qb,
                                               const float* __restrict__ vw,
                                               const float* __restrict__ vb) {
    extern __shared__ float sm[];
    float* wqT = sm;                 // [k*128+o]
    float* wvT = sm + 16384;
    float* xs  = sm + 32768;         // [c*129+j], reused as V tile

    int b = blockIdx.y;
    int n0 = blockIdx.x * NT;
    int t = threadIdx.x;

    for (int i = t; i < 16384; i += 512) {
        int o = i >> 7, k = i & 127;
        wqT[k * 128 + o] = qw[i];
        wvT[k * 128 + o] = vw[i];
    }
    for (int i = t; i < 16384; i += 512) {
        int c = i >> 7, j = i & 127;
        xs[c * XSTR + j] = x[((size_t)b * 128 + c) * NN + n0 + j];
    }
    __syncthreads();

    int h = t >> 7, j = t & 127, c0 = h * 32;
    const float inv_scale = 0.17677669529663687f;

    float qa[32], va[32];
    #pragma unroll
    for (int i = 0; i < 32; i++) { qa[i] = qb[c0 + i]; va[i] = vb[c0 + i]; }

    for (int k = 0; k < 128; k++) {
        float xv = xs[k * XSTR + j];
        const float4* wq4 = (const float4*)(wqT + k * 128 + c0);
        const float4* wv4 = (const float4*)(wvT + k * 128 + c0);
        #pragma unroll
        for (int i = 0; i < 8; i++) {
            float4 a = wq4[i];
            float4 c = wv4[i];
            qa[4*i+0] += a.x * xv; qa[4*i+1] += a.y * xv;
            qa[4*i+2] += a.z * xv; qa[4*i+3] += a.w * xv;
            va[4*i+0] += c.x * xv; va[4*i+1] += c.y * xv;
            va[4*i+2] += c.z * xv; va[4*i+3] += c.w * xv;
        }
    }

    // q: relu -> softmax over d_k (in registers)
    float m = 0.0f;
    #pragma unroll
    for (int i = 0; i < 32; i++) { qa[i] = fmaxf(qa[i], 0.0f); m = fmaxf(m, qa[i]); }
    float s = 0.0f;
    #pragma unroll
    for (int i = 0; i < 32; i++) { qa[i] = __expf((qa[i] - m) * inv_scale); s += qa[i]; }
    float is = 1.0f / s;
    float4* qdst = (float4*)(g_qsm + (((size_t)b * HEAD + h) * NN + n0 + j) * 32);
    #pragma unroll
    for (int i = 0; i < 8; i++)
        qdst[i] = make_float4(qa[4*i]*is, qa[4*i+1]*is, qa[4*i+2]*is, qa[4*i+3]*is);

    // v: relu, store global
    #pragma unroll
    for (int i = 0; i < 32; i++) va[i] = fmaxf(va[i], 0.0f);
    #pragma unroll
    for (int i = 0; i < 32; i++)
        g_v[((size_t)b * 128 + c0 + i) * NN + n0 + j] = va[i];

    __syncthreads();   // all conv reads of xs/wqT done

    // V tile into xs region
    #pragma unroll
    for (int i = 0; i < 32; i++)
        xs[(c0 + i) * XSTR + j] = va[i];
    // keysm tile into wqT region: ks[(h2*128 + j2)*32 + xk]
    for (int i = t; i < 16384; i += 512) {
        int h2 = i >> 12, r = i & 4095;
        int j2 = r >> 5, xk = r & 31;
        wqT[i] = g_keysm[(h2 * NN + n0 + j2) * 32 + xk];
    }
    __syncthreads();

    // kv partial: kv[h,x,y] += sum_j ks[h,j,x]*V[h*32+y, j]
    // 128 threads per head: 8 x-groups (4 wide) x 16 y-groups (2 wide)
    int idx = t & 127;
    int x0 = (idx >> 4) * 4;
    int y0 = (idx & 15) * 2;
    float acc[4][2];
    #pragma unroll
    for (int a = 0; a < 4; a++) { acc[a][0] = 0.0f; acc[a][1] = 0.0f; }

    #pragma unroll 4
    for (int jj = 0; jj < NT; jj++) {
        float4 kx = *(const float4*)(wqT + (h * NT + jj) * 32 + x0);
        float v0 = xs[(c0 + y0 + 0) * XSTR + jj];
        float v1 = xs[(c0 + y0 + 1) * XSTR + jj];
        acc[0][0] += kx.x * v0; acc[0][1] += kx.x * v1;
        acc[1][0] += kx.y * v0; acc[1][1] += kx.y * v1;
        acc[2][0] += kx.z * v0; acc[2][1] += kx.z * v1;
        acc[3][0] += kx.w * v0; acc[3][1] += kx.w * v1;
    }
    #pragma unroll
    for (int xi = 0; xi < 4; xi++)
        #pragma unroll
        for (int yi = 0; yi < 2; yi++)
            atomicAdd(&g_kv[(((size_t)b * HEAD + h) * DK + x0 + xi) * DK + y0 + yi],
                      acc[xi][yi]);
}

// ---------------- K2: attn + output conv + affine ------------------------
// 512 threads, 1 node/thread.
// smem: cwT 16384 | pre 128*129 | kvs 4096 | bds 4096
__global__ __launch_bounds__(512, 1) void k_out(const float* __restrict__ cw,
                                                const float* __restrict__ cb,
                                                const float* __restrict__ wpool,
                                                const float* __restrict__ affw,
                                                const float* __restrict__ affb,
                                                float* __restrict__ out) {
    extern __shared__ float sm[];
    float* cwT = sm;             // [k*128+o]
    float* pre = sm + 16384;     // [c*129+j], first q stage, then conv input
    float* kvs = sm + 32896;     // 4096
    float* bds = sm + 36992;     // [c*128+j]

    int b = blockIdx.y;
    int n0 = blockIdx.x * NT;
    int t = threadIdx.x;

    for (int i = t; i < 16384; i += 512) {
        int o = i >> 7, k = i & 127;
        cwT[k * 128 + o] = cw[i];
    }
    for (int i = t; i < HEAD * DK * DK; i += 512)
        kvs[i] = g_kv[(size_t)b * HEAD * DK * DK + i];
    for (int i = t; i < DK * NT; i += 512) {
        int c = i >> 7, jj = i & 127;
        bds[c * NT + jj] = g_biasdyn[(n0 + jj) * 32 + c];
    }
    float S = 0.0f;
    #pragma unroll
    for (int i = 0; i < 9; i++) S += wpool[i];

    int h = t >> 7, j = t & 127, c0 = h * 32;

    // stage q into pre region: pre[(c0+xk)*129 + node]
    {
        const float4* q0 = (const float4*)(g_qsm + (((size_t)b * HEAD + h) * NN + n0 + j) * 32);
        #pragma unroll
        for (int i = 0; i < 8; i++) {
            float4 a = q0[i];
            pre[(c0 + 4*i + 0) * XSTR + j] = a.x;
            pre[(c0 + 4*i + 1) * XSTR + j] = a.y;
            pre[(c0 + 4*i + 2) * XSTR + j] = a.z;
            pre[(c0 + 4*i + 3) * XSTR + j] = a.w;
        }
    }
    __syncthreads();

    float acc[32];
    #pragma unroll
    for (int y = 0; y < 32; y++) acc[y] = bds[y * NT + j];

    #pragma unroll 4
    for (int xk = 0; xk < 32; xk++) {
        float qx = pre[(c0 + xk) * XSTR + j];
        const float4* kr = (const float4*)(kvs + (h * 32 + xk) * 32);
        #pragma unroll
        for (int i = 0; i < 8; i++) {
            float4 kk = kr[i];
            acc[4*i+0] += qx * kk.x; acc[4*i+1] += qx * kk.y;
            acc[4*i+2] += qx * kk.z; acc[4*i+3] += qx * kk.w;
        }
    }
    #pragma unroll
    for (int y = 0; y < 32; y++) {
        float v = g_v[((size_t)b * 128 + c0 + y) * NN + n0 + j];
        acc[y] += S * v;
    }
    __syncthreads();   // everyone done reading pre (q)
    #pragma unroll
    for (int y = 0; y < 32; y++)
        pre[(c0 + y) * XSTR + j] = acc[y];
    __syncthreads();

    // output conv
    float oacc[32];
    #pragma unroll
    for (int i = 0; i < 32; i++) oacc[i] = cb[c0 + i];
    for (int k = 0; k < 128; k++) {
        float pv = pre[k * XSTR + j];
        const float4* cw4 = (const float4*)(cwT + k * 128 + c0);
        #pragma unroll
        for (int i = 0; i < 8; i++) {
            float4 a = cw4[i];
            oacc[4*i+0] += a.x * pv; oacc[4*i+1] += a.y * pv;
            oacc[4*i+2] += a.z * pv; oacc[4*i+3] += a.w * pv;
        }
    }
    #pragma unroll
    for (int i = 0; i < 32; i++) {
        int o = c0 + i;
        float r = fmaxf(oacc[i], 0.0f);
        float w = affw[o * NN + n0 + j];
        float bb = affb[o * NN + n0 + j];
        out[((size_t)b * 128 + o) * NN + n0 + j] = r + r * w + bb;
    }
}

extern "C" void kernel_launch(void* const* d_in, const int* in_sizes, int n_in,
                              void* d_out, int out_size) {
    const float* x     = (const float*)d_in[0];
    const float* qw    = (const float*)d_in[1];
    const float* qb    = (const float*)d_in[2];
    const float* vw    = (const float*)d_in[3];
    const float* vb    = (const float*)d_in[4];
    const float* cw    = (const float*)d_in[5];
    const float* cb    = (const float*)d_in[6];
    const float* mem   = (const float*)d_in[7];
    const float* nv1   = (const float*)d_in[8];
    const float* nv2   = (const float*)d_in[9];
    const float* wpool = (const float*)d_in[10];
    const float* bpool = (const float*)d_in[11];
    const float* affw  = (const float*)d_in[12];
    const float* affb  = (const float*)d_in[13];
    float* out = (float*)d_out;

    k_keysm<<<HEAD * NN / 8, 256>>>(mem);
    k_biasdyn<<<NN / 8, 256>>>(nv1, nv2, bpool);
    k_zero_kv<<<(BATCH * HEAD * DK * DK + 255) / 256, 256>>>();

    size_t smem1 = (size_t)(16384 + 16384 + 128 * XSTR) * 4;   // ~192.5 KB
    cudaFuncSetAttribute(k_qv, cudaFuncAttributeMaxDynamicSharedMemorySize, (int)smem1);
    k_qv<<<dim3(NTILES, BATCH), 512, smem1>>>(x, qw, qb, vw, vb);

    size_t smem2 = (size_t)(16384 + 128 * XSTR + 4096 + 4096) * 4;  // ~160.5 KB
    cudaFuncSetAttribute(k_out, cudaFuncAttributeMaxDynamicSharedMemorySize, (int)smem2);
    k_out<<<dim3(NTILES, BATCH), 512, smem2>>>(cw, cb, wpool, affw, affb, out);
}

// round 4
// speedup vs baseline: 2.7040x; 1.1520x over previous
#include <cuda_runtime.h>
#include <math.h>

#define BATCH 64
#define DMODEL 128
#define NN 2048
#define HEAD 4
#define DK 32
#define NT 128          // node tile
#define NTILES (NN/NT)  // 16

static __device__ float g_keysm[HEAD * NN * DK];               // 1 MB
static __device__ float g_biasdyn[NN * DK];                    // 256 KB
static __device__ float g_kv[BATCH * HEAD * DK * DK];          // 1 MB
// q softmaxed, CHANNEL-MAJOR: [(b*4+h)*32 + x][node]  (b*128+row)*2048+node
static __device__ float g_qsm[(size_t)BATCH * HEAD * DK * NN]; // 67 MB
static __device__ float g_v[(size_t)BATCH * DMODEL * NN];      // 67 MB

__device__ __forceinline__ float warp_max(float v) {
    #pragma unroll
    for (int o = 16; o; o >>= 1) v = fmaxf(v, __shfl_xor_sync(0xffffffffu, v, o));
    return v;
}
__device__ __forceinline__ float warp_sum(float v) {
    #pragma unroll
    for (int o = 16; o; o >>= 1) v += __shfl_xor_sync(0xffffffffu, v, o);
    return v;
}

// ---------------- P1: key softmax over d_k -------------------------------
__global__ void k_keysm(const float* __restrict__ mem) {
    const float inv_scale = 0.17677669529663687f; // 1/sqrt(32)
    int row = blockIdx.x * 8 + (threadIdx.x >> 5);
    int lane = threadIdx.x & 31;
    float v = mem[row * 32 + lane] * inv_scale;
    float m = warp_max(v);
    float e = __expf(v - m);
    float s = warp_sum(e);
    g_keysm[row * 32 + lane] = e / s;
}

// ---------------- P2: bias_dyn, 8 rows per block -------------------------
__global__ __launch_bounds__(256) void k_biasdyn(const float* __restrict__ nv1,
                                                 const float* __restrict__ nv2,
                                                 const float* __restrict__ bpool) {
    __shared__ float p[8][NN];
    __shared__ float red[256];
    __shared__ float a1[8][10];
    __shared__ float invs[8];
    int n0 = blockIdx.x * 8;
    int t = threadIdx.x;
    if (t < 80) a1[t / 10][t % 10] = nv1[(n0 + t / 10) * 10 + (t % 10)];
    __syncthreads();

    for (int r = 0; r < 8; r++) {
        float lv[8];
        float lmax = 0.0f;
        #pragma unroll
        for (int i = 0; i < 8; i++) {
            int m = t + i * 256;
            float acc = 0.0f;
            #pragma unroll
            for (int k = 0; k < 10; k++) acc += a1[r][k] * nv2[k * NN + m];
            acc = fmaxf(acc, 0.0f);
            lv[i] = acc;
            lmax = fmaxf(lmax, acc);
        }
        red[t] = lmax; __syncthreads();
        for (int s = 128; s; s >>= 1) { if (t < s) red[t] = fmaxf(red[t], red[t + s]); __syncthreads(); }
        float bmax = red[0];
        __syncthreads();
        float lsum = 0.0f;
        #pragma unroll
        for (int i = 0; i < 8; i++) {
            float e = __expf(lv[i] - bmax);
            p[r][t + i * 256] = e;
            lsum += e;
        }
        red[t] = lsum; __syncthreads();
        for (int s = 128; s; s >>= 1) { if (t < s) red[t] += red[t + s]; __syncthreads(); }
        if (t == 0) invs[r] = 1.0f / red[0];
        __syncthreads();
    }

    int c = t & 31, g = t >> 5;
    float acc[8];
    #pragma unroll
    for (int r = 0; r < 8; r++) acc[r] = 0.0f;
    for (int m = g; m < NN; m += 8) {
        float bp = bpool[m * 32 + c];
        #pragma unroll
        for (int r = 0; r < 8; r++) acc[r] += p[r][m] * bp;
    }
    for (int r = 0; r < 8; r++) {
        red[t] = acc[r]; __syncthreads();
        if (t < 32) {
            float s2 = 0.0f;
            #pragma unroll
            for (int g2 = 0; g2 < 8; g2++) s2 += red[g2 * 32 + t];
            g_biasdyn[(n0 + r) * 32 + t] = s2 * invs[r];
        }
        __syncthreads();
    }
}

// ---------------- P3: zero kv -------------------------------------------
__global__ void k_zero_kv() {
    int i = blockIdx.x * 256 + threadIdx.x;
    if (i < BATCH * HEAD * DK * DK) g_kv[i] = 0.0f;
}

// ---------------- K1: fused Q/V conv + q softmax + kv partials -----------
// 512 threads. Quad mapping: warp w -> head h=w&3; quad (l>>2) -> node group
// g=(w>>2)*8+(l>>2); lane's c4=l&3 -> channels h*32+c4*8..+8; nodes g*4..+4.
// smem: wqT 16384 | wvT 16384 | xs 16512 (conv: stride 128; reused as vt stride 129)
__global__ __launch_bounds__(512, 1) void k_qv(const float* __restrict__ x,
                                               const float* __restrict__ qw,
                                               const float* __restrict__ qb,
                                               const float* __restrict__ vw,
                                               const float* __restrict__ vb) {
    extern __shared__ float sm[];
    float* wqT = sm;                 // [k*128+o]; reused as keysm tile
    float* wvT = sm + 16384;
    float* xs  = sm + 32768;         // [c*128+j]; reused as vt [c*129+j]

    int b = blockIdx.y;
    int n0 = blockIdx.x * NT;
    int t = threadIdx.x;

    for (int i = t; i < 16384; i += 512) {
        int o = i >> 7, k = i & 127;
        wqT[k * 128 + o] = qw[i];
        wvT[k * 128 + o] = vw[i];
    }
    for (int i = t; i < 16384; i += 512) {
        int c = i >> 7, j = i & 127;
        xs[c * 128 + j] = x[((size_t)b * 128 + c) * NN + n0 + j];
    }
    __syncthreads();

    int w = t >> 5, l = t & 31;
    int h = w & 3;
    int g = ((w >> 2) << 3) + (l >> 2);
    int c4 = l & 3;
    int jn = g * 4;                   // node base (4 nodes)
    int c0t = h * 32 + c4 * 8;        // channel base (8 channels)
    const float inv_scale = 0.17677669529663687f;

    float qa[8][4], va[8][4];
    #pragma unroll
    for (int i = 0; i < 8; i++) {
        float qbi = qb[c0t + i], vbi = vb[c0t + i];
        #pragma unroll
        for (int n = 0; n < 4; n++) { qa[i][n] = qbi; va[i][n] = vbi; }
    }

    for (int k = 0; k < 128; k++) {
        float4 xv = *(const float4*)(xs + k * 128 + jn);
        float4 wq0 = *(const float4*)(wqT + k * 128 + c0t);
        float4 wq1 = *(const float4*)(wqT + k * 128 + c0t + 4);
        float4 wv0 = *(const float4*)(wvT + k * 128 + c0t);
        float4 wv1 = *(const float4*)(wvT + k * 128 + c0t + 4);
        float wqa[8] = {wq0.x, wq0.y, wq0.z, wq0.w, wq1.x, wq1.y, wq1.z, wq1.w};
        float wva[8] = {wv0.x, wv0.y, wv0.z, wv0.w, wv1.x, wv1.y, wv1.z, wv1.w};
        float xva[4] = {xv.x, xv.y, xv.z, xv.w};
        #pragma unroll
        for (int i = 0; i < 8; i++)
            #pragma unroll
            for (int n = 0; n < 4; n++) {
                qa[i][n] += wqa[i] * xva[n];
                va[i][n] += wva[i] * xva[n];
            }
    }

    // ---- q: relu -> softmax over 32 channels (quad c4 cooperation) ----
    #pragma unroll
    for (int n = 0; n < 4; n++) {
        float m = 0.0f;
        #pragma unroll
        for (int i = 0; i < 8; i++) { qa[i][n] = fmaxf(qa[i][n], 0.0f); m = fmaxf(m, qa[i][n]); }
        m = fmaxf(m, __shfl_xor_sync(0xffffffffu, m, 1));
        m = fmaxf(m, __shfl_xor_sync(0xffffffffu, m, 2));
        float s = 0.0f;
        #pragma unroll
        for (int i = 0; i < 8; i++) { qa[i][n] = __expf((qa[i][n] - m) * inv_scale); s += qa[i][n]; }
        s += __shfl_xor_sync(0xffffffffu, s, 1);
        s += __shfl_xor_sync(0xffffffffu, s, 2);
        float is = 1.0f / s;
        #pragma unroll
        for (int i = 0; i < 8; i++) qa[i][n] *= is;
    }
    // write q channel-major: g_qsm[(b*128 + h*32 + c)*2048 + node]
    #pragma unroll
    for (int i = 0; i < 8; i++) {
        float4* dst = (float4*)(g_qsm + ((size_t)b * 128 + c0t + i) * NN + n0 + jn);
        *dst = make_float4(qa[i][0], qa[i][1], qa[i][2], qa[i][3]);
    }

    // ---- v: relu, store global ----
    #pragma unroll
    for (int i = 0; i < 8; i++)
        #pragma unroll
        for (int n = 0; n < 4; n++) va[i][n] = fmaxf(va[i][n], 0.0f);
    #pragma unroll
    for (int i = 0; i < 8; i++) {
        float4* dst = (float4*)(g_v + ((size_t)b * 128 + c0t + i) * NN + n0 + jn);
        *dst = make_float4(va[i][0], va[i][1], va[i][2], va[i][3]);
    }

    __syncthreads();   // conv reads of xs/wqT done

    // vt into xs region (stride 129, scalar writes; reads conflict-free later)
    #pragma unroll
    for (int i = 0; i < 8; i++)
        #pragma unroll
        for (int n = 0; n < 4; n++)
            xs[(c0t + i) * 129 + jn + n] = va[i][n];
    // keysm tile into wqT region: ks[(h2*128 + j2)*32 + xk]
    for (int i = t; i < 16384; i += 512) {
        int h2 = i >> 12, r = i & 4095;
        int j2 = r >> 5, xk = r & 31;
        wqT[i] = g_keysm[(h2 * NN + n0 + j2) * 32 + xk];
    }
    __syncthreads();

    // kv partial: kv[h,x,y] += sum_j ks[h,j,x]*V[h*32+y, j]
    int idx = t & 127;
    int h2 = t >> 7;
    int x0 = (idx >> 4) * 4;
    int y0 = (idx & 15) * 2;
    float acc[4][2];
    #pragma unroll
    for (int a = 0; a < 4; a++) { acc[a][0] = 0.0f; acc[a][1] = 0.0f; }

    #pragma unroll 4
    for (int jj = 0; jj < NT; jj++) {
        float4 kx = *(const float4*)(wqT + (h2 * NT + jj) * 32 + x0);
        float v0 = xs[(h2 * 32 + y0 + 0) * 129 + jj];
        float v1 = xs[(h2 * 32 + y0 + 1) * 129 + jj];
        acc[0][0] += kx.x * v0; acc[0][1] += kx.x * v1;
        acc[1][0] += kx.y * v0; acc[1][1] += kx.y * v1;
        acc[2][0] += kx.z * v0; acc[2][1] += kx.z * v1;
        acc[3][0] += kx.w * v0; acc[3][1] += kx.w * v1;
    }
    #pragma unroll
    for (int xi = 0; xi < 4; xi++)
        #pragma unroll
        for (int yi = 0; yi < 2; yi++)
            atomicAdd(&g_kv[(((size_t)b * HEAD + h2) * DK + x0 + xi) * DK + y0 + yi],
                      acc[xi][yi]);
}

// ---------------- K2: attn + output conv + affine ------------------------
// 512 threads, quad mapping as in K1.
// smem: cwT 16384 | P 128*132=16896 (qs then pre) | kvs 128*36=4608
__global__ __launch_bounds__(512, 1) void k_out(const float* __restrict__ cw,
                                                const float* __restrict__ cb,
                                                const float* __restrict__ wpool,
                                                const float* __restrict__ affw,
                                                const float* __restrict__ affb,
                                                float* __restrict__ out) {
    extern __shared__ float sm[];
    float* cwT = sm;              // [k*128+o]
    float* P   = sm + 16384;      // [row*132 + j]: qs, then pre
    float* kvs = sm + 33280;      // [(h*32+x)*36 + y]

    int b = blockIdx.y;
    int n0 = blockIdx.x * NT;
    int t = threadIdx.x;

    for (int i = t; i < 16384; i += 512) {
        int o = i >> 7, k = i & 127;
        cwT[k * 128 + o] = cw[i];
    }
    for (int i = t; i < 4096; i += 512) {
        int row = i >> 5, y = i & 31;
        kvs[row * 36 + y] = g_kv[(size_t)b * 4096 + i];
    }
    // stage q (channel-major in gmem -> coalesced copy)
    for (int i = t; i < 4096; i += 512) {
        int row = i >> 5, cc = (i & 31) * 4;
        float4 v4 = *(const float4*)(g_qsm + ((size_t)b * 128 + row) * NN + n0 + cc);
        *(float4*)(P + row * 132 + cc) = v4;
    }
    float S = 0.0f;
    #pragma unroll
    for (int i = 0; i < 9; i++) S += wpool[i];
    __syncthreads();

    int w = t >> 5, l = t & 31;
    int h = w & 3;
    int g = ((w >> 2) << 3) + (l >> 2);
    int c4 = l & 3;
    int jn = g * 4;
    int c0t = h * 32 + c4 * 8;

    // ---- attn: acc[i][n] = bias_dyn + sum_x q[x][n]*kv[x][c] + S*V ----
    float acc[8][4];
    #pragma unroll
    for (int n = 0; n < 4; n++) {
        const float* bsrc = g_biasdyn + (n0 + jn + n) * 32 + c4 * 8;
        #pragma unroll
        for (int i = 0; i < 8; i++) acc[i][n] = bsrc[i];
    }
    #pragma unroll 4
    for (int xk = 0; xk < 32; xk++) {
        float4 qv = *(const float4*)(P + (h * 32 + xk) * 132 + jn);
        float4 k0 = *(const float4*)(kvs + (h * 32 + xk) * 36 + c4 * 8);
        float4 k1 = *(const float4*)(kvs + (h * 32 + xk) * 36 + c4 * 8 + 4);
        float ka[8] = {k0.x, k0.y, k0.z, k0.w, k1.x, k1.y, k1.z, k1.w};
        float qn[4] = {qv.x, qv.y, qv.z, qv.w};
        #pragma unroll
        for (int i = 0; i < 8; i++)
            #pragma unroll
            for (int n = 0; n < 4; n++)
                acc[i][n] += ka[i] * qn[n];
    }
    #pragma unroll
    for (int i = 0; i < 8; i++) {
        float4 v4 = *(const float4*)(g_v + ((size_t)b * 128 + c0t + i) * NN + n0 + jn);
        acc[i][0] += S * v4.x; acc[i][1] += S * v4.y;
        acc[i][2] += S * v4.z; acc[i][3] += S * v4.w;
    }
    __syncthreads();   // all q reads of P done
    #pragma unroll
    for (int i = 0; i < 8; i++)
        *(float4*)(P + (c0t + i) * 132 + jn) =
            make_float4(acc[i][0], acc[i][1], acc[i][2], acc[i][3]);
    __syncthreads();

    // ---- output conv ----
    float oacc[8][4];
    #pragma unroll
    for (int i = 0; i < 8; i++) {
        float cbi = cb[c0t + i];
        #pragma unroll
        for (int n = 0; n < 4; n++) oacc[i][n] = cbi;
    }
    for (int k = 0; k < 128; k++) {
        float4 pv = *(const float4*)(P + k * 132 + jn);
        float4 c0_ = *(const float4*)(cwT + k * 128 + c0t);
        float4 c1_ = *(const float4*)(cwT + k * 128 + c0t + 4);
        float ca[8] = {c0_.x, c0_.y, c0_.z, c0_.w, c1_.x, c1_.y, c1_.z, c1_.w};
        float pn[4] = {pv.x, pv.y, pv.z, pv.w};
        #pragma unroll
        for (int i = 0; i < 8; i++)
            #pragma unroll
            for (int n = 0; n < 4; n++)
                oacc[i][n] += ca[i] * pn[n];
    }
    #pragma unroll
    for (int i = 0; i < 8; i++) {
        int o = c0t + i;
        float4 wv = *(const float4*)(affw + (size_t)o * NN + n0 + jn);
        float4 bv = *(const float4*)(affb + (size_t)o * NN + n0 + jn);
        float wa[4] = {wv.x, wv.y, wv.z, wv.w};
        float ba[4] = {bv.x, bv.y, bv.z, bv.w};
        float ra[4];
        #pragma unroll
        for (int n = 0; n < 4; n++) {
            float r = fmaxf(oacc[i][n], 0.0f);
            ra[n] = r + r * wa[n] + ba[n];
        }
        *(float4*)(out + ((size_t)b * 128 + o) * NN + n0 + jn) =
            make_float4(ra[0], ra[1], ra[2], ra[3]);
    }
}

extern "C" void kernel_launch(void* const* d_in, const int* in_sizes, int n_in,
                              void* d_out, int out_size) {
    const float* x     = (const float*)d_in[0];
    const float* qw    = (const float*)d_in[1];
    const float* qb    = (const float*)d_in[2];
    const float* vw    = (const float*)d_in[3];
    const float* vb    = (const float*)d_in[4];
    const float* cw    = (const float*)d_in[5];
    const float* cb    = (const float*)d_in[6];
    const float* mem   = (const float*)d_in[7];
    const float* nv1   = (const float*)d_in[8];
    const float* nv2   = (const float*)d_in[9];
    const float* wpool = (const float*)d_in[10];
    const float* bpool = (const float*)d_in[11];
    const float* affw  = (const float*)d_in[12];
    const float* affb  = (const float*)d_in[13];
    float* out = (float*)d_out;

    k_keysm<<<HEAD * NN / 8, 256>>>(mem);
    k_biasdyn<<<NN / 8, 256>>>(nv1, nv2, bpool);
    k_zero_kv<<<(BATCH * HEAD * DK * DK + 255) / 256, 256>>>();

    size_t smem1 = (size_t)(16384 + 16384 + 16512) * 4;   // 192.5 KB
    cudaFuncSetAttribute(k_qv, cudaFuncAttributeMaxDynamicSharedMemorySize, (int)smem1);
    k_qv<<<dim3(NTILES, BATCH), 512, smem1>>>(x, qw, qb, vw, vb);

    size_t smem2 = (size_t)(16384 + 16896 + 4608) * 4;    // 148 KB
    cudaFuncSetAttribute(k_out, cudaFuncAttributeMaxDynamicSharedMemorySize, (int)smem2);
    k_out<<<dim3(NTILES, BATCH), 512, smem2>>>(cw, cb, wpool, affw, affb, out);
}

// round 7
// speedup vs baseline: 3.2120x; 1.1879x over previous
#include <cuda_runtime.h>
#include <cuda_bf16.h>
#include <math.h>
#include <stdint.h>

#define BATCH 64
#define DMODEL 128
#define NN 2048
#define HEAD 4
#define DK 32
#define NT 128
#define NTILES (NN/NT)  // 16

// smem region byte offsets (k_qv / k_out share the layout)
#define OFF_A 0            // 69632 B : operand A hi(34816)+lo(34816), stride 136 bf16
#define OFF_B 69632        // 69632 B : operand B hi+lo
#define OFF_D 139264       // 66048 B : fp32 D [128][129]
#define OFF_SB 205312      // 1024 B : biases (256 floats)
#define SMEM_SZ 206336
#define IMG_HALF 34816     // 128 rows * 272 B
#define ROWB 272           // 136 bf16 row stride in smem

// ---------------- device globals ----------------
static __device__ float g_keysm[HEAD * NN * DK];
static __device__ float g_biasdyn[NN * DK];
static __device__ float g_kv[BATCH * HEAD * DK * DK];
static __device__ float g_bias2[DMODEL * NN];
static __device__ float g_Cp[DMODEL * DK];
// packed gmem images: hi [128][128] bf16 (32768B) then lo (32768B)
static __device__ __align__(16) unsigned char g_wimg[3 * 65536];                      // Wq, Wv, Cs
static __device__ __align__(16) unsigned char g_xbf[(size_t)BATCH * NTILES * 65536];  // x^T per tile
static __device__ __align__(16) unsigned char g_qimg[(size_t)BATCH * NTILES * 65536]; // q^T per tile
static __device__ __align__(16) unsigned char g_vimg[(size_t)BATCH * NTILES * 65536]; // v^T per tile
static __device__ __align__(16) unsigned char g_Mb[(size_t)BATCH * 65536];            // Mb per batch

// ---------------- helpers ----------------
__device__ __forceinline__ uint32_t smem_u32(const void* p) {
    uint32_t a;
    asm("{ .reg .u64 t; cvta.to.shared.u64 t, %1; cvt.u32.u64 %0, t; }" : "=r"(a) : "l"(p));
    return a;
}
__device__ __forceinline__ void bf_split(float v, unsigned short& h, unsigned short& l) {
    __nv_bfloat16 bh = __float2bfloat16(v);
    h = __bfloat16_as_ushort(bh);
    l = __bfloat16_as_ushort(__float2bfloat16(v - __bfloat162float(bh)));
}
__device__ __forceinline__ uint4 pack8(const unsigned short* h) {
    uint4 u;
    u.x = (uint32_t)h[0] | ((uint32_t)h[1] << 16);
    u.y = (uint32_t)h[2] | ((uint32_t)h[3] << 16);
    u.z = (uint32_t)h[4] | ((uint32_t)h[5] << 16);
    u.w = (uint32_t)h[6] | ((uint32_t)h[7] << 16);
    return u;
}
__device__ __forceinline__ float warp_max(float v) {
    #pragma unroll
    for (int o = 16; o; o >>= 1) v = fmaxf(v, __shfl_xor_sync(0xffffffffu, v, o));
    return v;
}
__device__ __forceinline__ float warp_sum(float v) {
    #pragma unroll
    for (int o = 16; o; o >>= 1) v += __shfl_xor_sync(0xffffffffu, v, o);
    return v;
}
__device__ __forceinline__ void ldsm4(uint32_t addr, uint32_t& r0, uint32_t& r1,
                                      uint32_t& r2, uint32_t& r3) {
    asm volatile("ldmatrix.sync.aligned.m8n8.x4.shared.b16 {%0,%1,%2,%3}, [%4];"
                 : "=r"(r0), "=r"(r1), "=r"(r2), "=r"(r3) : "r"(addr));
}
__device__ __forceinline__ void mma16816(float d[4], const uint32_t a[4],
                                         uint32_t b0, uint32_t b1) {
    asm volatile("mma.sync.aligned.m16n8k16.row.col.f32.bf16.bf16.f32 "
                 "{%0,%1,%2,%3}, {%4,%5,%6,%7}, {%8,%9}, {%0,%1,%2,%3};"
                 : "+f"(d[0]), "+f"(d[1]), "+f"(d[2]), "+f"(d[3])
                 : "r"(a[0]), "r"(a[1]), "r"(a[2]), "r"(a[3]), "r"(b0), "r"(b1));
}

// gmem packed [128][128]x2 halves -> smem padded stride 136 (both halves)
__device__ __forceinline__ void load_img(const unsigned char* g, unsigned char* s, int t) {
    const uint4* src = (const uint4*)g;
    uint4* dst = (uint4*)s;
    #pragma unroll 1
    for (int half = 0; half < 2; half++)
        for (int i = t; i < 2048; i += 256) {
            int r = i >> 4, c = i & 15;
            dst[half * 2176 + r * 17 + c] = src[half * 2048 + i];
        }
}
__device__ __forceinline__ void store_img(unsigned char* g, const unsigned char* s, int t) {
    uint4* dst = (uint4*)g;
    const uint4* src = (const uint4*)s;
    #pragma unroll 1
    for (int half = 0; half < 2; half++)
        for (int i = t; i < 2048; i += 256) {
            int r = i >> 4, c = i & 15;
            dst[half * 2048 + i] = src[half * 2176 + r * 17 + c];
        }
}

// 3-pass hi/lo warp GEMM: D(64x32) += A(64x128) * B^T(32rows x 128)
__device__ __forceinline__ void gemm3(uint32_t Ahi, uint32_t Bhi, int wm, int wn,
                                      int lane, float D[4][4][4]) {
    int mat = lane >> 3, r8 = lane & 7;
    int arow = wm * 64 + ((mat & 1) << 3) + r8;
    int acol0 = (mat >> 1) << 3;
    int brow = wn * 32 + ((mat >> 1) << 3) + r8;
    int bcol0 = (mat & 1) << 3;
    #pragma unroll
    for (int p = 0; p < 3; p++) {
        uint32_t A = (p == 2) ? Ahi + IMG_HALF : Ahi;
        uint32_t B = (p == 1) ? Bhi + IMG_HALF : Bhi;
        #pragma unroll
        for (int ks = 0; ks < 8; ks++) {
            int k = ks * 16;
            uint32_t a[4][4];
            #pragma unroll
            for (int mt = 0; mt < 4; mt++)
                ldsm4(A + (arow + mt * 16) * ROWB + (k + acol0) * 2,
                      a[mt][0], a[mt][1], a[mt][2], a[mt][3]);
            uint32_t bf[2][4];
            #pragma unroll
            for (int bt = 0; bt < 2; bt++)
                ldsm4(B + (brow + bt * 16) * ROWB + (k + bcol0) * 2,
                      bf[bt][0], bf[bt][1], bf[bt][2], bf[bt][3]);
            #pragma unroll
            for (int mt = 0; mt < 4; mt++)
                #pragma unroll
                for (int nt = 0; nt < 4; nt++)
                    mma16816(D[mt][nt], a[mt], bf[nt >> 1][(nt & 1) * 2],
                             bf[nt >> 1][(nt & 1) * 2 + 1]);
        }
    }
}
__device__ __forceinline__ void dzero(float D[4][4][4]) {
    #pragma unroll
    for (int mt = 0; mt < 4; mt++)
        #pragma unroll
        for (int nt = 0; nt < 4; nt++)
            #pragma unroll
            for (int i = 0; i < 4; i++) D[mt][nt][i] = 0.0f;
}
__device__ __forceinline__ void dwrite(float* Dsm, int wm, int wn, int lane, float D[4][4][4]) {
    int r = lane >> 2, cc = (lane & 3) * 2;
    #pragma unroll
    for (int mt = 0; mt < 4; mt++)
        #pragma unroll
        for (int nt = 0; nt < 4; nt++) {
            int row = wm * 64 + mt * 16 + r;
            int col = wn * 32 + nt * 8 + cc;
            Dsm[row * 129 + col] = D[mt][nt][0];
            Dsm[row * 129 + col + 1] = D[mt][nt][1];
            Dsm[(row + 8) * 129 + col] = D[mt][nt][2];
            Dsm[(row + 8) * 129 + col + 1] = D[mt][nt][3];
        }
}

// ---------------- P1: key softmax ----------------
__global__ void k_keysm(const float* __restrict__ mem) {
    const float inv_scale = 0.17677669529663687f;
    int row = blockIdx.x * 8 + (threadIdx.x >> 5);
    int lane = threadIdx.x & 31;
    float v = mem[row * 32 + lane] * inv_scale;
    float m = warp_max(v);
    float e = __expf(v - m);
    float s = warp_sum(e);
    g_keysm[row * 32 + lane] = e / s;
}

// ---------------- P2: bias_dyn ----------------
__global__ __launch_bounds__(256) void k_biasdyn(const float* __restrict__ nv1,
                                                 const float* __restrict__ nv2,
                                                 const float* __restrict__ bpool) {
    __shared__ float p[8][NN];
    __shared__ float red[256];
    __shared__ float a1[8][10];
    __shared__ float invs[8];
    int n0 = blockIdx.x * 8;
    int t = threadIdx.x;
    if (t < 80) a1[t / 10][t % 10] = nv1[(n0 + t / 10) * 10 + (t % 10)];
    __syncthreads();
    for (int r = 0; r < 8; r++) {
        float lv[8];
        float lmax = 0.0f;
        #pragma unroll
        for (int i = 0; i < 8; i++) {
            int m = t + i * 256;
            float acc = 0.0f;
            #pragma unroll
            for (int k = 0; k < 10; k++) acc += a1[r][k] * nv2[k * NN + m];
            acc = fmaxf(acc, 0.0f);
            lv[i] = acc;
            lmax = fmaxf(lmax, acc);
        }
        red[t] = lmax; __syncthreads();
        for (int s = 128; s; s >>= 1) { if (t < s) red[t] = fmaxf(red[t], red[t + s]); __syncthreads(); }
        float bmax = red[0];
        __syncthreads();
        float lsum = 0.0f;
        #pragma unroll
        for (int i = 0; i < 8; i++) {
            float e = __expf(lv[i] - bmax);
            p[r][t + i * 256] = e;
            lsum += e;
        }
        red[t] = lsum; __syncthreads();
        for (int s = 128; s; s >>= 1) { if (t < s) red[t] += red[t + s]; __syncthreads(); }
        if (t == 0) invs[r] = 1.0f / red[0];
        __syncthreads();
    }
    int c = t & 31, g = t >> 5;
    float acc[8];
    #pragma unroll
    for (int r = 0; r < 8; r++) acc[r] = 0.0f;
    for (int m = g; m < NN; m += 8) {
        float bp = bpool[m * 32 + c];
        #pragma unroll
        for (int r = 0; r < 8; r++) acc[r] += p[r][m] * bp;
    }
    for (int r = 0; r < 8; r++) {
        red[t] = acc[r]; __syncthreads();
        if (t < 32) {
            float s2 = 0.0f;
            #pragma unroll
            for (int g2 = 0; g2 < 8; g2++) s2 += red[g2 * 32 + t];
            g_biasdyn[(n0 + r) * 32 + t] = s2 * invs[r];
        }
        __syncthreads();
    }
}

// ---------------- P3: zero kv ----------------
__global__ void k_zero_kv() {
    int i = blockIdx.x * 256 + threadIdx.x;
    if (i < BATCH * HEAD * DK * DK) g_kv[i] = 0.0f;
}

// ---------------- P4: weight images + Cp ----------------
__global__ __launch_bounds__(128) void k_prepw(const float* __restrict__ qw,
                                               const float* __restrict__ vw,
                                               const float* __restrict__ cw,
                                               const float* __restrict__ wpool) {
    int m = blockIdx.x;
    int o = threadIdx.x;
    if (m == 3) {
        for (int y = 0; y < 32; y++) {
            float s = 0.0f;
            #pragma unroll
            for (int h = 0; h < 4; h++) s += cw[o * 128 + h * 32 + y];
            g_Cp[o * 32 + y] = s;
        }
        return;
    }
    const float* w = (m == 0) ? qw : (m == 1) ? vw : cw;
    float scale = 1.0f;
    if (m == 2) {
        float S = 0.0f;
        #pragma unroll
        for (int i = 0; i < 9; i++) S += wpool[i];
        scale = S;
    }
    unsigned char* img = g_wimg + m * 65536;
    for (int cc = 0; cc < 16; cc++) {
        unsigned short hs[8], ls[8];
        #pragma unroll
        for (int k = 0; k < 8; k++) bf_split(w[o * 128 + cc * 8 + k] * scale, hs[k], ls[k]);
        int byte = (o * 128 + cc * 8) * 2;
        *(uint4*)(img + byte) = pack8(hs);
        *(uint4*)(img + 32768 + byte) = pack8(ls);
    }
}

// ---------------- P4b: bias2 = Cp @ bias_dyn^T ----------------
__global__ __launch_bounds__(128) void k_bias2() {
    __shared__ float bd[32];
    int n = blockIdx.x, t = threadIdx.x;
    if (t < 32) bd[t] = g_biasdyn[n * 32 + t];
    __syncthreads();
    float s = 0.0f;
    #pragma unroll
    for (int y = 0; y < 32; y++) s += g_Cp[t * 32 + y] * bd[y];
    g_bias2[t * NN + n] = s;
}

// ---------------- P5: x -> x^T bf16 hi/lo image per tile ----------------
__global__ __launch_bounds__(256) void k_prepx(const float* __restrict__ x) {
    extern __shared__ __align__(16) unsigned char psm[];
    float* stage = (float*)psm;   // [c][129]
    int b = blockIdx.y, n0 = blockIdx.x * NT, t = threadIdx.x;
    for (int i = t; i < 16384; i += 256) {
        int c = i >> 7, n = i & 127;
        stage[c * 129 + n] = x[((size_t)b * 128 + c) * NN + n0 + n];
    }
    __syncthreads();
    unsigned char* img = g_xbf + ((size_t)(b * NTILES + blockIdx.x)) * 65536;
    int node = t >> 1, half = t & 1;
    for (int cc = 0; cc < 8; cc++) {
        int c0 = half * 64 + cc * 8;
        unsigned short hs[8], ls[8];
        #pragma unroll
        for (int k = 0; k < 8; k++) bf_split(stage[(c0 + k) * 129 + node], hs[k], ls[k]);
        int byte = (node * 128 + c0) * 2;
        *(uint4*)(img + byte) = pack8(hs);
        *(uint4*)(img + 32768 + byte) = pack8(ls);
    }
}

// ---------------- K1: Q/V convs (warp-MMA) + softmax + kv partial --------
__global__ __launch_bounds__(256, 1) void k_qv(const float* __restrict__ qb,
                                               const float* __restrict__ vb) {
    extern __shared__ __align__(16) unsigned char sm[];
    int b = blockIdx.y, tile = blockIdx.x, n0 = tile * NT, t = threadIdx.x;
    uint32_t sb = smem_u32(sm);
    float* Dsm = (float*)(sm + OFF_D);
    float* sbias = (float*)(sm + OFF_SB);
    int w = t >> 5, lane = t & 31;
    int wm = w & 1, wn = w >> 1;
    const unsigned char* xg = g_xbf + ((size_t)(b * NTILES + tile)) * 65536;

    load_img(g_wimg, sm + OFF_A, t);                 // Wq
    load_img(xg, sm + OFF_B, t);                     // x^T
    if (t < 128) sbias[t] = qb[t]; else sbias[t] = vb[t - 128];
    __syncthreads();

    float D[4][4][4];
    dzero(D);
    gemm3(sb + OFF_A, sb + OFF_B, wm, wn, lane, D);  // Q = Wq @ x
    dwrite(Dsm, wm, wn, lane, D);
    __syncthreads();

    // ---- Q epilogue: per-node softmax over each head's 32 channels ----
    const float inv_scale = 0.17677669529663687f;
    {
        int node = t & 127, hb = t >> 7;
        #pragma unroll
        for (int hh = 0; hh < 2; hh++) {
            int h = hb + hh * 2;
            float q[32];
            float mx = 0.0f;
            #pragma unroll
            for (int i = 0; i < 32; i++) {
                q[i] = fmaxf(Dsm[(h * 32 + i) * 129 + node] + sbias[h * 32 + i], 0.0f);
                mx = fmaxf(mx, q[i]);
            }
            float s = 0.0f;
            #pragma unroll
            for (int i = 0; i < 32; i++) { q[i] = __expf((q[i] - mx) * inv_scale); s += q[i]; }
            float is = 1.0f / s;
            #pragma unroll
            for (int cc = 0; cc < 4; cc++) {
                unsigned short hs[8], ls[8];
                #pragma unroll
                for (int k = 0; k < 8; k++) bf_split(q[cc * 8 + k] * is, hs[k], ls[k]);
                int byte = node * ROWB + (h * 32 + cc * 8) * 2;
                *(uint4*)(sm + OFF_A + byte) = pack8(hs);
                *(uint4*)(sm + OFF_A + IMG_HALF + byte) = pack8(ls);
            }
        }
    }
    __syncthreads();
    store_img(g_qimg + ((size_t)(b * NTILES + tile)) * 65536, sm + OFF_A, t);
    __syncthreads();

    load_img(g_wimg + 65536, sm + OFF_A, t);         // Wv
    __syncthreads();
    dzero(D);
    gemm3(sb + OFF_A, sb + OFF_B, wm, wn, lane, D);  // V = Wv @ x
    dwrite(Dsm, wm, wn, lane, D);
    __syncthreads();

    // ---- V epilogue: relu (writeback) + bf16 image ----
    {
        int node = t & 127, hb = t >> 7;
        #pragma unroll
        for (int hh = 0; hh < 2; hh++) {
            int h = hb + hh * 2;
            float v[32];
            #pragma unroll
            for (int i = 0; i < 32; i++) {
                v[i] = fmaxf(Dsm[(h * 32 + i) * 129 + node] + sbias[128 + h * 32 + i], 0.0f);
                Dsm[(h * 32 + i) * 129 + node] = v[i];
            }
            #pragma unroll
            for (int cc = 0; cc < 4; cc++) {
                unsigned short hs[8], ls[8];
                #pragma unroll
                for (int k = 0; k < 8; k++) bf_split(v[cc * 8 + k], hs[k], ls[k]);
                int byte = node * ROWB + (h * 32 + cc * 8) * 2;
                *(uint4*)(sm + OFF_A + byte) = pack8(hs);
                *(uint4*)(sm + OFF_A + IMG_HALF + byte) = pack8(ls);
            }
        }
    }
    __syncthreads();
    store_img(g_vimg + ((size_t)(b * NTILES + tile)) * 65536, sm + OFF_A, t);
    __syncthreads();

    // ---- ks tile into A region, then kv partial ----
    float* ks = (float*)(sm + OFF_A);   // [(h*128 + j)*32 + x], 64KB
    for (int i = t; i < 16384; i += 256) {
        int h2 = i >> 12, r = i & 4095;
        int j2 = r >> 5, xk = r & 31;
        ks[i] = g_keysm[(h2 * NN + n0 + j2) * 32 + xk];
    }
    __syncthreads();
    {
        int idx = t & 63, h2 = t >> 6;
        int x0 = (idx >> 3) * 4, y0 = (idx & 7) * 4;
        float acc[4][4];
        #pragma unroll
        for (int a = 0; a < 4; a++)
            #pragma unroll
            for (int c = 0; c < 4; c++) acc[a][c] = 0.0f;
        #pragma unroll 4
        for (int jj = 0; jj < NT; jj++) {
            float4 kx = *(const float4*)(ks + (h2 * NT + jj) * 32 + x0);
            float vy[4];
            #pragma unroll
            for (int yi = 0; yi < 4; yi++) vy[yi] = Dsm[(h2 * 32 + y0 + yi) * 129 + jj];
            #pragma unroll
            for (int yi = 0; yi < 4; yi++) {
                acc[0][yi] += kx.x * vy[yi];
                acc[1][yi] += kx.y * vy[yi];
                acc[2][yi] += kx.z * vy[yi];
                acc[3][yi] += kx.w * vy[yi];
            }
        }
        #pragma unroll
        for (int xi = 0; xi < 4; xi++)
            #pragma unroll
            for (int yi = 0; yi < 4; yi++)
                atomicAdd(&g_kv[(((size_t)b * HEAD + h2) * DK + x0 + xi) * DK + y0 + yi],
                          acc[xi][yi]);
    }
}

// ---------------- P6: Mb[o][h*32+x] = sum_y cw[o][h*32+y]*kv[b,h,x,y] -----
__global__ __launch_bounds__(512) void k_mb(const float* __restrict__ cw) {
    __shared__ float kvT[32 * 128];   // [y][h*32+x]
    int b = blockIdx.x, t = threadIdx.x;
    for (int i = t; i < 4096; i += 512) {
        int row = i >> 5, y = i & 31;
        kvT[y * 128 + row] = g_kv[(size_t)b * 4096 + i];
    }
    __syncthreads();
    int o = t & 127, h = t >> 7;
    float acc[32];
    #pragma unroll
    for (int x = 0; x < 32; x++) acc[x] = 0.0f;
    for (int y = 0; y < 32; y++) {
        float cv = cw[o * 128 + h * 32 + y];
        const float* kr = kvT + y * 128 + h * 32;
        #pragma unroll
        for (int x = 0; x < 32; x++) acc[x] += cv * kr[x];
    }
    unsigned char* img = g_Mb + (size_t)b * 65536;
    for (int cc = 0; cc < 4; cc++) {
        unsigned short hs[8], ls[8];
        #pragma unroll
        for (int k = 0; k < 8; k++) bf_split(acc[cc * 8 + k], hs[k], ls[k]);
        int byte = (o * 128 + h * 32 + cc * 8) * 2;
        *(uint4*)(img + byte) = pack8(hs);
        *(uint4*)(img + 32768 + byte) = pack8(ls);
    }
}

// ---------------- K2: out = relu(Mb@q + Cs@v + bias2 + cb) -> affine -----
__global__ __launch_bounds__(256, 1) void k_out(const float* __restrict__ cb,
                                                const float* __restrict__ affw,
                                                const float* __restrict__ affb,
                                                float* __restrict__ out) {
    extern __shared__ __align__(16) unsigned char sm[];
    int b = blockIdx.y, tile = blockIdx.x, n0 = tile * NT, t = threadIdx.x;
    uint32_t sb = smem_u32(sm);
    float* Dsm = (float*)(sm + OFF_D);
    float* sbias = (float*)(sm + OFF_SB);
    int w = t >> 5, lane = t & 31;
    int wm = w & 1, wn = w >> 1;

    load_img(g_Mb + (size_t)b * 65536, sm + OFF_A, t);
    load_img(g_qimg + ((size_t)(b * NTILES + tile)) * 65536, sm + OFF_B, t);
    if (t < 128) sbias[t] = cb[t];
    __syncthreads();

    float D[4][4][4];
    dzero(D);
    gemm3(sb + OFF_A, sb + OFF_B, wm, wn, lane, D);  // Mb @ q
    __syncthreads();
    load_img(g_wimg + 2 * 65536, sm + OFF_A, t);     // Cs
    load_img(g_vimg + ((size_t)(b * NTILES + tile)) * 65536, sm + OFF_B, t);
    __syncthreads();
    gemm3(sb + OFF_A, sb + OFF_B, wm, wn, lane, D);  // += Cs @ v
    dwrite(Dsm, wm, wn, lane, D);
    __syncthreads();

    // ---- epilogue: coalesced out writes (warp = 16 channels, lane = node) --
    {
        int c0 = w * 16;
        #pragma unroll 1
        for (int ci = 0; ci < 16; ci++) {
            int c = c0 + ci;
            float cbv = sbias[c];
            #pragma unroll
            for (int g2 = 0; g2 < 4; g2++) {
                int n = g2 * 32 + lane;
                float val = Dsm[c * 129 + n] + cbv + g_bias2[c * NN + n0 + n];
                float r = fmaxf(val, 0.0f);
                float aw = affw[(size_t)c * NN + n0 + n];
                float ab = affb[(size_t)c * NN + n0 + n];
                out[((size_t)b * 128 + c) * NN + n0 + n] = r + r * aw + ab;
            }
        }
    }
}

extern "C" void kernel_launch(void* const* d_in, const int* in_sizes, int n_in,
                              void* d_out, int out_size) {
    const float* x     = (const float*)d_in[0];
    const float* qw    = (const float*)d_in[1];
    const float* qb    = (const float*)d_in[2];
    const float* vw    = (const float*)d_in[3];
    const float* vb    = (const float*)d_in[4];
    const float* cw    = (const float*)d_in[5];
    const float* cb    = (const float*)d_in[6];
    const float* mem   = (const float*)d_in[7];
    const float* nv1   = (const float*)d_in[8];
    const float* nv2   = (const float*)d_in[9];
    const float* wpool = (const float*)d_in[10];
    const float* bpool = (const float*)d_in[11];
    const float* affw  = (const float*)d_in[12];
    const float* affb  = (const float*)d_in[13];
    float* out = (float*)d_out;

    k_keysm<<<HEAD * NN / 8, 256>>>(mem);
    k_biasdyn<<<NN / 8, 256>>>(nv1, nv2, bpool);
    k_zero_kv<<<(BATCH * HEAD * DK * DK + 255) / 256, 256>>>();
    k_prepw<<<4, 128>>>(qw, vw, cw, wpool);
    k_bias2<<<NN, 128>>>();

    cudaFuncSetAttribute(k_prepx, cudaFuncAttributeMaxDynamicSharedMemorySize, 66048);
    k_prepx<<<dim3(NTILES, BATCH), 256, 66048>>>(x);

    cudaFuncSetAttribute(k_qv, cudaFuncAttributeMaxDynamicSharedMemorySize, SMEM_SZ);
    k_qv<<<dim3(NTILES, BATCH), 256, SMEM_SZ>>>(qb, vb);

    k_mb<<<BATCH, 512>>>(cw);

    cudaFuncSetAttribute(k_out, cudaFuncAttributeMaxDynamicSharedMemorySize, SMEM_SZ);
    k_out<<<dim3(NTILES, BATCH), 256, SMEM_SZ>>>(cb, affw, affb, out);
}

// round 8
// speedup vs baseline: 3.5659x; 1.1102x over previous
#include <cuda_runtime.h>
#include <cuda_bf16.h>
#include <math.h>
#include <stdint.h>

#define BATCH 64
#define DMODEL 128
#define NN 2048
#define HEAD 4
#define DK 32
#define NT 128
#define NTILES (NN/NT)  // 16

// smem byte offsets
#define OFF_A 0            // 69632 B : operand A hi+lo, stride 136 bf16
#define OFF_B 69632        // 69632 B : operand B hi+lo
#define OFF_D 139264       // 66048 B : fp32 D [128][129]  (k_qv only)
#define OFF_SB 205312      // 1024 B : biases
#define SMEM_QV 206336
#define OFF_C 139264       // k_out: third operand region
#define SMEM_OUT 208896
#define IMG_HALF 34816     // 128 rows * 272 B
#define ROWB 272           // 136 bf16 row stride

// ---------------- device globals ----------------
static __device__ float g_keysm[HEAD * NN * DK];
static __device__ float g_biasdyn[NN * DK];
static __device__ float g_kv[BATCH * HEAD * DK * DK];
static __device__ float g_bias2[DMODEL * NN];
static __device__ float g_Cp[DMODEL * DK];
// packed gmem images: hi [128][128] bf16 (32768B) then lo (32768B)
static __device__ __align__(16) unsigned char g_wimg[3 * 65536];                      // Wq, Wv, Cs
static __device__ __align__(16) unsigned char g_qimg[(size_t)BATCH * NTILES * 65536]; // q^T
static __device__ __align__(16) unsigned char g_vimg[(size_t)BATCH * NTILES * 65536]; // v^T
static __device__ __align__(16) unsigned char g_Mb[(size_t)BATCH * 65536];            // Mb

// ---------------- helpers ----------------
__device__ __forceinline__ uint32_t smem_u32(const void* p) {
    uint32_t a;
    asm("{ .reg .u64 t; cvta.to.shared.u64 t, %1; cvt.u32.u64 %0, t; }" : "=r"(a) : "l"(p));
    return a;
}
__device__ __forceinline__ void bf_split(float v, unsigned short& h, unsigned short& l) {
    __nv_bfloat16 bh = __float2bfloat16(v);
    h = __bfloat16_as_ushort(bh);
    l = __bfloat16_as_ushort(__float2bfloat16(v - __bfloat162float(bh)));
}
__device__ __forceinline__ uint4 pack8(const unsigned short* h) {
    uint4 u;
    u.x = (uint32_t)h[0] | ((uint32_t)h[1] << 16);
    u.y = (uint32_t)h[2] | ((uint32_t)h[3] << 16);
    u.z = (uint32_t)h[4] | ((uint32_t)h[5] << 16);
    u.w = (uint32_t)h[6] | ((uint32_t)h[7] << 16);
    return u;
}
__device__ __forceinline__ float warp_max(float v) {
    #pragma unroll
    for (int o = 16; o; o >>= 1) v = fmaxf(v, __shfl_xor_sync(0xffffffffu, v, o));
    return v;
}
__device__ __forceinline__ float warp_sum(float v) {
    #pragma unroll
    for (int o = 16; o; o >>= 1) v += __shfl_xor_sync(0xffffffffu, v, o);
    return v;
}
__device__ __forceinline__ void ldsm4(uint32_t addr, uint32_t& r0, uint32_t& r1,
                                      uint32_t& r2, uint32_t& r3) {
    asm volatile("ldmatrix.sync.aligned.m8n8.x4.shared.b16 {%0,%1,%2,%3}, [%4];"
                 : "=r"(r0), "=r"(r1), "=r"(r2), "=r"(r3) : "r"(addr));
}
__device__ __forceinline__ void mma16816(float d[4], const uint32_t a[4],
                                         uint32_t b0, uint32_t b1) {
    asm volatile("mma.sync.aligned.m16n8k16.row.col.f32.bf16.bf16.f32 "
                 "{%0,%1,%2,%3}, {%4,%5,%6,%7}, {%8,%9}, {%0,%1,%2,%3};"
                 : "+f"(d[0]), "+f"(d[1]), "+f"(d[2]), "+f"(d[3])
                 : "r"(a[0]), "r"(a[1]), "r"(a[2]), "r"(a[3]), "r"(b0), "r"(b1));
}

// gmem packed [128][128]x2 halves -> smem padded stride 136
__device__ __forceinline__ void load_img(const unsigned char* g, unsigned char* s, int t) {
    const uint4* src = (const uint4*)g;
    uint4* dst = (uint4*)s;
    #pragma unroll 1
    for (int half = 0; half < 2; half++)
        for (int i = t; i < 2048; i += 256) {
            int r = i >> 4, c = i & 15;
            dst[half * 2176 + r * 17 + c] = src[half * 2048 + i];
        }
}
__device__ __forceinline__ void store_img(unsigned char* g, const unsigned char* s, int t) {
    uint4* dst = (uint4*)g;
    const uint4* src = (const uint4*)s;
    #pragma unroll 1
    for (int half = 0; half < 2; half++)
        for (int i = t; i < 2048; i += 256) {
            int r = i >> 4, c = i & 15;
            dst[half * 2048 + i] = src[half * 2176 + r * 17 + c];
        }
}

// 3-term hi/lo warp GEMM, fragments loaded once per k-step.
// D(64x32) += A(64x128) * B^T(32rows x 128)
__device__ __forceinline__ void gemm3f(uint32_t Ahi, uint32_t Bhi, int wm, int wn,
                                       int lane, float D[4][4][4]) {
    int mat = lane >> 3, r8 = lane & 7;
    int arow = wm * 64 + ((mat & 1) << 3) + r8;
    int acol0 = (mat >> 1) << 3;
    int brow = wn * 32 + ((mat >> 1) << 3) + r8;
    int bcol0 = (mat & 1) << 3;
    #pragma unroll
    for (int ks = 0; ks < 8; ks++) {
        int k = ks * 16;
        uint32_t ah[4][4], al[4][4], bh[2][4], bl[2][4];
        #pragma unroll
        for (int mt = 0; mt < 4; mt++) {
            uint32_t addr = Ahi + (arow + mt * 16) * ROWB + (k + acol0) * 2;
            ldsm4(addr, ah[mt][0], ah[mt][1], ah[mt][2], ah[mt][3]);
            ldsm4(addr + IMG_HALF, al[mt][0], al[mt][1], al[mt][2], al[mt][3]);
        }
        #pragma unroll
        for (int bt = 0; bt < 2; bt++) {
            uint32_t addr = Bhi + (brow + bt * 16) * ROWB + (k + bcol0) * 2;
            ldsm4(addr, bh[bt][0], bh[bt][1], bh[bt][2], bh[bt][3]);
            ldsm4(addr + IMG_HALF, bl[bt][0], bl[bt][1], bl[bt][2], bl[bt][3]);
        }
        #pragma unroll
        for (int mt = 0; mt < 4; mt++)
            #pragma unroll
            for (int nt = 0; nt < 4; nt++)
                mma16816(D[mt][nt], ah[mt], bh[nt >> 1][(nt & 1) * 2],
                         bh[nt >> 1][(nt & 1) * 2 + 1]);
        #pragma unroll
        for (int mt = 0; mt < 4; mt++)
            #pragma unroll
            for (int nt = 0; nt < 4; nt++)
                mma16816(D[mt][nt], ah[mt], bl[nt >> 1][(nt & 1) * 2],
                         bl[nt >> 1][(nt & 1) * 2 + 1]);
        #pragma unroll
        for (int mt = 0; mt < 4; mt++)
            #pragma unroll
            for (int nt = 0; nt < 4; nt++)
                mma16816(D[mt][nt], al[mt], bh[nt >> 1][(nt & 1) * 2],
                         bh[nt >> 1][(nt & 1) * 2 + 1]);
    }
}
__device__ __forceinline__ void dzero(float D[4][4][4]) {
    #pragma unroll
    for (int mt = 0; mt < 4; mt++)
        #pragma unroll
        for (int nt = 0; nt < 4; nt++)
            #pragma unroll
            for (int i = 0; i < 4; i++) D[mt][nt][i] = 0.0f;
}
__device__ __forceinline__ void dwrite(float* Dsm, int wm, int wn, int lane, float D[4][4][4]) {
    int r = lane >> 2, cc = (lane & 3) * 2;
    #pragma unroll
    for (int mt = 0; mt < 4; mt++)
        #pragma unroll
        for (int nt = 0; nt < 4; nt++) {
            int row = wm * 64 + mt * 16 + r;
            int col = wn * 32 + nt * 8 + cc;
            Dsm[row * 129 + col] = D[mt][nt][0];
            Dsm[row * 129 + col + 1] = D[mt][nt][1];
            Dsm[(row + 8) * 129 + col] = D[mt][nt][2];
            Dsm[(row + 8) * 129 + col + 1] = D[mt][nt][3];
        }
}

// ---------------- P1: key softmax ----------------
__global__ void k_keysm(const float* __restrict__ mem) {
    const float inv_scale = 0.17677669529663687f;
    int row = blockIdx.x * 8 + (threadIdx.x >> 5);
    int lane = threadIdx.x & 31;
    float v = mem[row * 32 + lane] * inv_scale;
    float m = warp_max(v);
    float e = __expf(v - m);
    float s = warp_sum(e);
    g_keysm[row * 32 + lane] = e / s;
}

// ---------------- P2: bias_dyn ----------------
__global__ __launch_bounds__(256) void k_biasdyn(const float* __restrict__ nv1,
                                                 const float* __restrict__ nv2,
                                                 const float* __restrict__ bpool) {
    __shared__ float p[8][NN];
    __shared__ float red[256];
    __shared__ float a1[8][10];
    __shared__ float invs[8];
    int n0 = blockIdx.x * 8;
    int t = threadIdx.x;
    if (t < 80) a1[t / 10][t % 10] = nv1[(n0 + t / 10) * 10 + (t % 10)];
    __syncthreads();
    for (int r = 0; r < 8; r++) {
        float lv[8];
        float lmax = 0.0f;
        #pragma unroll
        for (int i = 0; i < 8; i++) {
            int m = t + i * 256;
            float acc = 0.0f;
            #pragma unroll
            for (int k = 0; k < 10; k++) acc += a1[r][k] * nv2[k * NN + m];
            acc = fmaxf(acc, 0.0f);
            lv[i] = acc;
            lmax = fmaxf(lmax, acc);
        }
        red[t] = lmax; __syncthreads();
        for (int s = 128; s; s >>= 1) { if (t < s) red[t] = fmaxf(red[t], red[t + s]); __syncthreads(); }
        float bmax = red[0];
        __syncthreads();
        float lsum = 0.0f;
        #pragma unroll
        for (int i = 0; i < 8; i++) {
            float e = __expf(lv[i] - bmax);
            p[r][t + i * 256] = e;
            lsum += e;
        }
        red[t] = lsum; __syncthreads();
        for (int s = 128; s; s >>= 1) { if (t < s) red[t] += red[t + s]; __syncthreads(); }
        if (t == 0) invs[r] = 1.0f / red[0];
        __syncthreads();
    }
    int c = t & 31, g = t >> 5;
    float acc[8];
    #pragma unroll
    for (int r = 0; r < 8; r++) acc[r] = 0.0f;
    for (int m = g; m < NN; m += 8) {
        float bp = bpool[m * 32 + c];
        #pragma unroll
        for (int r = 0; r < 8; r++) acc[r] += p[r][m] * bp;
    }
    for (int r = 0; r < 8; r++) {
        red[t] = acc[r]; __syncthreads();
        if (t < 32) {
            float s2 = 0.0f;
            #pragma unroll
            for (int g2 = 0; g2 < 8; g2++) s2 += red[g2 * 32 + t];
            g_biasdyn[(n0 + r) * 32 + t] = s2 * invs[r];
        }
        __syncthreads();
    }
}

// ---------------- P3: zero kv ----------------
__global__ void k_zero_kv() {
    int i = blockIdx.x * 256 + threadIdx.x;
    if (i < BATCH * HEAD * DK * DK) g_kv[i] = 0.0f;
}

// ---------------- P4: weight images + Cp (grid 4 x 8) ----------------
__global__ __launch_bounds__(128) void k_prepw(const float* __restrict__ qw,
                                               const float* __restrict__ vw,
                                               const float* __restrict__ cw,
                                               const float* __restrict__ wpool) {
    int m = blockIdx.x, part = blockIdx.y;
    int o = threadIdx.x;
    if (m == 3) {
        if (part == 0) {
            for (int y = 0; y < 32; y++) {
                float s = 0.0f;
                #pragma unroll
                for (int h = 0; h < 4; h++) s += cw[o * 128 + h * 32 + y];
                g_Cp[o * 32 + y] = s;
            }
        }
        return;
    }
    const float* w = (m == 0) ? qw : (m == 1) ? vw : cw;
    float scale = 1.0f;
    if (m == 2) {
        float S = 0.0f;
        #pragma unroll
        for (int i = 0; i < 9; i++) S += wpool[i];
        scale = S;
    }
    unsigned char* img = g_wimg + m * 65536;
    for (int cc = part * 2; cc < part * 2 + 2; cc++) {
        unsigned short hs[8], ls[8];
        #pragma unroll
        for (int k = 0; k < 8; k++) bf_split(w[o * 128 + cc * 8 + k] * scale, hs[k], ls[k]);
        int byte = (o * 128 + cc * 8) * 2;
        *(uint4*)(img + byte) = pack8(hs);
        *(uint4*)(img + 32768 + byte) = pack8(ls);
    }
}

// ---------------- P4b: bias2 = Cp @ bias_dyn^T ----------------
__global__ __launch_bounds__(128) void k_bias2() {
    __shared__ float bd[32];
    int n = blockIdx.x, t = threadIdx.x;
    if (t < 32) bd[t] = g_biasdyn[n * 32 + t];
    __syncthreads();
    float s = 0.0f;
    #pragma unroll
    for (int y = 0; y < 32; y++) s += g_Cp[t * 32 + y] * bd[y];
    g_bias2[t * NN + n] = s;
}

// ---------------- K1: x convert + Q/V convs + softmax + kv partial --------
__global__ __launch_bounds__(256, 1) void k_qv(const float* __restrict__ x,
                                               const float* __restrict__ qb,
                                               const float* __restrict__ vb) {
    extern __shared__ __align__(16) unsigned char sm[];
    int b = blockIdx.y, tile = blockIdx.x, n0 = tile * NT, t = threadIdx.x;
    uint32_t sb = smem_u32(sm);
    float* Dsm = (float*)(sm + OFF_D);
    float* sbias = (float*)(sm + OFF_SB);
    int w = t >> 5, lane = t & 31;
    int wm = w & 1, wn = w >> 1;

    load_img(g_wimg, sm + OFF_A, t);                 // Wq
    // stage fp32 x into Dsm
    for (int i = t; i < 16384; i += 256) {
        int c = i >> 7, n = i & 127;
        Dsm[c * 129 + n] = x[((size_t)b * 128 + c) * NN + n0 + n];
    }
    if (t < 128) sbias[t] = qb[t]; else sbias[t] = vb[t - 128];
    __syncthreads();

    // convert x -> B image (hi/lo) in smem
    {
        int node = t >> 1, half = t & 1;
        for (int cc = 0; cc < 8; cc++) {
            int c0 = half * 64 + cc * 8;
            unsigned short hs[8], ls[8];
            #pragma unroll
            for (int k = 0; k < 8; k++) bf_split(Dsm[(c0 + k) * 129 + node], hs[k], ls[k]);
            int byte = node * ROWB + c0 * 2;
            *(uint4*)(sm + OFF_B + byte) = pack8(hs);
            *(uint4*)(sm + OFF_B + IMG_HALF + byte) = pack8(ls);
        }
    }
    __syncthreads();

    float D[4][4][4];
    dzero(D);
    gemm3f(sb + OFF_A, sb + OFF_B, wm, wn, lane, D); // Q = Wq @ x
    dwrite(Dsm, wm, wn, lane, D);
    __syncthreads();

    // ---- Q epilogue: per-node softmax per head; q image into A region ----
    const float inv_scale = 0.17677669529663687f;
    {
        int node = t & 127, hb = t >> 7;
        #pragma unroll
        for (int hh = 0; hh < 2; hh++) {
            int h = hb + hh * 2;
            float q[32];
            float mx = 0.0f;
            #pragma unroll
            for (int i = 0; i < 32; i++) {
                q[i] = fmaxf(Dsm[(h * 32 + i) * 129 + node] + sbias[h * 32 + i], 0.0f);
                mx = fmaxf(mx, q[i]);
            }
            float s = 0.0f;
            #pragma unroll
            for (int i = 0; i < 32; i++) { q[i] = __expf((q[i] - mx) * inv_scale); s += q[i]; }
            float is = 1.0f / s;
            #pragma unroll
            for (int cc = 0; cc < 4; cc++) {
                unsigned short hs[8], ls[8];
                #pragma unroll
                for (int k = 0; k < 8; k++) bf_split(q[cc * 8 + k] * is, hs[k], ls[k]);
                int byte = node * ROWB + (h * 32 + cc * 8) * 2;
                *(uint4*)(sm + OFF_A + byte) = pack8(hs);
                *(uint4*)(sm + OFF_A + IMG_HALF + byte) = pack8(ls);
            }
        }
    }
    __syncthreads();
    store_img(g_qimg + ((size_t)(b * NTILES + tile)) * 65536, sm + OFF_A, t);
    __syncthreads();

    load_img(g_wimg + 65536, sm + OFF_A, t);         // Wv (B keeps x image)
    __syncthreads();
    dzero(D);
    gemm3f(sb + OFF_A, sb + OFF_B, wm, wn, lane, D); // V = Wv @ x
    dwrite(Dsm, wm, wn, lane, D);
    __syncthreads();

    // ---- V epilogue: relu writeback + v image into A; ks tile into B ----
    {
        int node = t & 127, hb = t >> 7;
        #pragma unroll
        for (int hh = 0; hh < 2; hh++) {
            int h = hb + hh * 2;
            float v[32];
            #pragma unroll
            for (int i = 0; i < 32; i++) {
                v[i] = fmaxf(Dsm[(h * 32 + i) * 129 + node] + sbias[128 + h * 32 + i], 0.0f);
                Dsm[(h * 32 + i) * 129 + node] = v[i];
            }
            #pragma unroll
            for (int cc = 0; cc < 4; cc++) {
                unsigned short hs[8], ls[8];
                #pragma unroll
                for (int k = 0; k < 8; k++) bf_split(v[cc * 8 + k], hs[k], ls[k]);
                int byte = node * ROWB + (h * 32 + cc * 8) * 2;
                *(uint4*)(sm + OFF_A + byte) = pack8(hs);
                *(uint4*)(sm + OFF_A + IMG_HALF + byte) = pack8(ls);
            }
        }
    }
    float* ks = (float*)(sm + OFF_B);   // 64 KB, overwrites x image
    for (int i = t; i < 16384; i += 256) {
        int h2 = i >> 12, r = i & 4095;
        int j2 = r >> 5, xk = r & 31;
        ks[i] = g_keysm[(h2 * NN + n0 + j2) * 32 + xk];
    }
    __syncthreads();
    store_img(g_vimg + ((size_t)(b * NTILES + tile)) * 65536, sm + OFF_A, t);
    {
        int idx = t & 63, h2 = t >> 6;
        int x0 = (idx >> 3) * 4, y0 = (idx & 7) * 4;
        float acc[4][4];
        #pragma unroll
        for (int a = 0; a < 4; a++)
            #pragma unroll
            for (int c = 0; c < 4; c++) acc[a][c] = 0.0f;
        #pragma unroll 4
        for (int jj = 0; jj < NT; jj++) {
            float4 kx = *(const float4*)(ks + (h2 * NT + jj) * 32 + x0);
            float vy[4];
            #pragma unroll
            for (int yi = 0; yi < 4; yi++) vy[yi] = Dsm[(h2 * 32 + y0 + yi) * 129 + jj];
            #pragma unroll
            for (int yi = 0; yi < 4; yi++) {
                acc[0][yi] += kx.x * vy[yi];
                acc[1][yi] += kx.y * vy[yi];
                acc[2][yi] += kx.z * vy[yi];
                acc[3][yi] += kx.w * vy[yi];
            }
        }
        #pragma unroll
        for (int xi = 0; xi < 4; xi++)
            #pragma unroll
            for (int yi = 0; yi < 4; yi++)
                atomicAdd(&g_kv[(((size_t)b * HEAD + h2) * DK + x0 + xi) * DK + y0 + yi],
                          acc[xi][yi]);
    }
}

// ---------------- P6: Mb[o][h*32+x] = sum_y cw[o][h*32+y]*kv[b,h,x,y] -----
__global__ __launch_bounds__(512) void k_mb(const float* __restrict__ cw) {
    __shared__ float kvT[32 * 128];
    int b = blockIdx.x, t = threadIdx.x;
    for (int i = t; i < 4096; i += 512) {
        int row = i >> 5, y = i & 31;
        kvT[y * 128 + row] = g_kv[(size_t)b * 4096 + i];
    }
    __syncthreads();
    int o = t & 127, h = t >> 7;
    float acc[32];
    #pragma unroll
    for (int x = 0; x < 32; x++) acc[x] = 0.0f;
    for (int y = 0; y < 32; y++) {
        float cv = cw[o * 128 + h * 32 + y];
        const float* kr = kvT + y * 128 + h * 32;
        #pragma unroll
        for (int x = 0; x < 32; x++) acc[x] += cv * kr[x];
    }
    unsigned char* img = g_Mb + (size_t)b * 65536;
    for (int cc = 0; cc < 4; cc++) {
        unsigned short hs[8], ls[8];
        #pragma unroll
        for (int k = 0; k < 8; k++) bf_split(acc[cc * 8 + k], hs[k], ls[k]);
        int byte = (o * 128 + h * 32 + cc * 8) * 2;
        *(uint4*)(img + byte) = pack8(hs);
        *(uint4*)(img + 32768 + byte) = pack8(ls);
    }
}

// ---------------- K2: out = relu(Mb@q + Cs@v + bias2 + cb) -> affine -----
__global__ __launch_bounds__(256, 1) void k_out(const float* __restrict__ cb,
                                                const float* __restrict__ affw,
                                                const float* __restrict__ affb,
                                                float* __restrict__ out) {
    extern __shared__ __align__(16) unsigned char sm[];
    int b = blockIdx.y, tile = blockIdx.x, n0 = tile * NT, t = threadIdx.x;
    uint32_t sb = smem_u32(sm);
    int w = t >> 5, lane = t & 31;
    int wm = w & 1, wn = w >> 1;

    load_img(g_Mb + (size_t)b * 65536, sm + OFF_A, t);
    load_img(g_qimg + ((size_t)(b * NTILES + tile)) * 65536, sm + OFF_B, t);
    load_img(g_wimg + 2 * 65536, sm + OFF_C, t);     // Cs preloaded
    __syncthreads();

    float D[4][4][4];
    dzero(D);
    gemm3f(sb + OFF_A, sb + OFF_B, wm, wn, lane, D); // Mb @ q
    __syncthreads();
    load_img(g_vimg + ((size_t)(b * NTILES + tile)) * 65536, sm + OFF_A, t);  // v over Mb
    __syncthreads();
    gemm3f(sb + OFF_C, sb + OFF_A, wm, wn, lane, D); // += Cs @ v

    // ---- direct register epilogue ----
    int r0 = lane >> 2, cp = (lane & 3) * 2;
    #pragma unroll
    for (int mt = 0; mt < 4; mt++)
        #pragma unroll
        for (int nt = 0; nt < 4; nt++) {
            int col = wn * 32 + nt * 8 + cp;
            #pragma unroll
            for (int half = 0; half < 2; half++) {
                int c = wm * 64 + mt * 16 + r0 + half * 8;
                size_t base = (size_t)c * NN + n0 + col;
                float cbv = __ldg(cb + c);
                float2 b2 = *(const float2*)(g_bias2 + base);
                float2 aw = *(const float2*)(affw + base);
                float2 ab = *(const float2*)(affb + base);
                float v0 = D[mt][nt][half * 2 + 0] + cbv + b2.x;
                float v1 = D[mt][nt][half * 2 + 1] + cbv + b2.y;
                float rr0 = fmaxf(v0, 0.0f), rr1 = fmaxf(v1, 0.0f);
                float2 o2;
                o2.x = rr0 + rr0 * aw.x + ab.x;
                o2.y = rr1 + rr1 * aw.y + ab.y;
                *(float2*)(out + ((size_t)b * 128) * NN + base) = o2;
            }
        }
}

extern "C" void kernel_launch(void* const* d_in, const int* in_sizes, int n_in,
                              void* d_out, int out_size) {
    const float* x     = (const float*)d_in[0];
    const float* qw    = (const float*)d_in[1];
    const float* qb    = (const float*)d_in[2];
    const float* vw    = (const float*)d_in[3];
    const float* vb    = (const float*)d_in[4];
    const float* cw    = (const float*)d_in[5];
    const float* cb    = (const float*)d_in[6];
    const float* mem   = (const float*)d_in[7];
    const float* nv1   = (const float*)d_in[8];
    const float* nv2   = (const float*)d_in[9];
    const float* wpool = (const float*)d_in[10];
    const float* bpool = (const float*)d_in[11];
    const float* affw  = (const float*)d_in[12];
    const float* affb  = (const float*)d_in[13];
    float* out = (float*)d_out;

    k_keysm<<<HEAD * NN / 8, 256>>>(mem);
    k_biasdyn<<<NN / 8, 256>>>(nv1, nv2, bpool);
    k_zero_kv<<<(BATCH * HEAD * DK * DK + 255) / 256, 256>>>();
    k_prepw<<<dim3(4, 8), 128>>>(qw, vw, cw, wpool);
    k_bias2<<<NN, 128>>>();

    cudaFuncSetAttribute(k_qv, cudaFuncAttributeMaxDynamicSharedMemorySize, SMEM_QV);
    k_qv<<<dim3(NTILES, BATCH), 256, SMEM_QV>>>(x, qb, vb);

    k_mb<<<BATCH, 512>>>(cw);

    cudaFuncSetAttribute(k_out, cudaFuncAttributeMaxDynamicSharedMemorySize, SMEM_OUT);
    k_out<<<dim3(NTILES, BATCH), 256, SMEM_OUT>>>(cb, affw, affb, out);
}

// round 9
// speedup vs baseline: 3.6938x; 1.0359x over previous
#include <cuda_runtime.h>
#include <cuda_bf16.h>
#include <math.h>
#include <stdint.h>

#define BATCH 64
#define DMODEL 128
#define NN 2048
#define HEAD 4
#define DK 32
#define NT 128
#define NTILES (NN/NT)  // 16

// smem byte offsets
#define OFF_A 0            // 69632 B : operand A hi+lo, stride 136 bf16
#define OFF_B 69632        // 69632 B : operand B hi+lo
#define OFF_D 139264       // 66048 B : fp32 D [128][129]  (k_qv only)
#define OFF_SB 205312      // 1024 B : biases
#define SMEM_QV 206336
#define OFF_C 139264       // k_out: third operand region
#define SMEM_OUT 208896
#define IMG_HALF 34816     // 128 rows * 272 B
#define ROWB 272           // 136 bf16 row stride

// ---------------- device globals ----------------
static __device__ float g_keysm[HEAD * NN * DK];
static __device__ float g_biasdyn[NN * DK];
static __device__ float g_kv[BATCH * HEAD * DK * DK];
static __device__ float g_bias2[DMODEL * NN];
static __device__ float g_Cp[DMODEL * DK];
// packed gmem images: hi [128][128] bf16 (32768B) then lo (32768B)
static __device__ __align__(16) unsigned char g_wimg[3 * 65536];                      // Wq, Wv, Cs
static __device__ __align__(16) unsigned char g_qimg[(size_t)BATCH * NTILES * 65536]; // q^T
static __device__ __align__(16) unsigned char g_vimg[(size_t)BATCH * NTILES * 65536]; // v^T
static __device__ __align__(16) unsigned char g_Mb[(size_t)BATCH * 65536];            // Mb

// ---------------- helpers ----------------
__device__ __forceinline__ uint32_t smem_u32(const void* p) {
    uint32_t a;
    asm("{ .reg .u64 t; cvta.to.shared.u64 t, %1; cvt.u32.u64 %0, t; }" : "=r"(a) : "l"(p));
    return a;
}
__device__ __forceinline__ void bf_split(float v, unsigned short& h, unsigned short& l) {
    __nv_bfloat16 bh = __float2bfloat16(v);
    h = __bfloat16_as_ushort(bh);
    l = __bfloat16_as_ushort(__float2bfloat16(v - __bfloat162float(bh)));
}
__device__ __forceinline__ uint4 pack8(const unsigned short* h) {
    uint4 u;
    u.x = (uint32_t)h[0] | ((uint32_t)h[1] << 16);
    u.y = (uint32_t)h[2] | ((uint32_t)h[3] << 16);
    u.z = (uint32_t)h[4] | ((uint32_t)h[5] << 16);
    u.w = (uint32_t)h[6] | ((uint32_t)h[7] << 16);
    return u;
}
__device__ __forceinline__ float warp_max(float v) {
    #pragma unroll
    for (int o = 16; o; o >>= 1) v = fmaxf(v, __shfl_xor_sync(0xffffffffu, v, o));
    return v;
}
__device__ __forceinline__ float warp_sum(float v) {
    #pragma unroll
    for (int o = 16; o; o >>= 1) v += __shfl_xor_sync(0xffffffffu, v, o);
    return v;
}
__device__ __forceinline__ void ldsm4(uint32_t addr, uint32_t& r0, uint32_t& r1,
                                      uint32_t& r2, uint32_t& r3) {
    asm volatile("ldmatrix.sync.aligned.m8n8.x4.shared.b16 {%0,%1,%2,%3}, [%4];"
                 : "=r"(r0), "=r"(r1), "=r"(r2), "=r"(r3) : "r"(addr));
}
__device__ __forceinline__ void mma16816(float d[4], const uint32_t a[4],
                                         uint32_t b0, uint32_t b1) {
    asm volatile("mma.sync.aligned.m16n8k16.row.col.f32.bf16.bf16.f32 "
                 "{%0,%1,%2,%3}, {%4,%5,%6,%7}, {%8,%9}, {%0,%1,%2,%3};"
                 : "+f"(d[0]), "+f"(d[1]), "+f"(d[2]), "+f"(d[3])
                 : "r"(a[0]), "r"(a[1]), "r"(a[2]), "r"(a[3]), "r"(b0), "r"(b1));
}

// gmem packed [128][128]x2 halves -> smem padded stride 136 (512 threads)
__device__ __forceinline__ void load_img(const unsigned char* g, unsigned char* s, int t) {
    const uint4* src = (const uint4*)g;
    uint4* dst = (uint4*)s;
    #pragma unroll 1
    for (int half = 0; half < 2; half++)
        for (int i = t; i < 2048; i += 512) {
            int r = i >> 4, c = i & 15;
            dst[half * 2176 + r * 17 + c] = src[half * 2048 + i];
        }
}
__device__ __forceinline__ void store_img(unsigned char* g, const unsigned char* s, int t) {
    uint4* dst = (uint4*)g;
    const uint4* src = (const uint4*)s;
    #pragma unroll 1
    for (int half = 0; half < 2; half++)
        for (int i = t; i < 2048; i += 512) {
            int r = i >> 4, c = i & 15;
            dst[half * 2048 + i] = src[half * 2176 + r * 17 + c];
        }
}

// 3-term hi/lo warp GEMM, 16 warps (4x4 grid), warp tile 32x32.
// D(32x32) += A(32rows x128) * B^T(32rows x 128)
__device__ __forceinline__ void gemm3f(uint32_t Ahi, uint32_t Bhi, int wm, int wn,
                                       int lane, float D[2][4][4]) {
    int mat = lane >> 3, r8 = lane & 7;
    int arow = wm * 32 + ((mat & 1) << 3) + r8;
    int acol0 = (mat >> 1) << 3;
    int brow = wn * 32 + ((mat >> 1) << 3) + r8;
    int bcol0 = (mat & 1) << 3;
    #pragma unroll
    for (int ks = 0; ks < 8; ks++) {
        int k = ks * 16;
        uint32_t ah[2][4], al[2][4], bh[2][4], bl[2][4];
        #pragma unroll
        for (int mt = 0; mt < 2; mt++) {
            uint32_t addr = Ahi + (arow + mt * 16) * ROWB + (k + acol0) * 2;
            ldsm4(addr, ah[mt][0], ah[mt][1], ah[mt][2], ah[mt][3]);
            ldsm4(addr + IMG_HALF, al[mt][0], al[mt][1], al[mt][2], al[mt][3]);
        }
        #pragma unroll
        for (int bt = 0; bt < 2; bt++) {
            uint32_t addr = Bhi + (brow + bt * 16) * ROWB + (k + bcol0) * 2;
            ldsm4(addr, bh[bt][0], bh[bt][1], bh[bt][2], bh[bt][3]);
            ldsm4(addr + IMG_HALF, bl[bt][0], bl[bt][1], bl[bt][2], bl[bt][3]);
        }
        #pragma unroll
        for (int mt = 0; mt < 2; mt++)
            #pragma unroll
            for (int nt = 0; nt < 4; nt++)
                mma16816(D[mt][nt], ah[mt], bh[nt >> 1][(nt & 1) * 2],
                         bh[nt >> 1][(nt & 1) * 2 + 1]);
        #pragma unroll
        for (int mt = 0; mt < 2; mt++)
            #pragma unroll
            for (int nt = 0; nt < 4; nt++)
                mma16816(D[mt][nt], ah[mt], bl[nt >> 1][(nt & 1) * 2],
                         bl[nt >> 1][(nt & 1) * 2 + 1]);
        #pragma unroll
        for (int mt = 0; mt < 2; mt++)
            #pragma unroll
            for (int nt = 0; nt < 4; nt++)
                mma16816(D[mt][nt], al[mt], bh[nt >> 1][(nt & 1) * 2],
                         bh[nt >> 1][(nt & 1) * 2 + 1]);
    }
}
__device__ __forceinline__ void dzero(float D[2][4][4]) {
    #pragma unroll
    for (int mt = 0; mt < 2; mt++)
        #pragma unroll
        for (int nt = 0; nt < 4; nt++)
            #pragma unroll
            for (int i = 0; i < 4; i++) D[mt][nt][i] = 0.0f;
}
__device__ __forceinline__ void dwrite(float* Dsm, int wm, int wn, int lane, float D[2][4][4]) {
    int r = lane >> 2, cc = (lane & 3) * 2;
    #pragma unroll
    for (int mt = 0; mt < 2; mt++)
        #pragma unroll
        for (int nt = 0; nt < 4; nt++) {
            int row = wm * 32 + mt * 16 + r;
            int col = wn * 32 + nt * 8 + cc;
            Dsm[row * 129 + col] = D[mt][nt][0];
            Dsm[row * 129 + col + 1] = D[mt][nt][1];
            Dsm[(row + 8) * 129 + col] = D[mt][nt][2];
            Dsm[(row + 8) * 129 + col + 1] = D[mt][nt][3];
        }
}

// ---------------- P1: key softmax ----------------
__global__ void k_keysm(const float* __restrict__ mem) {
    const float inv_scale = 0.17677669529663687f;
    int row = blockIdx.x * 8 + (threadIdx.x >> 5);
    int lane = threadIdx.x & 31;
    float v = mem[row * 32 + lane] * inv_scale;
    float m = warp_max(v);
    float e = __expf(v - m);
    float s = warp_sum(e);
    g_keysm[row * 32 + lane] = e / s;
}

// ---------------- P2: bias_dyn ----------------
__global__ __launch_bounds__(256) void k_biasdyn(const float* __restrict__ nv1,
                                                 const float* __restrict__ nv2,
                                                 const float* __restrict__ bpool) {
    __shared__ float p[8][NN];
    __shared__ float red[256];
    __shared__ float a1[8][10];
    __shared__ float invs[8];
    int n0 = blockIdx.x * 8;
    int t = threadIdx.x;
    if (t < 80) a1[t / 10][t % 10] = nv1[(n0 + t / 10) * 10 + (t % 10)];
    __syncthreads();
    for (int r = 0; r < 8; r++) {
        float lv[8];
        float lmax = 0.0f;
        #pragma unroll
        for (int i = 0; i < 8; i++) {
            int m = t + i * 256;
            float acc = 0.0f;
            #pragma unroll
            for (int k = 0; k < 10; k++) acc += a1[r][k] * nv2[k * NN + m];
            acc = fmaxf(acc, 0.0f);
            lv[i] = acc;
            lmax = fmaxf(lmax, acc);
        }
        red[t] = lmax; __syncthreads();
        for (int s = 128; s; s >>= 1) { if (t < s) red[t] = fmaxf(red[t], red[t + s]); __syncthreads(); }
        float bmax = red[0];
        __syncthreads();
        float lsum = 0.0f;
        #pragma unroll
        for (int i = 0; i < 8; i++) {
            float e = __expf(lv[i] - bmax);
            p[r][t + i * 256] = e;
            lsum += e;
        }
        red[t] = lsum; __syncthreads();
        for (int s = 128; s; s >>= 1) { if (t < s) red[t] += red[t + s]; __syncthreads(); }
        if (t == 0) invs[r] = 1.0f / red[0];
        __syncthreads();
    }
    int c = t & 31, g = t >> 5;
    float acc[8];
    #pragma unroll
    for (int r = 0; r < 8; r++) acc[r] = 0.0f;
    for (int m = g; m < NN; m += 8) {
        float bp = bpool[m * 32 + c];
        #pragma unroll
        for (int r = 0; r < 8; r++) acc[r] += p[r][m] * bp;
    }
    for (int r = 0; r < 8; r++) {
        red[t] = acc[r]; __syncthreads();
        if (t < 32) {
            float s2 = 0.0f;
            #pragma unroll
            for (int g2 = 0; g2 < 8; g2++) s2 += red[g2 * 32 + t];
            g_biasdyn[(n0 + r) * 32 + t] = s2 * invs[r];
        }
        __syncthreads();
    }
}

// ---------------- P3: zero kv ----------------
__global__ void k_zero_kv() {
    int i = blockIdx.x * 256 + threadIdx.x;
    if (i < BATCH * HEAD * DK * DK) g_kv[i] = 0.0f;
}

// ---------------- P4: weight images + Cp (grid 4 x 8) ----------------
__global__ __launch_bounds__(128) void k_prepw(const float* __restrict__ qw,
                                               const float* __restrict__ vw,
                                               const float* __restrict__ cw,
                                               const float* __restrict__ wpool) {
    int m = blockIdx.x, part = blockIdx.y;
    int o = threadIdx.x;
    if (m == 3) {
        if (part == 0) {
            for (int y = 0; y < 32; y++) {
                float s = 0.0f;
                #pragma unroll
                for (int h = 0; h < 4; h++) s += cw[o * 128 + h * 32 + y];
                g_Cp[o * 32 + y] = s;
            }
        }
        return;
    }
    const float* w = (m == 0) ? qw : (m == 1) ? vw : cw;
    float scale = 1.0f;
    if (m == 2) {
        float S = 0.0f;
        #pragma unroll
        for (int i = 0; i < 9; i++) S += wpool[i];
        scale = S;
    }
    unsigned char* img = g_wimg + m * 65536;
    for (int cc = part * 2; cc < part * 2 + 2; cc++) {
        unsigned short hs[8], ls[8];
        #pragma unroll
        for (int k = 0; k < 8; k++) bf_split(w[o * 128 + cc * 8 + k] * scale, hs[k], ls[k]);
        int byte = (o * 128 + cc * 8) * 2;
        *(uint4*)(img + byte) = pack8(hs);
        *(uint4*)(img + 32768 + byte) = pack8(ls);
    }
}

// ---------------- P4b: bias2 = Cp @ bias_dyn^T ----------------
__global__ __launch_bounds__(128) void k_bias2() {
    __shared__ float bd[32];
    int n = blockIdx.x, t = threadIdx.x;
    if (t < 32) bd[t] = g_biasdyn[n * 32 + t];
    __syncthreads();
    float s = 0.0f;
    #pragma unroll
    for (int y = 0; y < 32; y++) s += g_Cp[t * 32 + y] * bd[y];
    g_bias2[t * NN + n] = s;
}

// ---------------- K1: x convert + Q/V convs + softmax + kv partial --------
__global__ __launch_bounds__(512, 1) void k_qv(const float* __restrict__ x,
                                               const float* __restrict__ qb,
                                               const float* __restrict__ vb) {
    extern __shared__ __align__(16) unsigned char sm[];
    int b = blockIdx.y, tile = blockIdx.x, n0 = tile * NT, t = threadIdx.x;
    uint32_t sb = smem_u32(sm);
    float* Dsm = (float*)(sm + OFF_D);
    float* sbias = (float*)(sm + OFF_SB);
    int w = t >> 5, lane = t & 31;
    int wm = w >> 2, wn = w & 3;

    load_img(g_wimg, sm + OFF_A, t);                 // Wq
    // stage fp32 x into Dsm
    for (int i = t; i < 16384; i += 512) {
        int c = i >> 7, n = i & 127;
        Dsm[c * 129 + n] = x[((size_t)b * 128 + c) * NN + n0 + n];
    }
    if (t < 128) sbias[t] = qb[t];
    else if (t < 256) sbias[t] = vb[t - 128];
    __syncthreads();

    // convert x -> B image (hi/lo) in smem: thread = (node, 32-channel quarter)
    {
        int node = t >> 2, q4 = t & 3;
        for (int cc = 0; cc < 4; cc++) {
            int c0 = q4 * 32 + cc * 8;
            unsigned short hs[8], ls[8];
            #pragma unroll
            for (int k = 0; k < 8; k++) bf_split(Dsm[(c0 + k) * 129 + node], hs[k], ls[k]);
            int byte = node * ROWB + c0 * 2;
            *(uint4*)(sm + OFF_B + byte) = pack8(hs);
            *(uint4*)(sm + OFF_B + IMG_HALF + byte) = pack8(ls);
        }
    }
    __syncthreads();

    float D[2][4][4];
    dzero(D);
    gemm3f(sb + OFF_A, sb + OFF_B, wm, wn, lane, D); // Q = Wq @ x
    dwrite(Dsm, wm, wn, lane, D);
    __syncthreads();

    // ---- Q epilogue: per-node softmax per head; q image into A region ----
    const float inv_scale = 0.17677669529663687f;
    {
        int node = t & 127, h = t >> 7;
        float q[32];
        float mx = 0.0f;
        #pragma unroll
        for (int i = 0; i < 32; i++) {
            q[i] = fmaxf(Dsm[(h * 32 + i) * 129 + node] + sbias[h * 32 + i], 0.0f);
            mx = fmaxf(mx, q[i]);
        }
        float s = 0.0f;
        #pragma unroll
        for (int i = 0; i < 32; i++) { q[i] = __expf((q[i] - mx) * inv_scale); s += q[i]; }
        float is = 1.0f / s;
        #pragma unroll
        for (int cc = 0; cc < 4; cc++) {
            unsigned short hs[8], ls[8];
            #pragma unroll
            for (int k = 0; k < 8; k++) bf_split(q[cc * 8 + k] * is, hs[k], ls[k]);
            int byte = node * ROWB + (h * 32 + cc * 8) * 2;
            *(uint4*)(sm + OFF_A + byte) = pack8(hs);
            *(uint4*)(sm + OFF_A + IMG_HALF + byte) = pack8(ls);
        }
    }
    __syncthreads();
    store_img(g_qimg + ((size_t)(b * NTILES + tile)) * 65536, sm + OFF_A, t);
    __syncthreads();

    load_img(g_wimg + 65536, sm + OFF_A, t);         // Wv (B keeps x image)
    __syncthreads();
    dzero(D);
    gemm3f(sb + OFF_A, sb + OFF_B, wm, wn, lane, D); // V = Wv @ x
    dwrite(Dsm, wm, wn, lane, D);
    __syncthreads();

    // ---- V epilogue: relu writeback + v image into A; ks tile into B ----
    {
        int node = t & 127, h = t >> 7;
        float v[32];
        #pragma unroll
        for (int i = 0; i < 32; i++) {
            v[i] = fmaxf(Dsm[(h * 32 + i) * 129 + node] + sbias[128 + h * 32 + i], 0.0f);
            Dsm[(h * 32 + i) * 129 + node] = v[i];
        }
        #pragma unroll
        for (int cc = 0; cc < 4; cc++) {
            unsigned short hs[8], ls[8];
            #pragma unroll
            for (int k = 0; k < 8; k++) bf_split(v[cc * 8 + k], hs[k], ls[k]);
            int byte = node * ROWB + (h * 32 + cc * 8) * 2;
            *(uint4*)(sm + OFF_A + byte) = pack8(hs);
            *(uint4*)(sm + OFF_A + IMG_HALF + byte) = pack8(ls);
        }
    }
    float* ks = (float*)(sm + OFF_B);   // 64 KB, overwrites x image
    for (int i = t; i < 16384; i += 512) {
        int h2 = i >> 12, r = i & 4095;
        int j2 = r >> 5, xk = r & 31;
        ks[i] = g_keysm[(h2 * NN + n0 + j2) * 32 + xk];
    }
    __syncthreads();
    store_img(g_vimg + ((size_t)(b * NTILES + tile)) * 65536, sm + OFF_A, t);
    {
        int idx = t & 127, h2 = t >> 7;
        int x0 = (idx >> 4) * 4, y0 = (idx & 15) * 2;
        float acc[4][2];
        #pragma unroll
        for (int a = 0; a < 4; a++) { acc[a][0] = 0.0f; acc[a][1] = 0.0f; }
        #pragma unroll 4
        for (int jj = 0; jj < NT; jj++) {
            float4 kx = *(const float4*)(ks + (h2 * NT + jj) * 32 + x0);
            float v0 = Dsm[(h2 * 32 + y0 + 0) * 129 + jj];
            float v1 = Dsm[(h2 * 32 + y0 + 1) * 129 + jj];
            acc[0][0] += kx.x * v0; acc[0][1] += kx.x * v1;
            acc[1][0] += kx.y * v0; acc[1][1] += kx.y * v1;
            acc[2][0] += kx.z * v0; acc[2][1] += kx.z * v1;
            acc[3][0] += kx.w * v0; acc[3][1] += kx.w * v1;
        }
        #pragma unroll
        for (int xi = 0; xi < 4; xi++)
            #pragma unroll
            for (int yi = 0; yi < 2; yi++)
                atomicAdd(&g_kv[(((size_t)b * HEAD + h2) * DK + x0 + xi) * DK + y0 + yi],
                          acc[xi][yi]);
    }
}

// ---------------- P6: Mb[o][h*32+x] = sum_y cw[o][h*32+y]*kv[b,h,x,y] -----
__global__ __launch_bounds__(512) void k_mb(const float* __restrict__ cw) {
    __shared__ float kvT[32 * 128];
    int b = blockIdx.x, t = threadIdx.x;
    for (int i = t; i < 4096; i += 512) {
        int row = i >> 5, y = i & 31;
        kvT[y * 128 + row] = g_kv[(size_t)b * 4096 + i];
    }
    __syncthreads();
    int o = t & 127, h = t >> 7;
    float acc[32];
    #pragma unroll
    for (int x = 0; x < 32; x++) acc[x] = 0.0f;
    for (int y = 0; y < 32; y++) {
        float cv = cw[o * 128 + h * 32 + y];
        const float* kr = kvT + y * 128 + h * 32;
        #pragma unroll
        for (int x = 0; x < 32; x++) acc[x] += cv * kr[x];
    }
    unsigned char* img = g_Mb + (size_t)b * 65536;
    for (int cc = 0; cc < 4; cc++) {
        unsigned short hs[8], ls[8];
        #pragma unroll
        for (int k = 0; k < 8; k++) bf_split(acc[cc * 8 + k], hs[k], ls[k]);
        int byte = (o * 128 + h * 32 + cc * 8) * 2;
        *(uint4*)(img + byte) = pack8(hs);
        *(uint4*)(img + 32768 + byte) = pack8(ls);
    }
}

// ---------------- K2: out = relu(Mb@q + Cs@v + bias2 + cb) -> affine -----
__global__ __launch_bounds__(512, 1) void k_out(const float* __restrict__ cb,
                                                const float* __restrict__ affw,
                                                const float* __restrict__ affb,
                                                float* __restrict__ out) {
    extern __shared__ __align__(16) unsigned char sm[];
    int b = blockIdx.y, tile = blockIdx.x, n0 = tile * NT, t = threadIdx.x;
    uint32_t sb = smem_u32(sm);
    int w = t >> 5, lane = t & 31;
    int wm = w >> 2, wn = w & 3;

    load_img(g_Mb + (size_t)b * 65536, sm + OFF_A, t);
    load_img(g_qimg + ((size_t)(b * NTILES + tile)) * 65536, sm + OFF_B, t);
    load_img(g_wimg + 2 * 65536, sm + OFF_C, t);     // Cs preloaded
    __syncthreads();

    float D[2][4][4];
    dzero(D);
    gemm3f(sb + OFF_A, sb + OFF_B, wm, wn, lane, D); // Mb @ q
    __syncthreads();
    load_img(g_vimg + ((size_t)(b * NTILES + tile)) * 65536, sm + OFF_A, t);  // v over Mb
    __syncthreads();
    gemm3f(sb + OFF_C, sb + OFF_A, wm, wn, lane, D); // += Cs @ v

    // ---- direct register epilogue ----
    int r0 = lane >> 2, cp = (lane & 3) * 2;
    #pragma unroll
    for (int mt = 0; mt < 2; mt++)
        #pragma unroll
        for (int nt = 0; nt < 4; nt++) {
            int col = wn * 32 + nt * 8 + cp;
            #pragma unroll
            for (int half = 0; half < 2; half++) {
                int c = wm * 32 + mt * 16 + r0 + half * 8;
                size_t base = (size_t)c * NN + n0 + col;
                float cbv = __ldg(cb + c);
                float2 b2 = *(const float2*)(g_bias2 + base);
                float2 aw = *(const float2*)(affw + base);
                float2 ab = *(const float2*)(affb + base);
                float v0 = D[mt][nt][half * 2 + 0] + cbv + b2.x;
                float v1 = D[mt][nt][half * 2 + 1] + cbv + b2.y;
                float rr0 = fmaxf(v0, 0.0f), rr1 = fmaxf(v1, 0.0f);
                float2 o2;
                o2.x = rr0 + rr0 * aw.x + ab.x;
                o2.y = rr1 + rr1 * aw.y + ab.y;
                *(float2*)(out + ((size_t)b * 128) * NN + base) = o2;
            }
        }
}

extern "C" void kernel_launch(void* const* d_in, const int* in_sizes, int n_in,
                              void* d_out, int out_size) {
    const float* x     = (const float*)d_in[0];
    const float* qw    = (const float*)d_in[1];
    const float* qb    = (const float*)d_in[2];
    const float* vw    = (const float*)d_in[3];
    const float* vb    = (const float*)d_in[4];
    const float* cw    = (const float*)d_in[5];
    const float* cb    = (const float*)d_in[6];
    const float* mem   = (const float*)d_in[7];
    const float* nv1   = (const float*)d_in[8];
    const float* nv2   = (const float*)d_in[9];
    const float* wpool = (const float*)d_in[10];
    const float* bpool = (const float*)d_in[11];
    const float* affw  = (const float*)d_in[12];
    const float* affb  = (const float*)d_in[13];
    float* out = (float*)d_out;

    k_keysm<<<HEAD * NN / 8, 256>>>(mem);
    k_biasdyn<<<NN / 8, 256>>>(nv1, nv2, bpool);
    k_zero_kv<<<(BATCH * HEAD * DK * DK + 255) / 256, 256>>>();
    k_prepw<<<dim3(4, 8), 128>>>(qw, vw, cw, wpool);
    k_bias2<<<NN, 128>>>();

    cudaFuncSetAttribute(k_qv, cudaFuncAttributeMaxDynamicSharedMemorySize, SMEM_QV);
    k_qv<<<dim3(NTILES, BATCH), 512, SMEM_QV>>>(x, qb, vb);

    k_mb<<<BATCH, 512>>>(cw);

    cudaFuncSetAttribute(k_out, cudaFuncAttributeMaxDynamicSharedMemorySize, SMEM_OUT);
    k_out<<<dim3(NTILES, BATCH), 512, SMEM_OUT>>>(cb, affw, affb, out);
}

// round 10
// speedup vs baseline: 4.4272x; 1.1986x over previous
#include <cuda_runtime.h>
#include <cuda_fp16.h>
#include <math.h>
#include <stdint.h>

#define BATCH 64
#define DMODEL 128
#define NN 2048
#define HEAD 4
#define DK 32
#define NT 128
#define NTILES (NN/NT)  // 16

// smem byte offsets
#define IMG_HALF 34816     // 128 rows * 272 B (one half: hi or lo)
#define ROWB 272           // 136 fp16 row stride
// k_qv: A (hi+lo) | B (hi only) | D fp32 | biases
#define QV_A 0             // 69632
#define QV_B 69632         // 34816
#define QV_D 104448        // 66048 : fp32 [128][129]
#define QV_SB 170496       // 1024
#define SMEM_QV 171520
// k_out: A=Mb hi/lo | C=Cs hi/lo | Bq hi | Bv hi
#define KO_A 0             // 69632
#define KO_C 69632         // 69632
#define KO_BQ 139264       // 34816
#define KO_BV 174080       // 34816
#define SMEM_OUT 208896

// ---------------- device globals ----------------
static __device__ float g_keysm[HEAD * NN * DK];
static __device__ float g_biasdyn[NN * DK];
static __device__ float g_kv[BATCH * HEAD * DK * DK];
static __device__ float g_bias2[DMODEL * NN];
static __device__ float g_Cp[DMODEL * DK];
// packed gmem images (fp16): weights/Mb = hi [128][128] (32768B) + lo (32768B)
static __device__ __align__(16) unsigned char g_wimg[3 * 65536];                      // Wq, Wv, Cs
static __device__ __align__(16) unsigned char g_qimg[(size_t)BATCH * NTILES * 32768]; // q hi
static __device__ __align__(16) unsigned char g_vimg[(size_t)BATCH * NTILES * 32768]; // v hi
static __device__ __align__(16) unsigned char g_Mb[(size_t)BATCH * 65536];            // Mb hi/lo

// ---------------- helpers ----------------
__device__ __forceinline__ uint32_t smem_u32(const void* p) {
    uint32_t a;
    asm("{ .reg .u64 t; cvta.to.shared.u64 t, %1; cvt.u32.u64 %0, t; }" : "=r"(a) : "l"(p));
    return a;
}
__device__ __forceinline__ void hf_split(float v, unsigned short& h, unsigned short& l) {
    __half hh = __float2half_rn(v);
    h = __half_as_ushort(hh);
    l = __half_as_ushort(__float2half_rn(v - __half2float(hh)));
}
__device__ __forceinline__ unsigned short hf1(float v) {
    return __half_as_ushort(__float2half_rn(v));
}
__device__ __forceinline__ uint4 pack8(const unsigned short* h) {
    uint4 u;
    u.x = (uint32_t)h[0] | ((uint32_t)h[1] << 16);
    u.y = (uint32_t)h[2] | ((uint32_t)h[3] << 16);
    u.z = (uint32_t)h[4] | ((uint32_t)h[5] << 16);
    u.w = (uint32_t)h[6] | ((uint32_t)h[7] << 16);
    return u;
}
__device__ __forceinline__ float warp_max(float v) {
    #pragma unroll
    for (int o = 16; o; o >>= 1) v = fmaxf(v, __shfl_xor_sync(0xffffffffu, v, o));
    return v;
}
__device__ __forceinline__ float warp_sum(float v) {
    #pragma unroll
    for (int o = 16; o; o >>= 1) v += __shfl_xor_sync(0xffffffffu, v, o);
    return v;
}
__device__ __forceinline__ void ldsm4(uint32_t addr, uint32_t& r0, uint32_t& r1,
                                      uint32_t& r2, uint32_t& r3) {
    asm volatile("ldmatrix.sync.aligned.m8n8.x4.shared.b16 {%0,%1,%2,%3}, [%4];"
                 : "=r"(r0), "=r"(r1), "=r"(r2), "=r"(r3) : "r"(addr));
}
__device__ __forceinline__ void mma16816(float d[4], const uint32_t a[4],
                                         uint32_t b0, uint32_t b1) {
    asm volatile("mma.sync.aligned.m16n8k16.row.col.f32.f16.f16.f32 "
                 "{%0,%1,%2,%3}, {%4,%5,%6,%7}, {%8,%9}, {%0,%1,%2,%3};"
                 : "+f"(d[0]), "+f"(d[1]), "+f"(d[2]), "+f"(d[3])
                 : "r"(a[0]), "r"(a[1]), "r"(a[2]), "r"(a[3]), "r"(b0), "r"(b1));
}

// gmem packed hi+lo -> smem padded (both halves)
__device__ __forceinline__ void load_img2(const unsigned char* g, unsigned char* s, int t) {
    const uint4* src = (const uint4*)g;
    uint4* dst = (uint4*)s;
    #pragma unroll 1
    for (int half = 0; half < 2; half++)
        for (int i = t; i < 2048; i += 512) {
            int r = i >> 4, c = i & 15;
            dst[half * 2176 + r * 17 + c] = src[half * 2048 + i];
        }
}
// single-half loaders/stores
__device__ __forceinline__ void load_img1(const unsigned char* g, unsigned char* s, int t) {
    const uint4* src = (const uint4*)g;
    uint4* dst = (uint4*)s;
    for (int i = t; i < 2048; i += 512) {
        int r = i >> 4, c = i & 15;
        dst[r * 17 + c] = src[i];
    }
}
__device__ __forceinline__ void store_img1(unsigned char* g, const unsigned char* s, int t) {
    uint4* dst = (uint4*)g;
    const uint4* src = (const uint4*)s;
    for (int i = t; i < 2048; i += 512) {
        int r = i >> 4, c = i & 15;
        dst[i] = src[r * 17 + c];
    }
}

// 2-pass asymmetric GEMM: D(32x32) += (Ah + Al)(hi/lo fp16) * Bh^T(fp16)
// 16 warps, 4x4 warp grid.
__device__ __forceinline__ void gemm2f(uint32_t Ahi, uint32_t Bhi, int wm, int wn,
                                       int lane, float D[2][4][4]) {
    int mat = lane >> 3, r8 = lane & 7;
    int arow = wm * 32 + ((mat & 1) << 3) + r8;
    int acol0 = (mat >> 1) << 3;
    int brow = wn * 32 + ((mat >> 1) << 3) + r8;
    int bcol0 = (mat & 1) << 3;
    #pragma unroll
    for (int ks = 0; ks < 8; ks++) {
        int k = ks * 16;
        uint32_t ah[2][4], al[2][4], bh[2][4];
        #pragma unroll
        for (int mt = 0; mt < 2; mt++) {
            uint32_t addr = Ahi + (arow + mt * 16) * ROWB + (k + acol0) * 2;
            ldsm4(addr, ah[mt][0], ah[mt][1], ah[mt][2], ah[mt][3]);
            ldsm4(addr + IMG_HALF, al[mt][0], al[mt][1], al[mt][2], al[mt][3]);
        }
        #pragma unroll
        for (int bt = 0; bt < 2; bt++) {
            uint32_t addr = Bhi + (brow + bt * 16) * ROWB + (k + bcol0) * 2;
            ldsm4(addr, bh[bt][0], bh[bt][1], bh[bt][2], bh[bt][3]);
        }
        #pragma unroll
        for (int mt = 0; mt < 2; mt++)
            #pragma unroll
            for (int nt = 0; nt < 4; nt++)
                mma16816(D[mt][nt], ah[mt], bh[nt >> 1][(nt & 1) * 2],
                         bh[nt >> 1][(nt & 1) * 2 + 1]);
        #pragma unroll
        for (int mt = 0; mt < 2; mt++)
            #pragma unroll
            for (int nt = 0; nt < 4; nt++)
                mma16816(D[mt][nt], al[mt], bh[nt >> 1][(nt & 1) * 2],
                         bh[nt >> 1][(nt & 1) * 2 + 1]);
    }
}
__device__ __forceinline__ void dzero(float D[2][4][4]) {
    #pragma unroll
    for (int mt = 0; mt < 2; mt++)
        #pragma unroll
        for (int nt = 0; nt < 4; nt++)
            #pragma unroll
            for (int i = 0; i < 4; i++) D[mt][nt][i] = 0.0f;
}
__device__ __forceinline__ void dwrite(float* Dsm, int wm, int wn, int lane, float D[2][4][4]) {
    int r = lane >> 2, cc = (lane & 3) * 2;
    #pragma unroll
    for (int mt = 0; mt < 2; mt++)
        #pragma unroll
        for (int nt = 0; nt < 4; nt++) {
            int row = wm * 32 + mt * 16 + r;
            int col = wn * 32 + nt * 8 + cc;
            Dsm[row * 129 + col] = D[mt][nt][0];
            Dsm[row * 129 + col + 1] = D[mt][nt][1];
            Dsm[(row + 8) * 129 + col] = D[mt][nt][2];
            Dsm[(row + 8) * 129 + col + 1] = D[mt][nt][3];
        }
}

// ---------------- P1: key softmax ----------------
__global__ void k_keysm(const float* __restrict__ mem) {
    const float inv_scale = 0.17677669529663687f;
    int row = blockIdx.x * 8 + (threadIdx.x >> 5);
    int lane = threadIdx.x & 31;
    float v = mem[row * 32 + lane] * inv_scale;
    float m = warp_max(v);
    float e = __expf(v - m);
    float s = warp_sum(e);
    g_keysm[row * 32 + lane] = e / s;
}

// ---------------- P2: bias_dyn ----------------
__global__ __launch_bounds__(256) void k_biasdyn(const float* __restrict__ nv1,
                                                 const float* __restrict__ nv2,
                                                 const float* __restrict__ bpool) {
    __shared__ float p[8][NN];
    __shared__ float red[256];
    __shared__ float a1[8][10];
    __shared__ float invs[8];
    int n0 = blockIdx.x * 8;
    int t = threadIdx.x;
    if (t < 80) a1[t / 10][t % 10] = nv1[(n0 + t / 10) * 10 + (t % 10)];
    __syncthreads();
    for (int r = 0; r < 8; r++) {
        float lv[8];
        float lmax = 0.0f;
        #pragma unroll
        for (int i = 0; i < 8; i++) {
            int m = t + i * 256;
            float acc = 0.0f;
            #pragma unroll
            for (int k = 0; k < 10; k++) acc += a1[r][k] * nv2[k * NN + m];
            acc = fmaxf(acc, 0.0f);
            lv[i] = acc;
            lmax = fmaxf(lmax, acc);
        }
        red[t] = lmax; __syncthreads();
        for (int s = 128; s; s >>= 1) { if (t < s) red[t] = fmaxf(red[t], red[t + s]); __syncthreads(); }
        float bmax = red[0];
        __syncthreads();
        float lsum = 0.0f;
        #pragma unroll
        for (int i = 0; i < 8; i++) {
            float e = __expf(lv[i] - bmax);
            p[r][t + i * 256] = e;
            lsum += e;
        }
        red[t] = lsum; __syncthreads();
        for (int s = 128; s; s >>= 1) { if (t < s) red[t] += red[t + s]; __syncthreads(); }
        if (t == 0) invs[r] = 1.0f / red[0];
        __syncthreads();
    }
    int c = t & 31, g = t >> 5;
    float acc[8];
    #pragma unroll
    for (int r = 0; r < 8; r++) acc[r] = 0.0f;
    for (int m = g; m < NN; m += 8) {
        float bp = bpool[m * 32 + c];
        #pragma unroll
        for (int r = 0; r < 8; r++) acc[r] += p[r][m] * bp;
    }
    for (int r = 0; r < 8; r++) {
        red[t] = acc[r]; __syncthreads();
        if (t < 32) {
            float s2 = 0.0f;
            #pragma unroll
            for (int g2 = 0; g2 < 8; g2++) s2 += red[g2 * 32 + t];
            g_biasdyn[(n0 + r) * 32 + t] = s2 * invs[r];
        }
        __syncthreads();
    }
}

// ---------------- P3: zero kv ----------------
__global__ void k_zero_kv() {
    int i = blockIdx.x * 256 + threadIdx.x;
    if (i < BATCH * HEAD * DK * DK) g_kv[i] = 0.0f;
}

// ---------------- P4: weight images (fp16 hi/lo) + Cp ----------------
__global__ __launch_bounds__(128) void k_prepw(const float* __restrict__ qw,
                                               const float* __restrict__ vw,
                                               const float* __restrict__ cw,
                                               const float* __restrict__ wpool) {
    int m = blockIdx.x, part = blockIdx.y;
    int o = threadIdx.x;
    if (m == 3) {
        if (part == 0) {
            for (int y = 0; y < 32; y++) {
                float s = 0.0f;
                #pragma unroll
                for (int h = 0; h < 4; h++) s += cw[o * 128 + h * 32 + y];
                g_Cp[o * 32 + y] = s;
            }
        }
        return;
    }
    const float* w = (m == 0) ? qw : (m == 1) ? vw : cw;
    float scale = 1.0f;
    if (m == 2) {
        float S = 0.0f;
        #pragma unroll
        for (int i = 0; i < 9; i++) S += wpool[i];
        scale = S;
    }
    unsigned char* img = g_wimg + m * 65536;
    for (int cc = part * 2; cc < part * 2 + 2; cc++) {
        unsigned short hs[8], ls[8];
        #pragma unroll
        for (int k = 0; k < 8; k++) hf_split(w[o * 128 + cc * 8 + k] * scale, hs[k], ls[k]);
        int byte = (o * 128 + cc * 8) * 2;
        *(uint4*)(img + byte) = pack8(hs);
        *(uint4*)(img + 32768 + byte) = pack8(ls);
    }
}

// ---------------- P4b: bias2 = Cp @ bias_dyn^T ----------------
__global__ __launch_bounds__(128) void k_bias2() {
    __shared__ float bd[32];
    int n = blockIdx.x, t = threadIdx.x;
    if (t < 32) bd[t] = g_biasdyn[n * 32 + t];
    __syncthreads();
    float s = 0.0f;
    #pragma unroll
    for (int y = 0; y < 32; y++) s += g_Cp[t * 32 + y] * bd[y];
    g_bias2[t * NN + n] = s;
}

// ---------------- K1: x convert + Q/V convs + softmax + kv partial --------
__global__ __launch_bounds__(512, 1) void k_qv(const float* __restrict__ x,
                                               const float* __restrict__ qb,
                                               const float* __restrict__ vb) {
    extern __shared__ __align__(16) unsigned char sm[];
    int b = blockIdx.y, tile = blockIdx.x, n0 = tile * NT, t = threadIdx.x;
    uint32_t sb = smem_u32(sm);
    float* Dsm = (float*)(sm + QV_D);
    float* sbias = (float*)(sm + QV_SB);
    int w = t >> 5, lane = t & 31;
    int wm = w >> 2, wn = w & 3;

    load_img2(g_wimg, sm + QV_A, t);                 // Wq hi/lo
    for (int i = t; i < 16384; i += 512) {
        int c = i >> 7, n = i & 127;
        Dsm[c * 129 + n] = x[((size_t)b * 128 + c) * NN + n0 + n];
    }
    if (t < 128) sbias[t] = qb[t];
    else if (t < 256) sbias[t] = vb[t - 128];
    __syncthreads();

    // convert x -> B image (hi only)
    {
        int node = t >> 2, q4 = t & 3;
        #pragma unroll
        for (int cc = 0; cc < 4; cc++) {
            int c0 = q4 * 32 + cc * 8;
            unsigned short hs[8];
            #pragma unroll
            for (int k = 0; k < 8; k++) hs[k] = hf1(Dsm[(c0 + k) * 129 + node]);
            *(uint4*)(sm + QV_B + node * ROWB + c0 * 2) = pack8(hs);
        }
    }
    __syncthreads();

    float D[2][4][4];
    dzero(D);
    gemm2f(sb + QV_A, sb + QV_B, wm, wn, lane, D);   // Q = Wq @ x
    dwrite(Dsm, wm, wn, lane, D);
    __syncthreads();

    // ---- Q epilogue: per-node softmax per head; q hi image into A ----
    const float inv_scale = 0.17677669529663687f;
    {
        int node = t & 127, h = t >> 7;
        float q[32];
        float mx = 0.0f;
        #pragma unroll
        for (int i = 0; i < 32; i++) {
            q[i] = fmaxf(Dsm[(h * 32 + i) * 129 + node] + sbias[h * 32 + i], 0.0f);
            mx = fmaxf(mx, q[i]);
        }
        float s = 0.0f;
        #pragma unroll
        for (int i = 0; i < 32; i++) { q[i] = __expf((q[i] - mx) * inv_scale); s += q[i]; }
        float is = 1.0f / s;
        #pragma unroll
        for (int cc = 0; cc < 4; cc++) {
            unsigned short hs[8];
            #pragma unroll
            for (int k = 0; k < 8; k++) hs[k] = hf1(q[cc * 8 + k] * is);
            *(uint4*)(sm + QV_A + node * ROWB + (h * 32 + cc * 8) * 2) = pack8(hs);
        }
    }
    __syncthreads();
    store_img1(g_qimg + ((size_t)(b * NTILES + tile)) * 32768, sm + QV_A, t);
    __syncthreads();

    load_img2(g_wimg + 65536, sm + QV_A, t);         // Wv hi/lo (B keeps x)
    __syncthreads();
    dzero(D);
    gemm2f(sb + QV_A, sb + QV_B, wm, wn, lane, D);   // V = Wv @ x
    dwrite(Dsm, wm, wn, lane, D);
    __syncthreads();

    // ---- V epilogue: relu writeback; v hi image into B; ks into A ----
    {
        int node = t & 127, h = t >> 7;
        float v[32];
        #pragma unroll
        for (int i = 0; i < 32; i++) {
            v[i] = fmaxf(Dsm[(h * 32 + i) * 129 + node] + sbias[128 + h * 32 + i], 0.0f);
            Dsm[(h * 32 + i) * 129 + node] = v[i];
        }
        #pragma unroll
        for (int cc = 0; cc < 4; cc++) {
            unsigned short hs[8];
            #pragma unroll
            for (int k = 0; k < 8; k++) hs[k] = hf1(v[cc * 8 + k]);
            *(uint4*)(sm + QV_B + node * ROWB + (h * 32 + cc * 8) * 2) = pack8(hs);
        }
    }
    float* ks = (float*)(sm + QV_A);   // 17408 floats avail >= 16384
    for (int i = t; i < 16384; i += 512) {
        int h2 = i >> 12, r = i & 4095;
        int j2 = r >> 5, xk = r & 31;
        ks[i] = g_keysm[(h2 * NN + n0 + j2) * 32 + xk];
    }
    __syncthreads();
    store_img1(g_vimg + ((size_t)(b * NTILES + tile)) * 32768, sm + QV_B, t);
    {
        int idx = t & 127, h2 = t >> 7;
        int x0 = (idx >> 4) * 4, y0 = (idx & 15) * 2;
        float acc[4][2];
        #pragma unroll
        for (int a = 0; a < 4; a++) { acc[a][0] = 0.0f; acc[a][1] = 0.0f; }
        #pragma unroll 4
        for (int jj = 0; jj < NT; jj++) {
            float4 kx = *(const float4*)(ks + (h2 * NT + jj) * 32 + x0);
            float v0 = Dsm[(h2 * 32 + y0 + 0) * 129 + jj];
            float v1 = Dsm[(h2 * 32 + y0 + 1) * 129 + jj];
            acc[0][0] += kx.x * v0; acc[0][1] += kx.x * v1;
            acc[1][0] += kx.y * v0; acc[1][1] += kx.y * v1;
            acc[2][0] += kx.z * v0; acc[2][1] += kx.z * v1;
            acc[3][0] += kx.w * v0; acc[3][1] += kx.w * v1;
        }
        #pragma unroll
        for (int xi = 0; xi < 4; xi++)
            #pragma unroll
            for (int yi = 0; yi < 2; yi++)
                atomicAdd(&g_kv[(((size_t)b * HEAD + h2) * DK + x0 + xi) * DK + y0 + yi],
                          acc[xi][yi]);
    }
}

// ---------------- P6: Mb (fp16 hi/lo) ----------------
__global__ __launch_bounds__(512) void k_mb(const float* __restrict__ cw) {
    __shared__ float kvT[32 * 128];
    int b = blockIdx.x, t = threadIdx.x;
    for (int i = t; i < 4096; i += 512) {
        int row = i >> 5, y = i & 31;
        kvT[y * 128 + row] = g_kv[(size_t)b * 4096 + i];
    }
    __syncthreads();
    int o = t & 127, h = t >> 7;
    float acc[32];
    #pragma unroll
    for (int x = 0; x < 32; x++) acc[x] = 0.0f;
    for (int y = 0; y < 32; y++) {
        float cv = cw[o * 128 + h * 32 + y];
        const float* kr = kvT + y * 128 + h * 32;
        #pragma unroll
        for (int x = 0; x < 32; x++) acc[x] += cv * kr[x];
    }
    unsigned char* img = g_Mb + (size_t)b * 65536;
    for (int cc = 0; cc < 4; cc++) {
        unsigned short hs[8], ls[8];
        #pragma unroll
        for (int k = 0; k < 8; k++) hf_split(acc[cc * 8 + k], hs[k], ls[k]);
        int byte = (o * 128 + h * 32 + cc * 8) * 2;
        *(uint4*)(img + byte) = pack8(hs);
        *(uint4*)(img + 32768 + byte) = pack8(ls);
    }
}

// ---------------- K2: out = relu(Mb@q + Cs@v + bias2 + cb) -> affine -----
__global__ __launch_bounds__(512, 1) void k_out(const float* __restrict__ cb,
                                                const float* __restrict__ affw,
                                                const float* __restrict__ affb,
                                                float* __restrict__ out) {
    extern __shared__ __align__(16) unsigned char sm[];
    int b = blockIdx.y, tile = blockIdx.x, n0 = tile * NT, t = threadIdx.x;
    uint32_t sb = smem_u32(sm);
    int w = t >> 5, lane = t & 31;
    int wm = w >> 2, wn = w & 3;

    load_img2(g_Mb + (size_t)b * 65536, sm + KO_A, t);
    load_img2(g_wimg + 2 * 65536, sm + KO_C, t);
    load_img1(g_qimg + ((size_t)(b * NTILES + tile)) * 32768, sm + KO_BQ, t);
    load_img1(g_vimg + ((size_t)(b * NTILES + tile)) * 32768, sm + KO_BV, t);
    __syncthreads();

    float D[2][4][4];
    dzero(D);
    gemm2f(sb + KO_A, sb + KO_BQ, wm, wn, lane, D);  // Mb @ q
    gemm2f(sb + KO_C, sb + KO_BV, wm, wn, lane, D);  // += Cs @ v

    // ---- direct register epilogue ----
    int r0 = lane >> 2, cp = (lane & 3) * 2;
    #pragma unroll
    for (int mt = 0; mt < 2; mt++)
        #pragma unroll
        for (int nt = 0; nt < 4; nt++) {
            int col = wn * 32 + nt * 8 + cp;
            #pragma unroll
            for (int half = 0; half < 2; half++) {
                int c = wm * 32 + mt * 16 + r0 + half * 8;
                size_t base = (size_t)c * NN + n0 + col;
                float cbv = __ldg(cb + c);
                float2 b2 = *(const float2*)(g_bias2 + base);
                float2 aw = *(const float2*)(affw + base);
                float2 ab = *(const float2*)(affb + base);
                float v0 = D[mt][nt][half * 2 + 0] + cbv + b2.x;
                float v1 = D[mt][nt][half * 2 + 1] + cbv + b2.y;
                float rr0 = fmaxf(v0, 0.0f), rr1 = fmaxf(v1, 0.0f);
                float2 o2;
                o2.x = rr0 + rr0 * aw.x + ab.x;
                o2.y = rr1 + rr1 * aw.y + ab.y;
                *(float2*)(out + ((size_t)b * 128) * NN + base) = o2;
            }
        }
}

extern "C" void kernel_launch(void* const* d_in, const int* in_sizes, int n_in,
                              void* d_out, int out_size) {
    const float* x     = (const float*)d_in[0];
    const float* qw    = (const float*)d_in[1];
    const float* qb    = (const float*)d_in[2];
    const float* vw    = (const float*)d_in[3];
    const float* vb    = (const float*)d_in[4];
    const float* cw    = (const float*)d_in[5];
    const float* cb    = (const float*)d_in[6];
    const float* mem   = (const float*)d_in[7];
    const float* nv1   = (const float*)d_in[8];
    const float* nv2   = (const float*)d_in[9];
    const float* wpool = (const float*)d_in[10];
    const float* bpool = (const float*)d_in[11];
    const float* affw  = (const float*)d_in[12];
    const float* affb  = (const float*)d_in[13];
    float* out = (float*)d_out;

    k_keysm<<<HEAD * NN / 8, 256>>>(mem);
    k_biasdyn<<<NN / 8, 256>>>(nv1, nv2, bpool);
    k_zero_kv<<<(BATCH * HEAD * DK * DK + 255) / 256, 256>>>();
    k_prepw<<<dim3(4, 8), 128>>>(qw, vw, cw, wpool);
    k_bias2<<<NN, 128>>>();

    cudaFuncSetAttribute(k_qv, cudaFuncAttributeMaxDynamicSharedMemorySize, SMEM_QV);
    k_qv<<<dim3(NTILES, BATCH), 512, SMEM_QV>>>(x, qb, vb);

    k_mb<<<BATCH, 512>>>(cw);

    cudaFuncSetAttribute(k_out, cudaFuncAttributeMaxDynamicSharedMemorySize, SMEM_OUT);
    k_out<<<dim3(NTILES, BATCH), 512, SMEM_OUT>>>(cb, affw, affb, out);
}

// round 11
// speedup vs baseline: 5.0002x; 1.1294x over previous
#include <cuda_runtime.h>
#include <cuda_fp16.h>
#include <math.h>
#include <stdint.h>

#define BATCH 64
#define DMODEL 128
#define NN 2048
#define HEAD 4
#define DK 32
#define NT 128
#define NTILES (NN/NT)  // 16

// smem byte offsets
#define IMG_SZ 34816       // 128 rows * 272 B (single fp16 image, padded)
#define ROWB 272           // 136 fp16 row stride
// k_qv: A | B | D fp32 | biases
#define QV_A 0             // 34816
#define QV_B 34816         // 34816
#define QV_D 69632         // 66048 : fp32 [128][129]
#define QV_SB 135680       // 1024
#define SMEM_QV 136704
// k_out: A=Mb | C=Cs | Bq | Bv
#define KO_A 0
#define KO_C 34816
#define KO_BQ 69632
#define KO_BV 104448
#define SMEM_OUT 139264

// ---------------- device globals ----------------
static __device__ float g_keysm[HEAD * NN * DK];
static __device__ float g_biasdyn[NN * DK];
static __device__ float g_kv[BATCH * HEAD * DK * DK];
static __device__ float g_bias2[DMODEL * NN];
static __device__ float g_Cp[DMODEL * DK];
// packed gmem images (fp16, single): [128][128] = 32768 B
static __device__ __align__(16) unsigned char g_wimg[3 * 32768];                      // Wq, Wv, Cs
static __device__ __align__(16) unsigned char g_qimg[(size_t)BATCH * NTILES * 32768]; // q
static __device__ __align__(16) unsigned char g_vimg[(size_t)BATCH * NTILES * 32768]; // v
static __device__ __align__(16) unsigned char g_Mb[(size_t)BATCH * 32768];            // Mb

// ---------------- helpers ----------------
__device__ __forceinline__ uint32_t smem_u32(const void* p) {
    uint32_t a;
    asm("{ .reg .u64 t; cvta.to.shared.u64 t, %1; cvt.u32.u64 %0, t; }" : "=r"(a) : "l"(p));
    return a;
}
__device__ __forceinline__ unsigned short hf1(float v) {
    return __half_as_ushort(__float2half_rn(v));
}
__device__ __forceinline__ uint4 pack8(const unsigned short* h) {
    uint4 u;
    u.x = (uint32_t)h[0] | ((uint32_t)h[1] << 16);
    u.y = (uint32_t)h[2] | ((uint32_t)h[3] << 16);
    u.z = (uint32_t)h[4] | ((uint32_t)h[5] << 16);
    u.w = (uint32_t)h[6] | ((uint32_t)h[7] << 16);
    return u;
}
__device__ __forceinline__ float warp_max(float v) {
    #pragma unroll
    for (int o = 16; o; o >>= 1) v = fmaxf(v, __shfl_xor_sync(0xffffffffu, v, o));
    return v;
}
__device__ __forceinline__ float warp_sum(float v) {
    #pragma unroll
    for (int o = 16; o; o >>= 1) v += __shfl_xor_sync(0xffffffffu, v, o);
    return v;
}
__device__ __forceinline__ void ldsm4(uint32_t addr, uint32_t& r0, uint32_t& r1,
                                      uint32_t& r2, uint32_t& r3) {
    asm volatile("ldmatrix.sync.aligned.m8n8.x4.shared.b16 {%0,%1,%2,%3}, [%4];"
                 : "=r"(r0), "=r"(r1), "=r"(r2), "=r"(r3) : "r"(addr));
}
__device__ __forceinline__ void mma16816(float d[4], const uint32_t a[4],
                                         uint32_t b0, uint32_t b1) {
    asm volatile("mma.sync.aligned.m16n8k16.row.col.f32.f16.f16.f32 "
                 "{%0,%1,%2,%3}, {%4,%5,%6,%7}, {%8,%9}, {%0,%1,%2,%3};"
                 : "+f"(d[0]), "+f"(d[1]), "+f"(d[2]), "+f"(d[3])
                 : "r"(a[0]), "r"(a[1]), "r"(a[2]), "r"(a[3]), "r"(b0), "r"(b1));
}
// gmem packed [128][128] fp16 -> smem padded stride 136 (512 threads)
__device__ __forceinline__ void load_img1(const unsigned char* g, unsigned char* s, int t) {
    const uint4* src = (const uint4*)g;
    uint4* dst = (uint4*)s;
    for (int i = t; i < 2048; i += 512) {
        int r = i >> 4, c = i & 15;
        dst[r * 17 + c] = src[i];
    }
}
__device__ __forceinline__ void store_img1(unsigned char* g, const unsigned char* s, int t) {
    uint4* dst = (uint4*)g;
    const uint4* src = (const uint4*)s;
    for (int i = t; i < 2048; i += 512) {
        int r = i >> 4, c = i & 15;
        dst[i] = src[r * 17 + c];
    }
}

// single-pass fp16 GEMM: D(32x32) += A * B^T ; 16 warps, 4x4 warp grid.
__device__ __forceinline__ void gemm1f(uint32_t A, uint32_t B, int wm, int wn,
                                       int lane, float D[2][4][4]) {
    int mat = lane >> 3, r8 = lane & 7;
    int arow = wm * 32 + ((mat & 1) << 3) + r8;
    int acol0 = (mat >> 1) << 3;
    int brow = wn * 32 + ((mat >> 1) << 3) + r8;
    int bcol0 = (mat & 1) << 3;
    #pragma unroll
    for (int ks = 0; ks < 8; ks++) {
        int k = ks * 16;
        uint32_t a[2][4], bf[2][4];
        #pragma unroll
        for (int mt = 0; mt < 2; mt++)
            ldsm4(A + (arow + mt * 16) * ROWB + (k + acol0) * 2,
                  a[mt][0], a[mt][1], a[mt][2], a[mt][3]);
        #pragma unroll
        for (int bt = 0; bt < 2; bt++)
            ldsm4(B + (brow + bt * 16) * ROWB + (k + bcol0) * 2,
                  bf[bt][0], bf[bt][1], bf[bt][2], bf[bt][3]);
        #pragma unroll
        for (int mt = 0; mt < 2; mt++)
            #pragma unroll
            for (int nt = 0; nt < 4; nt++)
                mma16816(D[mt][nt], a[mt], bf[nt >> 1][(nt & 1) * 2],
                         bf[nt >> 1][(nt & 1) * 2 + 1]);
    }
}
__device__ __forceinline__ void dzero(float D[2][4][4]) {
    #pragma unroll
    for (int mt = 0; mt < 2; mt++)
        #pragma unroll
        for (int nt = 0; nt < 4; nt++)
            #pragma unroll
            for (int i = 0; i < 4; i++) D[mt][nt][i] = 0.0f;
}
__device__ __forceinline__ void dwrite(float* Dsm, int wm, int wn, int lane, float D[2][4][4]) {
    int r = lane >> 2, cc = (lane & 3) * 2;
    #pragma unroll
    for (int mt = 0; mt < 2; mt++)
        #pragma unroll
        for (int nt = 0; nt < 4; nt++) {
            int row = wm * 32 + mt * 16 + r;
            int col = wn * 32 + nt * 8 + cc;
            Dsm[row * 129 + col] = D[mt][nt][0];
            Dsm[row * 129 + col + 1] = D[mt][nt][1];
            Dsm[(row + 8) * 129 + col] = D[mt][nt][2];
            Dsm[(row + 8) * 129 + col + 1] = D[mt][nt][3];
        }
}

// ---------------- P1: key softmax ----------------
__global__ void k_keysm(const float* __restrict__ mem) {
    const float inv_scale = 0.17677669529663687f;
    int row = blockIdx.x * 8 + (threadIdx.x >> 5);
    int lane = threadIdx.x & 31;
    float v = mem[row * 32 + lane] * inv_scale;
    float m = warp_max(v);
    float e = __expf(v - m);
    float s = warp_sum(e);
    g_keysm[row * 32 + lane] = e / s;
}

// ---------------- P2: bias_dyn ----------------
__global__ __launch_bounds__(256) void k_biasdyn(const float* __restrict__ nv1,
                                                 const float* __restrict__ nv2,
                                                 const float* __restrict__ bpool) {
    __shared__ float p[8][NN];
    __shared__ float red[256];
    __shared__ float a1[8][10];
    __shared__ float invs[8];
    int n0 = blockIdx.x * 8;
    int t = threadIdx.x;
    if (t < 80) a1[t / 10][t % 10] = nv1[(n0 + t / 10) * 10 + (t % 10)];
    __syncthreads();
    for (int r = 0; r < 8; r++) {
        float lv[8];
        float lmax = 0.0f;
        #pragma unroll
        for (int i = 0; i < 8; i++) {
            int m = t + i * 256;
            float acc = 0.0f;
            #pragma unroll
            for (int k = 0; k < 10; k++) acc += a1[r][k] * nv2[k * NN + m];
            acc = fmaxf(acc, 0.0f);
            lv[i] = acc;
            lmax = fmaxf(lmax, acc);
        }
        red[t] = lmax; __syncthreads();
        for (int s = 128; s; s >>= 1) { if (t < s) red[t] = fmaxf(red[t], red[t + s]); __syncthreads(); }
        float bmax = red[0];
        __syncthreads();
        float lsum = 0.0f;
        #pragma unroll
        for (int i = 0; i < 8; i++) {
            float e = __expf(lv[i] - bmax);
            p[r][t + i * 256] = e;
            lsum += e;
        }
        red[t] = lsum; __syncthreads();
        for (int s = 128; s; s >>= 1) { if (t < s) red[t] += red[t + s]; __syncthreads(); }
        if (t == 0) invs[r] = 1.0f / red[0];
        __syncthreads();
    }
    int c = t & 31, g = t >> 5;
    float acc[8];
    #pragma unroll
    for (int r = 0; r < 8; r++) acc[r] = 0.0f;
    for (int m = g; m < NN; m += 8) {
        float bp = bpool[m * 32 + c];
        #pragma unroll
        for (int r = 0; r < 8; r++) acc[r] += p[r][m] * bp;
    }
    for (int r = 0; r < 8; r++) {
        red[t] = acc[r]; __syncthreads();
        if (t < 32) {
            float s2 = 0.0f;
            #pragma unroll
            for (int g2 = 0; g2 < 8; g2++) s2 += red[g2 * 32 + t];
            g_biasdyn[(n0 + r) * 32 + t] = s2 * invs[r];
        }
        __syncthreads();
    }
}

// ---------------- P3: zero kv ----------------
__global__ void k_zero_kv() {
    int i = blockIdx.x * 256 + threadIdx.x;
    if (i < BATCH * HEAD * DK * DK) g_kv[i] = 0.0f;
}

// ---------------- P4: weight images (single fp16) + Cp ----------------
__global__ __launch_bounds__(128) void k_prepw(const float* __restrict__ qw,
                                               const float* __restrict__ vw,
                                               const float* __restrict__ cw,
                                               const float* __restrict__ wpool) {
    int m = blockIdx.x, part = blockIdx.y;
    int o = threadIdx.x;
    if (m == 3) {
        if (part == 0) {
            for (int y = 0; y < 32; y++) {
                float s = 0.0f;
                #pragma unroll
                for (int h = 0; h < 4; h++) s += cw[o * 128 + h * 32 + y];
                g_Cp[o * 32 + y] = s;
            }
        }
        return;
    }
    const float* w = (m == 0) ? qw : (m == 1) ? vw : cw;
    float scale = 1.0f;
    if (m == 2) {
        float S = 0.0f;
        #pragma unroll
        for (int i = 0; i < 9; i++) S += wpool[i];
        scale = S;
    }
    unsigned char* img = g_wimg + m * 32768;
    for (int cc = part * 2; cc < part * 2 + 2; cc++) {
        unsigned short hs[8];
        #pragma unroll
        for (int k = 0; k < 8; k++) hs[k] = hf1(w[o * 128 + cc * 8 + k] * scale);
        *(uint4*)(img + (o * 128 + cc * 8) * 2) = pack8(hs);
    }
}

// ---------------- P4b: bias2 = Cp @ bias_dyn^T ----------------
__global__ __launch_bounds__(128) void k_bias2() {
    __shared__ float bd[32];
    int n = blockIdx.x, t = threadIdx.x;
    if (t < 32) bd[t] = g_biasdyn[n * 32 + t];
    __syncthreads();
    float s = 0.0f;
    #pragma unroll
    for (int y = 0; y < 32; y++) s += g_Cp[t * 32 + y] * bd[y];
    g_bias2[t * NN + n] = s;
}

// ---------------- K1: x convert + Q/V convs + softmax + kv partial --------
__global__ __launch_bounds__(512, 1) void k_qv(const float* __restrict__ x,
                                               const float* __restrict__ qb,
                                               const float* __restrict__ vb) {
    extern __shared__ __align__(16) unsigned char sm[];
    int b = blockIdx.y, tile = blockIdx.x, n0 = tile * NT, t = threadIdx.x;
    uint32_t sb = smem_u32(sm);
    float* Dsm = (float*)(sm + QV_D);
    float* sbias = (float*)(sm + QV_SB);
    int w = t >> 5, lane = t & 31;
    int wm = w >> 2, wn = w & 3;

    load_img1(g_wimg, sm + QV_A, t);                 // Wq
    for (int i = t; i < 16384; i += 512) {
        int c = i >> 7, n = i & 127;
        Dsm[c * 129 + n] = x[((size_t)b * 128 + c) * NN + n0 + n];
    }
    if (t < 128) sbias[t] = qb[t];
    else if (t < 256) sbias[t] = vb[t - 128];
    __syncthreads();

    // convert x -> B image
    {
        int node = t >> 2, q4 = t & 3;
        #pragma unroll
        for (int cc = 0; cc < 4; cc++) {
            int c0 = q4 * 32 + cc * 8;
            unsigned short hs[8];
            #pragma unroll
            for (int k = 0; k < 8; k++) hs[k] = hf1(Dsm[(c0 + k) * 129 + node]);
            *(uint4*)(sm + QV_B + node * ROWB + c0 * 2) = pack8(hs);
        }
    }
    __syncthreads();

    float D[2][4][4];
    dzero(D);
    gemm1f(sb + QV_A, sb + QV_B, wm, wn, lane, D);   // Q = Wq @ x
    dwrite(Dsm, wm, wn, lane, D);
    __syncthreads();

    // ---- Q epilogue: per-node softmax per head; q image into A ----
    const float inv_scale = 0.17677669529663687f;
    {
        int node = t & 127, h = t >> 7;
        float q[32];
        float mx = 0.0f;
        #pragma unroll
        for (int i = 0; i < 32; i++) {
            q[i] = fmaxf(Dsm[(h * 32 + i) * 129 + node] + sbias[h * 32 + i], 0.0f);
            mx = fmaxf(mx, q[i]);
        }
        float s = 0.0f;
        #pragma unroll
        for (int i = 0; i < 32; i++) { q[i] = __expf((q[i] - mx) * inv_scale); s += q[i]; }
        float is = 1.0f / s;
        #pragma unroll
        for (int cc = 0; cc < 4; cc++) {
            unsigned short hs[8];
            #pragma unroll
            for (int k = 0; k < 8; k++) hs[k] = hf1(q[cc * 8 + k] * is);
            *(uint4*)(sm + QV_A + node * ROWB + (h * 32 + cc * 8) * 2) = pack8(hs);
        }
    }
    __syncthreads();
    store_img1(g_qimg + ((size_t)(b * NTILES + tile)) * 32768, sm + QV_A, t);
    __syncthreads();

    load_img1(g_wimg + 32768, sm + QV_A, t);         // Wv (B keeps x)
    __syncthreads();
    dzero(D);
    gemm1f(sb + QV_A, sb + QV_B, wm, wn, lane, D);   // V = Wv @ x
    dwrite(Dsm, wm, wn, lane, D);
    __syncthreads();

    // ---- V epilogue: relu writeback; v image into B ----
    {
        int node = t & 127, h = t >> 7;
        float v[32];
        #pragma unroll
        for (int i = 0; i < 32; i++) {
            v[i] = fmaxf(Dsm[(h * 32 + i) * 129 + node] + sbias[128 + h * 32 + i], 0.0f);
            Dsm[(h * 32 + i) * 129 + node] = v[i];
        }
        #pragma unroll
        for (int cc = 0; cc < 4; cc++) {
            unsigned short hs[8];
            #pragma unroll
            for (int k = 0; k < 8; k++) hs[k] = hf1(v[cc * 8 + k]);
            *(uint4*)(sm + QV_B + node * ROWB + (h * 32 + cc * 8) * 2) = pack8(hs);
        }
    }
    __syncthreads();
    store_img1(g_vimg + ((size_t)(b * NTILES + tile)) * 32768, sm + QV_B, t);
    __syncthreads();   // v image fully read before ks overwrites A+B

    // ---- ks spans A+B (65536 B), then kv partial ----
    float* ks = (float*)sm;
    for (int i = t; i < 16384; i += 512) {
        int h2 = i >> 12, r = i & 4095;
        int j2 = r >> 5, xk = r & 31;
        ks[i] = g_keysm[(h2 * NN + n0 + j2) * 32 + xk];
    }
    __syncthreads();
    {
        int idx = t & 127, h2 = t >> 7;
        int x0 = (idx >> 4) * 4, y0 = (idx & 15) * 2;
        float acc[4][2];
        #pragma unroll
        for (int a = 0; a < 4; a++) { acc[a][0] = 0.0f; acc[a][1] = 0.0f; }
        #pragma unroll 4
        for (int jj = 0; jj < NT; jj++) {
            float4 kx = *(const float4*)(ks + (h2 * NT + jj) * 32 + x0);
            float v0 = Dsm[(h2 * 32 + y0 + 0) * 129 + jj];
            float v1 = Dsm[(h2 * 32 + y0 + 1) * 129 + jj];
            acc[0][0] += kx.x * v0; acc[0][1] += kx.x * v1;
            acc[1][0] += kx.y * v0; acc[1][1] += kx.y * v1;
            acc[2][0] += kx.z * v0; acc[2][1] += kx.z * v1;
            acc[3][0] += kx.w * v0; acc[3][1] += kx.w * v1;
        }
        #pragma unroll
        for (int xi = 0; xi < 4; xi++)
            #pragma unroll
            for (int yi = 0; yi < 2; yi++)
                atomicAdd(&g_kv[(((size_t)b * HEAD + h2) * DK + x0 + xi) * DK + y0 + yi],
                          acc[xi][yi]);
    }
}

// ---------------- P6: Mb (single fp16) ----------------
__global__ __launch_bounds__(512) void k_mb(const float* __restrict__ cw) {
    __shared__ float kvT[32 * 128];
    int b = blockIdx.x, t = threadIdx.x;
    for (int i = t; i < 4096; i += 512) {
        int row = i >> 5, y = i & 31;
        kvT[y * 128 + row] = g_kv[(size_t)b * 4096 + i];
    }
    __syncthreads();
    int o = t & 127, h = t >> 7;
    float acc[32];
    #pragma unroll
    for (int x = 0; x < 32; x++) acc[x] = 0.0f;
    for (int y = 0; y < 32; y++) {
        float cv = cw[o * 128 + h * 32 + y];
        const float* kr = kvT + y * 128 + h * 32;
        #pragma unroll
        for (int x = 0; x < 32; x++) acc[x] += cv * kr[x];
    }
    unsigned char* img = g_Mb + (size_t)b * 32768;
    for (int cc = 0; cc < 4; cc++) {
        unsigned short hs[8];
        #pragma unroll
        for (int k = 0; k < 8; k++) hs[k] = hf1(acc[cc * 8 + k]);
        *(uint4*)(img + (o * 128 + h * 32 + cc * 8) * 2) = pack8(hs);
    }
}

// ---------------- K2: out = relu(Mb@q + Cs@v + bias2 + cb) -> affine -----
__global__ __launch_bounds__(512, 1) void k_out(const float* __restrict__ cb,
                                                const float* __restrict__ affw,
                                                const float* __restrict__ affb,
                                                float* __restrict__ out) {
    extern __shared__ __align__(16) unsigned char sm[];
    int b = blockIdx.y, tile = blockIdx.x, n0 = tile * NT, t = threadIdx.x;
    uint32_t sb = smem_u32(sm);
    int w = t >> 5, lane = t & 31;
    int wm = w >> 2, wn = w & 3;

    load_img1(g_Mb + (size_t)b * 32768, sm + KO_A, t);
    load_img1(g_wimg + 2 * 32768, sm + KO_C, t);
    load_img1(g_qimg + ((size_t)(b * NTILES + tile)) * 32768, sm + KO_BQ, t);
    load_img1(g_vimg + ((size_t)(b * NTILES + tile)) * 32768, sm + KO_BV, t);
    __syncthreads();

    float D[2][4][4];
    dzero(D);
    gemm1f(sb + KO_A, sb + KO_BQ, wm, wn, lane, D);  // Mb @ q
    gemm1f(sb + KO_C, sb + KO_BV, wm, wn, lane, D);  // += Cs @ v

    // ---- direct register epilogue ----
    int r0 = lane >> 2, cp = (lane & 3) * 2;
    #pragma unroll
    for (int mt = 0; mt < 2; mt++)
        #pragma unroll
        for (int nt = 0; nt < 4; nt++) {
            int col = wn * 32 + nt * 8 + cp;
            #pragma unroll
            for (int half = 0; half < 2; half++) {
                int c = wm * 32 + mt * 16 + r0 + half * 8;
                size_t base = (size_t)c * NN + n0 + col;
                float cbv = __ldg(cb + c);
                float2 b2 = *(const float2*)(g_bias2 + base);
                float2 aw = *(const float2*)(affw + base);
                float2 ab = *(const float2*)(affb + base);
                float v0 = D[mt][nt][half * 2 + 0] + cbv + b2.x;
                float v1 = D[mt][nt][half * 2 + 1] + cbv + b2.y;
                float rr0 = fmaxf(v0, 0.0f), rr1 = fmaxf(v1, 0.0f);
                float2 o2;
                o2.x = rr0 + rr0 * aw.x + ab.x;
                o2.y = rr1 + rr1 * aw.y + ab.y;
                *(float2*)(out + ((size_t)b * 128) * NN + base) = o2;
            }
        }
}

extern "C" void kernel_launch(void* const* d_in, const int* in_sizes, int n_in,
                              void* d_out, int out_size) {
    const float* x     = (const float*)d_in[0];
    const float* qw    = (const float*)d_in[1];
    const float* qb    = (const float*)d_in[2];
    const float* vw    = (const float*)d_in[3];
    const float* vb    = (const float*)d_in[4];
    const float* cw    = (const float*)d_in[5];
    const float* cb    = (const float*)d_in[6];
    const float* mem   = (const float*)d_in[7];
    const float* nv1   = (const float*)d_in[8];
    const float* nv2   = (const float*)d_in[9];
    const float* wpool = (const float*)d_in[10];
    const float* bpool = (const float*)d_in[11];
    const float* affw  = (const float*)d_in[12];
    const float* affb  = (const float*)d_in[13];
    float* out = (float*)d_out;

    k_keysm<<<HEAD * NN / 8, 256>>>(mem);
    k_biasdyn<<<NN / 8, 256>>>(nv1, nv2, bpool);
    k_zero_kv<<<(BATCH * HEAD * DK * DK + 255) / 256, 256>>>();
    k_prepw<<<dim3(4, 8), 128>>>(qw, vw, cw, wpool);
    k_bias2<<<NN, 128>>>();

    cudaFuncSetAttribute(k_qv, cudaFuncAttributeMaxDynamicSharedMemorySize, SMEM_QV);
    k_qv<<<dim3(NTILES, BATCH), 512, SMEM_QV>>>(x, qb, vb);

    k_mb<<<BATCH, 512>>>(cw);

    cudaFuncSetAttribute(k_out, cudaFuncAttributeMaxDynamicSharedMemorySize, SMEM_OUT);
    k_out<<<dim3(NTILES, BATCH), 512, SMEM_OUT>>>(cb, affw, affb, out);
}

// round 12
// speedup vs baseline: 5.1966x; 1.0393x over previous
#include <cuda_runtime.h>
#include <cuda_fp16.h>
#include <math.h>
#include <stdint.h>

#define BATCH 64
#define DMODEL 128
#define NN 2048
#define HEAD 4
#define DK 32
#define NT 128
#define NTILES (NN/NT)  // 16

#define IMG_SZ 34816       // 128 rows * 272 B
#define ROWB 272
// k_qv: A | B | D fp32 | biases | Q(img staging)
#define QV_A 0             // 34816
#define QV_B 34816         // 34816
#define QV_D 69632         // 66048 : fp32 [128][129]
#define QV_SB 135680       // 1024
#define QV_Q 136704        // 34816
#define SMEM_QV 171520
// k_out (2 tiles): Mb | Cs | q0 | v0 | q1 | v1
#define KO_A 0
#define KO_C 34816
#define KO_BQ0 69632
#define KO_BV0 104448
#define KO_BQ1 139264
#define KO_BV1 174080
#define SMEM_OUT 208896
// k_prolog dyn smem (biasdyn partition)
#define PL_P 0             // 65536 : p[8][2048]
#define PL_RED 65536       // 1024
#define PL_A1 66560        // 320
#define PL_INV 66880       // 32
#define SMEM_PL 66944

// ---------------- device globals ----------------
static __device__ float g_keysm[HEAD * NN * DK];
static __device__ float g_biasdyn[NN * DK];
static __device__ float g_kv[BATCH * HEAD * DK * DK];
static __device__ float g_bias2[DMODEL * NN];
static __device__ float g_Cp[DMODEL * DK];
static __device__ __align__(16) unsigned char g_wimg[3 * 32768];                      // Wq, Wv, Cs
static __device__ __align__(16) unsigned char g_qimg[(size_t)BATCH * NTILES * 32768];
static __device__ __align__(16) unsigned char g_vimg[(size_t)BATCH * NTILES * 32768];
static __device__ __align__(16) unsigned char g_Mb[(size_t)BATCH * 32768];

// ---------------- helpers ----------------
__device__ __forceinline__ uint32_t smem_u32(const void* p) {
    uint32_t a;
    asm("{ .reg .u64 t; cvta.to.shared.u64 t, %1; cvt.u32.u64 %0, t; }" : "=r"(a) : "l"(p));
    return a;
}
__device__ __forceinline__ unsigned short hf1(float v) {
    return __half_as_ushort(__float2half_rn(v));
}
__device__ __forceinline__ uint4 pack8(const unsigned short* h) {
    uint4 u;
    u.x = (uint32_t)h[0] | ((uint32_t)h[1] << 16);
    u.y = (uint32_t)h[2] | ((uint32_t)h[3] << 16);
    u.z = (uint32_t)h[4] | ((uint32_t)h[5] << 16);
    u.w = (uint32_t)h[6] | ((uint32_t)h[7] << 16);
    return u;
}
__device__ __forceinline__ float warp_max(float v) {
    #pragma unroll
    for (int o = 16; o; o >>= 1) v = fmaxf(v, __shfl_xor_sync(0xffffffffu, v, o));
    return v;
}
__device__ __forceinline__ float warp_sum(float v) {
    #pragma unroll
    for (int o = 16; o; o >>= 1) v += __shfl_xor_sync(0xffffffffu, v, o);
    return v;
}
__device__ __forceinline__ void ldsm4(uint32_t addr, uint32_t& r0, uint32_t& r1,
                                      uint32_t& r2, uint32_t& r3) {
    asm volatile("ldmatrix.sync.aligned.m8n8.x4.shared.b16 {%0,%1,%2,%3}, [%4];"
                 : "=r"(r0), "=r"(r1), "=r"(r2), "=r"(r3) : "r"(addr));
}
__device__ __forceinline__ void mma16816(float d[4], const uint32_t a[4],
                                         uint32_t b0, uint32_t b1) {
    asm volatile("mma.sync.aligned.m16n8k16.row.col.f32.f16.f16.f32 "
                 "{%0,%1,%2,%3}, {%4,%5,%6,%7}, {%8,%9}, {%0,%1,%2,%3};"
                 : "+f"(d[0]), "+f"(d[1]), "+f"(d[2]), "+f"(d[3])
                 : "r"(a[0]), "r"(a[1]), "r"(a[2]), "r"(a[3]), "r"(b0), "r"(b1));
}
__device__ __forceinline__ void load_img1(const unsigned char* g, unsigned char* s, int t) {
    const uint4* src = (const uint4*)g;
    uint4* dst = (uint4*)s;
    for (int i = t; i < 2048; i += 512) {
        int r = i >> 4, c = i & 15;
        dst[r * 17 + c] = src[i];
    }
}
__device__ __forceinline__ void store_img1(unsigned char* g, const unsigned char* s, int t) {
    uint4* dst = (uint4*)g;
    const uint4* src = (const uint4*)s;
    for (int i = t; i < 2048; i += 512) {
        int r = i >> 4, c = i & 15;
        dst[i] = src[r * 17 + c];
    }
}

// single-pass fp16 GEMM: D(32x32) += A * B^T ; 16 warps, 4x4 warp grid.
__device__ __forceinline__ void gemm1f(uint32_t A, uint32_t B, int wm, int wn,
                                       int lane, float D[2][4][4]) {
    int mat = lane >> 3, r8 = lane & 7;
    int arow = wm * 32 + ((mat & 1) << 3) + r8;
    int acol0 = (mat >> 1) << 3;
    int brow = wn * 32 + ((mat >> 1) << 3) + r8;
    int bcol0 = (mat & 1) << 3;
    #pragma unroll
    for (int ks = 0; ks < 8; ks++) {
        int k = ks * 16;
        uint32_t a[2][4], bf[2][4];
        #pragma unroll
        for (int mt = 0; mt < 2; mt++)
            ldsm4(A + (arow + mt * 16) * ROWB + (k + acol0) * 2,
                  a[mt][0], a[mt][1], a[mt][2], a[mt][3]);
        #pragma unroll
        for (int bt = 0; bt < 2; bt++)
            ldsm4(B + (brow + bt * 16) * ROWB + (k + bcol0) * 2,
                  bf[bt][0], bf[bt][1], bf[bt][2], bf[bt][3]);
        #pragma unroll
        for (int mt = 0; mt < 2; mt++)
            #pragma unroll
            for (int nt = 0; nt < 4; nt++)
                mma16816(D[mt][nt], a[mt], bf[nt >> 1][(nt & 1) * 2],
                         bf[nt >> 1][(nt & 1) * 2 + 1]);
    }
}
__device__ __forceinline__ void dzero(float D[2][4][4]) {
    #pragma unroll
    for (int mt = 0; mt < 2; mt++)
        #pragma unroll
        for (int nt = 0; nt < 4; nt++)
            #pragma unroll
            for (int i = 0; i < 4; i++) D[mt][nt][i] = 0.0f;
}
__device__ __forceinline__ void dwrite(float* Dsm, int wm, int wn, int lane, float D[2][4][4]) {
    int r = lane >> 2, cc = (lane & 3) * 2;
    #pragma unroll
    for (int mt = 0; mt < 2; mt++)
        #pragma unroll
        for (int nt = 0; nt < 4; nt++) {
            int row = wm * 32 + mt * 16 + r;
            int col = wn * 32 + nt * 8 + cc;
            Dsm[row * 129 + col] = D[mt][nt][0];
            Dsm[row * 129 + col + 1] = D[mt][nt][1];
            Dsm[(row + 8) * 129 + col] = D[mt][nt][2];
            Dsm[(row + 8) * 129 + col + 1] = D[mt][nt][3];
        }
}

// ---------------- P: merged prolog (keysm | zero_kv | prepw | biasdyn) ----
__global__ __launch_bounds__(256) void k_prolog(const float* __restrict__ mem,
                                                const float* __restrict__ nv1,
                                                const float* __restrict__ nv2,
                                                const float* __restrict__ bpool,
                                                const float* __restrict__ qw,
                                                const float* __restrict__ vw,
                                                const float* __restrict__ cw,
                                                const float* __restrict__ wpool) {
    extern __shared__ __align__(16) unsigned char psm[];
    int p = blockIdx.x;
    int t = threadIdx.x;
    const float inv_scale = 0.17677669529663687f;

    if (p < 1024) {                      // ---- keysm: 8 rows/block ----
        int row = p * 8 + (t >> 5);
        int lane = t & 31;
        float v = mem[row * 32 + lane] * inv_scale;
        float m = warp_max(v);
        float e = __expf(v - m);
        float s = warp_sum(e);
        g_keysm[row * 32 + lane] = e / s;
        return;
    }
    if (p < 1088) {                      // ---- zero_kv: 4096 floats/block ----
        float4* kv4 = (float4*)g_kv;
        int base = (p - 1024) * 1024;
        #pragma unroll
        for (int i = 0; i < 4; i++)
            kv4[base + t + i * 256] = make_float4(0.f, 0.f, 0.f, 0.f);
        return;
    }
    if (p < 1120) {                      // ---- prepw (128 active threads) ----
        if (t >= 128) return;
        int pb = p - 1088;
        int m = pb >> 3, part = pb & 7;
        int o = t;
        if (m == 3) {
            if (part == 0) {
                for (int y = 0; y < 32; y++) {
                    float s = 0.0f;
                    #pragma unroll
                    for (int h = 0; h < 4; h++) s += cw[o * 128 + h * 32 + y];
                    g_Cp[o * 32 + y] = s;
                }
            }
            return;
        }
        const float* w = (m == 0) ? qw : (m == 1) ? vw : cw;
        float scale = 1.0f;
        if (m == 2) {
            float S = 0.0f;
            #pragma unroll
            for (int i = 0; i < 9; i++) S += wpool[i];
            scale = S;
        }
        unsigned char* img = g_wimg + m * 32768;
        for (int cc = part * 2; cc < part * 2 + 2; cc++) {
            unsigned short hs[8];
            #pragma unroll
            for (int k = 0; k < 8; k++) hs[k] = hf1(w[o * 128 + cc * 8 + k] * scale);
            *(uint4*)(img + (o * 128 + cc * 8) * 2) = pack8(hs);
        }
        return;
    }
    // ---- biasdyn: 8 rows/block ----
    {
        float* pp = (float*)(psm + PL_P);          // [8][2048]
        float* red = (float*)(psm + PL_RED);
        float* a1 = (float*)(psm + PL_A1);         // [8][10]
        float* invs = (float*)(psm + PL_INV);
        int n0 = (p - 1120) * 8;
        if (t < 80) a1[t] = nv1[(n0 + t / 10) * 10 + (t % 10)];
        __syncthreads();
        for (int r = 0; r < 8; r++) {
            float lv[8];
            float lmax = 0.0f;
            #pragma unroll
            for (int i = 0; i < 8; i++) {
                int m = t + i * 256;
                float acc = 0.0f;
                #pragma unroll
                for (int k = 0; k < 10; k++) acc += a1[r * 10 + k] * nv2[k * NN + m];
                acc = fmaxf(acc, 0.0f);
                lv[i] = acc;
                lmax = fmaxf(lmax, acc);
            }
            red[t] = lmax; __syncthreads();
            for (int s = 128; s; s >>= 1) { if (t < s) red[t] = fmaxf(red[t], red[t + s]); __syncthreads(); }
            float bmax = red[0];
            __syncthreads();
            float lsum = 0.0f;
            #pragma unroll
            for (int i = 0; i < 8; i++) {
                float e = __expf(lv[i] - bmax);
                pp[r * NN + t + i * 256] = e;
                lsum += e;
            }
            red[t] = lsum; __syncthreads();
            for (int s = 128; s; s >>= 1) { if (t < s) red[t] += red[t + s]; __syncthreads(); }
            if (t == 0) invs[r] = 1.0f / red[0];
            __syncthreads();
        }
        int c = t & 31, g = t >> 5;
        float acc[8];
        #pragma unroll
        for (int r = 0; r < 8; r++) acc[r] = 0.0f;
        for (int m = g; m < NN; m += 8) {
            float bp = bpool[m * 32 + c];
            #pragma unroll
            for (int r = 0; r < 8; r++) acc[r] += pp[r * NN + m] * bp;
        }
        for (int r = 0; r < 8; r++) {
            red[t] = acc[r]; __syncthreads();
            if (t < 32) {
                float s2 = 0.0f;
                #pragma unroll
                for (int g2 = 0; g2 < 8; g2++) s2 += red[g2 * 32 + t];
                g_biasdyn[(n0 + r) * 32 + t] = s2 * invs[r];
            }
            __syncthreads();
        }
    }
}

// ---------------- P4b: bias2 = Cp @ bias_dyn^T ----------------
__global__ __launch_bounds__(128) void k_bias2() {
    __shared__ float bd[32];
    int n = blockIdx.x, t = threadIdx.x;
    if (t < 32) bd[t] = g_biasdyn[n * 32 + t];
    __syncthreads();
    float s = 0.0f;
    #pragma unroll
    for (int y = 0; y < 32; y++) s += g_Cp[t * 32 + y] * bd[y];
    g_bias2[t * NN + n] = s;
}

// ---------------- K1: x convert + Q/V convs + softmax + kv partial --------
__global__ __launch_bounds__(512, 1) void k_qv(const float* __restrict__ x,
                                               const float* __restrict__ qb,
                                               const float* __restrict__ vb) {
    extern __shared__ __align__(16) unsigned char sm[];
    int b = blockIdx.y, tile = blockIdx.x, n0 = tile * NT, t = threadIdx.x;
    uint32_t sb = smem_u32(sm);
    float* Dsm = (float*)(sm + QV_D);
    float* sbias = (float*)(sm + QV_SB);
    int w = t >> 5, lane = t & 31;
    int wm = w >> 2, wn = w & 3;

    // phase 1
    load_img1(g_wimg, sm + QV_A, t);                 // Wq
    for (int i = t; i < 16384; i += 512) {
        int c = i >> 7, n = i & 127;
        Dsm[c * 129 + n] = x[((size_t)b * 128 + c) * NN + n0 + n];
    }
    if (t < 128) sbias[t] = qb[t];
    else if (t < 256) sbias[t] = vb[t - 128];
    __syncthreads();

    // phase 2: convert x -> B image
    {
        int node = t >> 2, q4 = t & 3;
        #pragma unroll
        for (int cc = 0; cc < 4; cc++) {
            int c0 = q4 * 32 + cc * 8;
            unsigned short hs[8];
            #pragma unroll
            for (int k = 0; k < 8; k++) hs[k] = hf1(Dsm[(c0 + k) * 129 + node]);
            *(uint4*)(sm + QV_B + node * ROWB + c0 * 2) = pack8(hs);
        }
    }
    __syncthreads();

    // phase 3: Q GEMM
    float D[2][4][4];
    dzero(D);
    gemm1f(sb + QV_A, sb + QV_B, wm, wn, lane, D);
    dwrite(Dsm, wm, wn, lane, D);
    __syncthreads();

    // phase 4: Q epilogue -> Q region; Wv load -> A (concurrent, disjoint)
    const float inv_scale = 0.17677669529663687f;
    {
        int node = t & 127, h = t >> 7;
        float q[32];
        float mx = 0.0f;
        #pragma unroll
        for (int i = 0; i < 32; i++) {
            q[i] = fmaxf(Dsm[(h * 32 + i) * 129 + node] + sbias[h * 32 + i], 0.0f);
            mx = fmaxf(mx, q[i]);
        }
        float s = 0.0f;
        #pragma unroll
        for (int i = 0; i < 32; i++) { q[i] = __expf((q[i] - mx) * inv_scale); s += q[i]; }
        float is = 1.0f / s;
        #pragma unroll
        for (int cc = 0; cc < 4; cc++) {
            unsigned short hs[8];
            #pragma unroll
            for (int k = 0; k < 8; k++) hs[k] = hf1(q[cc * 8 + k] * is);
            *(uint4*)(sm + QV_Q + node * ROWB + (h * 32 + cc * 8) * 2) = pack8(hs);
        }
    }
    load_img1(g_wimg + 32768, sm + QV_A, t);         // Wv
    __syncthreads();

    // phase 5: store q; V GEMM
    store_img1(g_qimg + ((size_t)(b * NTILES + tile)) * 32768, sm + QV_Q, t);
    dzero(D);
    gemm1f(sb + QV_A, sb + QV_B, wm, wn, lane, D);
    dwrite(Dsm, wm, wn, lane, D);
    __syncthreads();

    // phase 6: V epilogue (relu writeback + image -> Q region); ks -> A+B
    {
        int node = t & 127, h = t >> 7;
        float v[32];
        #pragma unroll
        for (int i = 0; i < 32; i++) {
            v[i] = fmaxf(Dsm[(h * 32 + i) * 129 + node] + sbias[128 + h * 32 + i], 0.0f);
            Dsm[(h * 32 + i) * 129 + node] = v[i];
        }
        #pragma unroll
        for (int cc = 0; cc < 4; cc++) {
            unsigned short hs[8];
            #pragma unroll
            for (int k = 0; k < 8; k++) hs[k] = hf1(v[cc * 8 + k]);
            *(uint4*)(sm + QV_Q + node * ROWB + (h * 32 + cc * 8) * 2) = pack8(hs);
        }
    }
    float* ks = (float*)sm;   // spans A+B (65536 B)
    for (int i = t; i < 16384; i += 512) {
        int h2 = i >> 12, r = i & 4095;
        int j2 = r >> 5, xk = r & 31;
        ks[i] = g_keysm[(h2 * NN + n0 + j2) * 32 + xk];
    }
    __syncthreads();

    // phase 7: store v; kv partial
    store_img1(g_vimg + ((size_t)(b * NTILES + tile)) * 32768, sm + QV_Q, t);
    {
        int idx = t & 127, h2 = t >> 7;
        int x0 = (idx >> 4) * 4, y0 = (idx & 15) * 2;
        float acc[4][2];
        #pragma unroll
        for (int a = 0; a < 4; a++) { acc[a][0] = 0.0f; acc[a][1] = 0.0f; }
        #pragma unroll 4
        for (int jj = 0; jj < NT; jj++) {
            float4 kx = *(const float4*)(ks + (h2 * NT + jj) * 32 + x0);
            float v0 = Dsm[(h2 * 32 + y0 + 0) * 129 + jj];
            float v1 = Dsm[(h2 * 32 + y0 + 1) * 129 + jj];
            acc[0][0] += kx.x * v0; acc[0][1] += kx.x * v1;
            acc[1][0] += kx.y * v0; acc[1][1] += kx.y * v1;
            acc[2][0] += kx.z * v0; acc[2][1] += kx.z * v1;
            acc[3][0] += kx.w * v0; acc[3][1] += kx.w * v1;
        }
        #pragma unroll
        for (int xi = 0; xi < 4; xi++)
            #pragma unroll
            for (int yi = 0; yi < 2; yi++)
                atomicAdd(&g_kv[(((size_t)b * HEAD + h2) * DK + x0 + xi) * DK + y0 + yi],
                          acc[xi][yi]);
    }
}

// ---------------- P6: Mb (single fp16) ----------------
__global__ __launch_bounds__(512) void k_mb(const float* __restrict__ cw) {
    __shared__ float kvT[32 * 128];
    int b = blockIdx.x, t = threadIdx.x;
    for (int i = t; i < 4096; i += 512) {
        int row = i >> 5, y = i & 31;
        kvT[y * 128 + row] = g_kv[(size_t)b * 4096 + i];
    }
    __syncthreads();
    int o = t & 127, h = t >> 7;
    float acc[32];
    #pragma unroll
    for (int x = 0; x < 32; x++) acc[x] = 0.0f;
    for (int y = 0; y < 32; y++) {
        float cv = cw[o * 128 + h * 32 + y];
        const float* kr = kvT + y * 128 + h * 32;
        #pragma unroll
        for (int x = 0; x < 32; x++) acc[x] += cv * kr[x];
    }
    unsigned char* img = g_Mb + (size_t)b * 32768;
    for (int cc = 0; cc < 4; cc++) {
        unsigned short hs[8];
        #pragma unroll
        for (int k = 0; k < 8; k++) hs[k] = hf1(acc[cc * 8 + k]);
        *(uint4*)(img + (o * 128 + h * 32 + cc * 8) * 2) = pack8(hs);
    }
}

// ---------------- K2: 2 tiles/CTA; out = relu(Mb@q + Cs@v + b2 + cb) -----
__global__ __launch_bounds__(512, 1) void k_out(const float* __restrict__ cb,
                                                const float* __restrict__ affw,
                                                const float* __restrict__ affb,
                                                float* __restrict__ out) {
    extern __shared__ __align__(16) unsigned char sm[];
    int b = blockIdx.y, pair = blockIdx.x, t = threadIdx.x;
    uint32_t sb = smem_u32(sm);
    int w = t >> 5, lane = t & 31;
    int wm = w >> 2, wn = w & 3;
    int tile0 = pair * 2;

    load_img1(g_Mb + (size_t)b * 32768, sm + KO_A, t);
    load_img1(g_wimg + 2 * 32768, sm + KO_C, t);
    load_img1(g_qimg + ((size_t)(b * NTILES + tile0)) * 32768, sm + KO_BQ0, t);
    load_img1(g_vimg + ((size_t)(b * NTILES + tile0)) * 32768, sm + KO_BV0, t);
    load_img1(g_qimg + ((size_t)(b * NTILES + tile0 + 1)) * 32768, sm + KO_BQ1, t);
    load_img1(g_vimg + ((size_t)(b * NTILES + tile0 + 1)) * 32768, sm + KO_BV1, t);
    __syncthreads();

    int r0 = lane >> 2, cp = (lane & 3) * 2;
    #pragma unroll 1
    for (int tt = 0; tt < 2; tt++) {
        int n0 = (tile0 + tt) * NT;
        float D[2][4][4];
        dzero(D);
        gemm1f(sb + KO_A, sb + (tt ? KO_BQ1 : KO_BQ0), wm, wn, lane, D);
        gemm1f(sb + KO_C, sb + (tt ? KO_BV1 : KO_BV0), wm, wn, lane, D);
        #pragma unroll
        for (int mt = 0; mt < 2; mt++)
            #pragma unroll
            for (int nt = 0; nt < 4; nt++) {
                int col = wn * 32 + nt * 8 + cp;
                #pragma unroll
                for (int half = 0; half < 2; half++) {
                    int c = wm * 32 + mt * 16 + r0 + half * 8;
                    size_t base = (size_t)c * NN + n0 + col;
                    float cbv = __ldg(cb + c);
                    float2 b2 = *(const float2*)(g_bias2 + base);
                    float2 aw = *(const float2*)(affw + base);
                    float2 ab = *(const float2*)(affb + base);
                    float v0 = D[mt][nt][half * 2 + 0] + cbv + b2.x;
                    float v1 = D[mt][nt][half * 2 + 1] + cbv + b2.y;
                    float rr0 = fmaxf(v0, 0.0f), rr1 = fmaxf(v1, 0.0f);
                    float2 o2;
                    o2.x = rr0 + rr0 * aw.x + ab.x;
                    o2.y = rr1 + rr1 * aw.y + ab.y;
                    *(float2*)(out + ((size_t)b * 128) * NN + base) = o2;
                }
            }
    }
}

extern "C" void kernel_launch(void* const* d_in, const int* in_sizes, int n_in,
                              void* d_out, int out_size) {
    const float* x     = (const float*)d_in[0];
    const float* qw    = (const float*)d_in[1];
    const float* qb    = (const float*)d_in[2];
    const float* vw    = (const float*)d_in[3];
    const float* vb    = (const float*)d_in[4];
    const float* cw    = (const float*)d_in[5];
    const float* cb    = (const float*)d_in[6];
    const float* mem   = (const float*)d_in[7];
    const float* nv1   = (const float*)d_in[8];
    const float* nv2   = (const float*)d_in[9];
    const float* wpool = (const float*)d_in[10];
    const float* bpool = (const float*)d_in[11];
    const float* affw  = (const float*)d_in[12];
    const float* affb  = (const float*)d_in[13];
    float* out = (float*)d_out;

    cudaFuncSetAttribute(k_prolog, cudaFuncAttributeMaxDynamicSharedMemorySize, SMEM_PL);
    k_prolog<<<1376, 256, SMEM_PL>>>(mem, nv1, nv2, bpool, qw, vw, cw, wpool);

    k_bias2<<<NN, 128>>>();

    cudaFuncSetAttribute(k_qv, cudaFuncAttributeMaxDynamicSharedMemorySize, SMEM_QV);
    k_qv<<<dim3(NTILES, BATCH), 512, SMEM_QV>>>(x, qb, vb);

    k_mb<<<BATCH, 512>>>(cw);

    cudaFuncSetAttribute(k_out, cudaFuncAttributeMaxDynamicSharedMemorySize, SMEM_OUT);
    k_out<<<dim3(NTILES / 2, BATCH), 512, SMEM_OUT>>>(cb, affw, affb, out);
}